// round 3
// baseline (speedup 1.0000x reference)
#include <cuda_runtime.h>
#include <cstddef>
#include <cstdint>

#define NN 100000
#define NE 3200000

// ---------------- scratch (module-load allocated, no runtime alloc) ----------
__device__ __align__(16) float g_bufA[(size_t)NN * 128];  // GEMM output h
__device__ __align__(16) float g_bufB[(size_t)NN * 128];  // agg ping
__device__ __align__(16) float g_bufC[(size_t)NN * 128];  // agg pong
__device__ float g_dinv[NN];
__device__ float g_dinv2[NN];
__device__ __align__(16) float g_norm[NE];
__device__ int g_srcI[NE];
__device__ int g_dstI[NE];
__device__ int g_is64;

// ---------------- edge-index dtype probe + unpack ----------------------------
// JAX with x64 disabled coerces the reference's int64 edge_index to int32.
// Detect the actual layout from the data (high words of int64 values < 2^17
// are all zero; int32 src values are ~never all zero over 1024 samples).
__global__ void k_detect(const int* __restrict__ w) {
    if (blockIdx.x == 0 && threadIdx.x == 0) {
        int is64 = 1;
        for (int i = 0; i < 2048; i += 2) {
            if (w[i + 1] != 0) { is64 = 0; break; }
        }
        g_is64 = is64;
    }
}

__global__ void k_unpack(const int* __restrict__ w,
                         int* __restrict__ srcI, int* __restrict__ dstI) {
    const int is64 = g_is64;
    long long i = (long long)blockIdx.x * blockDim.x + threadIdx.x;
    long long stride = (long long)gridDim.x * blockDim.x;
    if (is64) {
        for (; i < NE; i += stride) {
            srcI[i] = w[2 * i];
            dstI[i] = w[2 * (long long)NE + 2 * i];
        }
    } else {
        for (; i < NE; i += stride) {
            srcI[i] = w[i];
            dstI[i] = w[NE + i];
        }
    }
}

// ---------------- degree / norm precompute ----------------------------------
__global__ void k_init_deg(float* deg) {
    int i = blockIdx.x * blockDim.x + threadIdx.x;
    if (i < NN) deg[i] = 1.0f;  // self loop
}

__global__ void k_count_deg(const int* __restrict__ dst, float* deg) {
    long long i = (long long)blockIdx.x * blockDim.x + threadIdx.x;
    long long stride = (long long)gridDim.x * blockDim.x;
    for (; i < NE; i += stride) atomicAdd(&deg[dst[i]], 1.0f);
}

__global__ void k_finish_deg(float* deg_dinv2, float* dinv) {
    int i = blockIdx.x * blockDim.x + threadIdx.x;
    if (i < NN) {
        float dv = rsqrtf(deg_dinv2[i]);
        dinv[i] = dv;
        deg_dinv2[i] = dv * dv;   // self-loop norm = dinv^2
    }
}

__global__ void k_edge_norm(const int* __restrict__ src,
                            const int* __restrict__ dst,
                            const float* __restrict__ dinv,
                            float* __restrict__ norm) {
    long long i = (long long)blockIdx.x * blockDim.x + threadIdx.x;
    long long stride = (long long)gridDim.x * blockDim.x;
    for (; i < NE; i += stride)
        norm[i] = dinv[src[i]] * dinv[dst[i]];
}

// ---------------- GEMM + self-loop init (+ fused prev bias/ReLU) ------------
// t[n,DOUT]   = act(in) @ W          (act = relu(in + pb) if PREACT else in)
// agg[n,DOUT] = t * dinv2[n]         (self-loop contribution seed)
template <int DIN, int DOUT, bool PREACT>
__global__ void __launch_bounds__(128)
k_gemm(const float* __restrict__ in, const float* __restrict__ W,
       const float* __restrict__ pb, const float* __restrict__ dinv2,
       float* __restrict__ t, float* __restrict__ agg) {
    extern __shared__ float sm[];
    float* sW  = sm;                     // DIN*DOUT
    float* sIn = sm + DIN * DOUT;        // 16*DIN
    float* sPb = sIn + 16 * DIN;         // DIN
    const int tid = threadIdx.x;

    for (int i = tid; i < DIN * DOUT; i += 128) sW[i] = W[i];
    if (PREACT)
        for (int i = tid; i < DIN; i += 128) sPb[i] = pb[i];
    __syncthreads();

    constexpr int CQ  = DOUT / 4;    // col-quads
    constexpr int G   = 128 / CQ;    // row groups
    constexpr int RPT = 16 / G;      // rows per thread
    const int colq = tid % CQ;
    const int grp  = tid / CQ;

    for (int tile = blockIdx.x * 16; tile < NN; tile += gridDim.x * 16) {
        // stage 16 input rows (with fused prev-layer bias+relu)
        for (int i = tid; i < 16 * DIN; i += 128) {
            int r = i / DIN, k = i - r * DIN;
            float v = 0.0f;
            if (tile + r < NN) {
                v = in[(size_t)(tile + r) * DIN + k];
                if (PREACT) v = fmaxf(v + sPb[k], 0.0f);
            }
            sIn[i] = v;
        }
        __syncthreads();

        float acc[RPT][4];
#pragma unroll
        for (int rr = 0; rr < RPT; rr++) {
            acc[rr][0] = 0.f; acc[rr][1] = 0.f; acc[rr][2] = 0.f; acc[rr][3] = 0.f;
        }
#pragma unroll 4
        for (int k = 0; k < DIN; k++) {
            float4 w = *reinterpret_cast<const float4*>(&sW[k * DOUT + colq * 4]);
#pragma unroll
            for (int rr = 0; rr < RPT; rr++) {
                float s = sIn[(grp * RPT + rr) * DIN + k];
                acc[rr][0] = fmaf(s, w.x, acc[rr][0]);
                acc[rr][1] = fmaf(s, w.y, acc[rr][1]);
                acc[rr][2] = fmaf(s, w.z, acc[rr][2]);
                acc[rr][3] = fmaf(s, w.w, acc[rr][3]);
            }
        }
#pragma unroll
        for (int rr = 0; rr < RPT; rr++) {
            int r = grp * RPT + rr;
            int row = tile + r;
            if (row < NN) {
                size_t o = (size_t)row * DOUT + colq * 4;
                float4 v = make_float4(acc[rr][0], acc[rr][1], acc[rr][2], acc[rr][3]);
                *reinterpret_cast<float4*>(&t[o]) = v;
                float d2 = dinv2[row];
                float4 a = make_float4(v.x * d2, v.y * d2, v.z * d2, v.w * d2);
                *reinterpret_cast<float4*>(&agg[o]) = a;
            }
        }
        __syncthreads();
    }
}

// ---------------- edge scatter: agg[dst] += h[src] * norm  -------------------
template <int DOUT>
__global__ void __launch_bounds__(256)
k_scatter(const int* __restrict__ src, const int* __restrict__ dst,
          const float* __restrict__ norm, const float* __restrict__ h,
          float* __restrict__ agg) {
    constexpr int LPE = DOUT / 4;   // lanes per edge
    constexpr int EPS = 32 / LPE;   // edges per inner step
    const int lane = threadIdx.x & 31;
    const long long warpId = ((long long)blockIdx.x * blockDim.x + threadIdx.x) >> 5;
    const long long nWarps = ((long long)gridDim.x * blockDim.x) >> 5;
    const int sub    = lane / LPE;
    const int within = lane % LPE;

    for (long long base = warpId * 32; base < NE; base += nWarps * 32) {
        int cnt = (int)min((long long)32, (long long)NE - base);
        int s = 0, d = 0;
        float nm = 0.0f;
        if (lane < cnt) {
            s  = src[base + lane];
            d  = dst[base + lane];
            nm = norm[base + lane];
        }
        for (int j = 0; j < cnt; j += EPS) {
            int idx = j + sub;
            int ss   = __shfl_sync(0xffffffffu, s, idx);
            int dd   = __shfl_sync(0xffffffffu, d, idx);
            float nn = __shfl_sync(0xffffffffu, nm, idx);
            if (idx < cnt) {
                const float4 v = *reinterpret_cast<const float4*>(
                    h + (size_t)ss * DOUT + (size_t)within * 4);
                float4 m = make_float4(v.x * nn, v.y * nn, v.z * nn, v.w * nn);
                float* p = agg + (size_t)dd * DOUT + (size_t)within * 4;
                asm volatile("red.global.add.v4.f32 [%0], {%1,%2,%3,%4};"
                             :: "l"(p), "f"(m.x), "f"(m.y), "f"(m.z), "f"(m.w)
                             : "memory");
            }
        }
    }
}

// ---------------- fused actor/critic heads + softmax -------------------------
// smem float offsets
constexpr int HO_Wa1 = 0;                       // 64*128
constexpr int HO_Wa2 = HO_Wa1 + 64 * 128;       // 128*64
constexpr int HO_Wa3 = HO_Wa2 + 128 * 64;       // 64*8
constexpr int HO_Wc1 = HO_Wa3 + 64 * 8;         // 64*128
constexpr int HO_Wc2 = HO_Wc1 + 64 * 128;       // 128*64
constexpr int HO_Wc3 = HO_Wc2 + 128 * 64;       // 64
constexpr int HO_ba1 = HO_Wc3 + 64;             // 128
constexpr int HO_ba2 = HO_ba1 + 128;            // 64
constexpr int HO_ba3 = HO_ba2 + 64;             // 8
constexpr int HO_bc1 = HO_ba3 + 8;              // 128
constexpr int HO_bc2 = HO_bc1 + 128;            // 64
constexpr int HO_bc3 = HO_bc2 + 64;             // 1
constexpr int HO_b3  = HO_bc3 + 1;              // 64
constexpr int HO_H   = HO_b3 + 64;              // 16*64
constexpr int HO_A1  = HO_H + 16 * 64;          // 16*128
constexpr int HO_C1  = HO_A1 + 16 * 128;        // 16*128
constexpr int HO_A2  = HO_C1 + 16 * 128;        // 16*64
constexpr int HO_C2  = HO_A2 + 16 * 64;         // 16*64
constexpr int HO_LOG = HO_C2 + 16 * 64;         // 16*8
constexpr int HO_VAL = HO_LOG + 16 * 8;         // 16
constexpr int HO_TOT = HO_VAL + 16;

__device__ __forceinline__ void coop_copy(float* d, const float* s, int n, int tid, int nt) {
    for (int i = tid; i < n; i += nt) d[i] = s[i];
}

__global__ void __launch_bounds__(256)
k_heads(const float* __restrict__ hagg, const float* __restrict__ b3,
        const float* __restrict__ Wa1, const float* __restrict__ ba1,
        const float* __restrict__ Wa2, const float* __restrict__ ba2,
        const float* __restrict__ Wa3, const float* __restrict__ ba3,
        const float* __restrict__ Wc1, const float* __restrict__ bc1,
        const float* __restrict__ Wc2, const float* __restrict__ bc2,
        const float* __restrict__ Wc3, const float* __restrict__ bc3,
        float* __restrict__ out) {
    extern __shared__ float sm[];
    const int t = threadIdx.x;
    coop_copy(sm + HO_Wa1, Wa1, 64 * 128, t, 256);
    coop_copy(sm + HO_Wa2, Wa2, 128 * 64, t, 256);
    coop_copy(sm + HO_Wa3, Wa3, 64 * 8, t, 256);
    coop_copy(sm + HO_Wc1, Wc1, 64 * 128, t, 256);
    coop_copy(sm + HO_Wc2, Wc2, 128 * 64, t, 256);
    coop_copy(sm + HO_Wc3, Wc3, 64, t, 256);
    coop_copy(sm + HO_ba1, ba1, 128, t, 256);
    coop_copy(sm + HO_ba2, ba2, 64, t, 256);
    coop_copy(sm + HO_ba3, ba3, 8, t, 256);
    coop_copy(sm + HO_bc1, bc1, 128, t, 256);
    coop_copy(sm + HO_bc2, bc2, 64, t, 256);
    coop_copy(sm + HO_bc3, bc3, 1, t, 256);
    coop_copy(sm + HO_b3,  b3,  64, t, 256);
    __syncthreads();

    for (int tile = blockIdx.x * 16; tile < NN; tile += gridDim.x * 16) {
        const int rows = min(16, NN - tile);
        // stage h = agg3 + b3
        for (int i = t; i < rows * 64; i += 256) {
            int r = i >> 6, k = i & 63;
            sm[HO_H + i] = hagg[(size_t)(tile + r) * 64 + k] + sm[HO_b3 + k];
        }
        __syncthreads();

        // stage 1: 64 -> 128 (actor on t<128, critic on t>=128)
        {
            const bool actor = t < 128;
            const int col = t & 127;
            const float* Wl = actor ? (sm + HO_Wa1) : (sm + HO_Wc1);
            const float bias = actor ? sm[HO_ba1 + col] : sm[HO_bc1 + col];
            float* dstS = actor ? (sm + HO_A1) : (sm + HO_C1);
            for (int r = 0; r < rows; r++) {
                float acc = bias;
#pragma unroll 8
                for (int k = 0; k < 64; k++)
                    acc = fmaf(sm[HO_H + r * 64 + k], Wl[k * 128 + col], acc);
                dstS[r * 128 + col] = fmaxf(acc, 0.0f);
            }
        }
        __syncthreads();

        // stage 2: 128 -> 64
        if ((t & 127) < 64) {
            const bool actor = t < 128;
            const int col = t & 63;
            const float* Wl = actor ? (sm + HO_Wa2) : (sm + HO_Wc2);
            const float* inS = actor ? (sm + HO_A1) : (sm + HO_C1);
            const float bias = actor ? sm[HO_ba2 + col] : sm[HO_bc2 + col];
            float* dstS = actor ? (sm + HO_A2) : (sm + HO_C2);
            for (int r = 0; r < rows; r++) {
                float acc = bias;
#pragma unroll 8
                for (int k = 0; k < 128; k++)
                    acc = fmaf(inS[r * 128 + k], Wl[k * 64 + col], acc);
                dstS[r * 64 + col] = fmaxf(acc, 0.0f);
            }
        }
        __syncthreads();

        // stage 3: logits (8) and value (1)
        if (t < 128) {
            int r = t >> 3, a = t & 7;
            if (r < rows) {
                float acc = sm[HO_ba3 + a];
#pragma unroll 8
                for (int k = 0; k < 64; k++)
                    acc = fmaf(sm[HO_A2 + r * 64 + k], sm[HO_Wa3 + k * 8 + a], acc);
                sm[HO_LOG + r * 8 + a] = acc;
            }
        } else if (t < 144) {
            int r = t - 128;
            if (r < rows) {
                float acc = sm[HO_bc3];
#pragma unroll 8
                for (int k = 0; k < 64; k++)
                    acc = fmaf(sm[HO_C2 + r * 64 + k], sm[HO_Wc3 + k], acc);
                sm[HO_VAL + r] = acc;
            }
        }
        __syncthreads();

        // stage 4: softmax + write [probs(8), value]
        if (t < rows) {
            float mx = -1e30f;
#pragma unroll
            for (int a = 0; a < 8; a++) mx = fmaxf(mx, sm[HO_LOG + t * 8 + a]);
            float e[8], ssum = 0.0f;
#pragma unroll
            for (int a = 0; a < 8; a++) {
                e[a] = expf(sm[HO_LOG + t * 8 + a] - mx);
                ssum += e[a];
            }
            float inv = 1.0f / ssum;
            size_t o = (size_t)(tile + t) * 9;
#pragma unroll
            for (int a = 0; a < 8; a++) out[o + a] = e[a] * inv;
            out[o + 8] = sm[HO_VAL + t];
        }
        __syncthreads();
    }
}

// ---------------- launch -----------------------------------------------------
extern "C" void kernel_launch(void* const* d_in, const int* in_sizes, int n_in,
                              void* d_out, int out_size) {
    const float* x   = (const float*)d_in[0];
    const int*   eiw = (const int*)d_in[1];   // raw words; dtype resolved on-device
    const float* W1 = (const float*)d_in[2];  const float* b1 = (const float*)d_in[3];
    const float* W2 = (const float*)d_in[4];  const float* b2 = (const float*)d_in[5];
    const float* W3 = (const float*)d_in[6];  const float* b3 = (const float*)d_in[7];
    const float* Wa1 = (const float*)d_in[8];  const float* ba1 = (const float*)d_in[9];
    const float* Wa2 = (const float*)d_in[10]; const float* ba2 = (const float*)d_in[11];
    const float* Wa3 = (const float*)d_in[12]; const float* ba3 = (const float*)d_in[13];
    const float* Wc1 = (const float*)d_in[14]; const float* bc1 = (const float*)d_in[15];
    const float* Wc2 = (const float*)d_in[16]; const float* bc2 = (const float*)d_in[17];
    const float* Wc3 = (const float*)d_in[18]; const float* bc3 = (const float*)d_in[19];
    float* out = (float*)d_out;

    void *pA, *pB, *pC, *pdinv, *pdinv2, *pnorm, *psrc, *pdst;
    cudaGetSymbolAddress(&pA, g_bufA);
    cudaGetSymbolAddress(&pB, g_bufB);
    cudaGetSymbolAddress(&pC, g_bufC);
    cudaGetSymbolAddress(&pdinv, g_dinv);
    cudaGetSymbolAddress(&pdinv2, g_dinv2);
    cudaGetSymbolAddress(&pnorm, g_norm);
    cudaGetSymbolAddress(&psrc, g_srcI);
    cudaGetSymbolAddress(&pdst, g_dstI);
    float* A = (float*)pA;  float* B = (float*)pB;  float* C = (float*)pC;
    float* dinv = (float*)pdinv;  float* dinv2 = (float*)pdinv2;
    float* norm = (float*)pnorm;
    int* src = (int*)psrc;  int* dst = (int*)pdst;

    const int SM_G1 = (128 * 128 + 16 * 128 + 128) * 4;  // 74240
    const int SM_G2 = (128 * 64 + 16 * 128 + 128) * 4;   // 41472
    const int SM_H  = HO_TOT * 4;                        // ~164 KB

    cudaFuncSetAttribute(k_gemm<128, 128, false>,
                         cudaFuncAttributeMaxDynamicSharedMemorySize, SM_G1);
    cudaFuncSetAttribute(k_gemm<128, 128, true>,
                         cudaFuncAttributeMaxDynamicSharedMemorySize, SM_G1);
    cudaFuncSetAttribute(k_gemm<128, 64, true>,
                         cudaFuncAttributeMaxDynamicSharedMemorySize, SM_G2);
    cudaFuncSetAttribute(k_heads,
                         cudaFuncAttributeMaxDynamicSharedMemorySize, SM_H);

    // resolve edge dtype + normalize indices to int32
    k_detect<<<1, 32>>>(eiw);
    k_unpack<<<2048, 256>>>(eiw, src, dst);

    // degree + norm
    k_init_deg<<<(NN + 255) / 256, 256>>>(dinv2);
    k_count_deg<<<1216, 256>>>(dst, dinv2);
    k_finish_deg<<<(NN + 255) / 256, 256>>>(dinv2, dinv);
    k_edge_norm<<<2048, 256>>>(src, dst, dinv, norm);

    // layer 1: x @ W1 -> A, agg seed -> B; scatter A -> B
    k_gemm<128, 128, false><<<456, 128, SM_G1>>>(x, W1, b1, dinv2, A, B);
    k_scatter<128><<<1216, 256>>>(src, dst, norm, A, B);

    // layer 2: relu(B + b1) @ W2 -> A, agg seed -> C; scatter A -> C
    k_gemm<128, 128, true><<<456, 128, SM_G1>>>(B, W2, b1, dinv2, A, C);
    k_scatter<128><<<1216, 256>>>(src, dst, norm, A, C);

    // layer 3: relu(C + b2) @ W3 -> A, agg seed -> B; scatter A -> B
    k_gemm<128, 64, true><<<456, 128, SM_G2>>>(C, W3, b2, dinv2, A, B);
    k_scatter<64><<<1216, 256>>>(src, dst, norm, A, B);

    // heads: (B + b3) -> actor softmax + critic value -> out [NN, 9]
    k_heads<<<152, 256, SM_H>>>(B, b3,
                                Wa1, ba1, Wa2, ba2, Wa3, ba3,
                                Wc1, bc1, Wc2, bc2, Wc3, bc3, out);
}

// round 4
// speedup vs baseline: 1.8510x; 1.8510x over previous
#include <cuda_runtime.h>
#include <cstddef>
#include <cstdint>

#define NN 100000
#define NE 3200000

// ---------------- scratch (module-load allocated, no runtime alloc) ----------
__device__ __align__(16) float g_bufA[(size_t)NN * 128];  // GEMM output h
__device__ __align__(16) float g_bufB[(size_t)NN * 128];  // aggregation out
__device__ float g_dinv[NN];
__device__ float g_dinv2[NN];   // 1/deg
__device__ int g_srcI[NE];
__device__ int g_dstI[NE];
__device__ int g_cnt[NN];       // in-degree counts (excl self)
__device__ int g_rowPtr[NN + 1];
__device__ int g_cur[NN];       // fill cursors
__device__ int g_eSrc[NE];      // CSR-by-dst: src per slot
__device__ float g_eNorm[NE];   // CSR-by-dst: norm per slot
__device__ int g_is64;

// ---------------- edge-index dtype probe ------------------------------------
__global__ void k_detect(const int* __restrict__ w) {
    if (blockIdx.x == 0 && threadIdx.x == 0) {
        int is64 = 1;
        for (int i = 0; i < 2048; i += 2) {
            if (w[i + 1] != 0) { is64 = 0; break; }
        }
        g_is64 = is64;
    }
}

__global__ void k_zero_cnt(int* __restrict__ cnt) {
    int i = blockIdx.x * blockDim.x + threadIdx.x;
    if (i < NN) cnt[i] = 0;
}

// unpack indices to int32 AND count in-degree (by dst) in one pass
__global__ void k_unpack_count(const int* __restrict__ w,
                               int* __restrict__ srcI, int* __restrict__ dstI,
                               int* __restrict__ cnt) {
    const int is64 = g_is64;
    long long i = (long long)blockIdx.x * blockDim.x + threadIdx.x;
    long long stride = (long long)gridDim.x * blockDim.x;
    if (is64) {
        for (; i < NE; i += stride) {
            int s = w[2 * i];
            int d = w[2 * (long long)NE + 2 * i];
            srcI[i] = s; dstI[i] = d;
            atomicAdd(&cnt[d], 1);
        }
    } else {
        for (; i < NE; i += stride) {
            int s = w[i];
            int d = w[NE + i];
            srcI[i] = s; dstI[i] = d;
            atomicAdd(&cnt[d], 1);
        }
    }
}

// single-block prefix scan over counts -> rowPtr/cur; also dinv, dinv2
__global__ void __launch_bounds__(1024)
k_scan(const int* __restrict__ cnt, int* __restrict__ rowPtr,
       int* __restrict__ cur, float* __restrict__ dinv, float* __restrict__ dinv2) {
    __shared__ int sdata[1024];
    __shared__ int sOff;
    const int tid = threadIdx.x;
    if (tid == 0) sOff = 0;
    __syncthreads();
    for (int base = 0; base < NN; base += 1024) {
        int idx = base + tid;
        int v = (idx < NN) ? cnt[idx] : 0;
        sdata[tid] = v;
        __syncthreads();
        // Hillis-Steele inclusive scan
        for (int d = 1; d < 1024; d <<= 1) {
            int t = (tid >= d) ? sdata[tid - d] : 0;
            __syncthreads();
            sdata[tid] += t;
            __syncthreads();
        }
        int incl = sdata[tid];
        int off = sOff;
        if (idx < NN) {
            int start = off + incl - v;
            rowPtr[idx] = start;
            cur[idx] = start;
            float dv = rsqrtf((float)(v + 1));   // +1 self loop
            dinv[idx] = dv;
            dinv2[idx] = dv * dv;
        }
        __syncthreads();
        if (tid == 0) sOff = off + sdata[1023];
        __syncthreads();
    }
    if (tid == 0) rowPtr[NN] = sOff;
}

// fill CSR slots: eSrc, eNorm (norm = dinv[src]*dinv[dst] folded here)
__global__ void k_fill(const int* __restrict__ src, const int* __restrict__ dst,
                       const float* __restrict__ dinv,
                       int* __restrict__ cur,
                       int* __restrict__ eSrc, float* __restrict__ eNorm) {
    long long i = (long long)blockIdx.x * blockDim.x + threadIdx.x;
    long long stride = (long long)gridDim.x * blockDim.x;
    for (; i < NE; i += stride) {
        int s = src[i];
        int d = dst[i];
        int pos = atomicAdd(&cur[d], 1);
        eSrc[pos] = s;
        eNorm[pos] = dinv[s] * dinv[d];
    }
}

// ---------------- GEMM (+ fused prev bias/ReLU) ------------------------------
// t[n,DOUT] = act(in) @ W   (act = relu(in + pb) if PREACT else in)
template <int DIN, int DOUT, bool PREACT>
__global__ void __launch_bounds__(128)
k_gemm(const float* __restrict__ in, const float* __restrict__ W,
       const float* __restrict__ pb, float* __restrict__ t) {
    extern __shared__ float sm[];
    float* sW  = sm;                     // DIN*DOUT
    float* sIn = sm + DIN * DOUT;        // 16*DIN
    float* sPb = sIn + 16 * DIN;         // DIN
    const int tid = threadIdx.x;

    for (int i = tid; i < DIN * DOUT; i += 128) sW[i] = W[i];
    if (PREACT)
        for (int i = tid; i < DIN; i += 128) sPb[i] = pb[i];
    __syncthreads();

    constexpr int CQ  = DOUT / 4;    // col-quads
    constexpr int G   = 128 / CQ;    // row groups
    constexpr int RPT = 16 / G;      // rows per thread
    const int colq = tid % CQ;
    const int grp  = tid / CQ;

    for (int tile = blockIdx.x * 16; tile < NN; tile += gridDim.x * 16) {
        for (int i = tid; i < 16 * DIN; i += 128) {
            int r = i / DIN, k = i - r * DIN;
            float v = 0.0f;
            if (tile + r < NN) {
                v = in[(size_t)(tile + r) * DIN + k];
                if (PREACT) v = fmaxf(v + sPb[k], 0.0f);
            }
            sIn[i] = v;
        }
        __syncthreads();

        float acc[RPT][4];
#pragma unroll
        for (int rr = 0; rr < RPT; rr++) {
            acc[rr][0] = 0.f; acc[rr][1] = 0.f; acc[rr][2] = 0.f; acc[rr][3] = 0.f;
        }
#pragma unroll 4
        for (int k = 0; k < DIN; k++) {
            float4 w = *reinterpret_cast<const float4*>(&sW[k * DOUT + colq * 4]);
#pragma unroll
            for (int rr = 0; rr < RPT; rr++) {
                float s = sIn[(grp * RPT + rr) * DIN + k];
                acc[rr][0] = fmaf(s, w.x, acc[rr][0]);
                acc[rr][1] = fmaf(s, w.y, acc[rr][1]);
                acc[rr][2] = fmaf(s, w.z, acc[rr][2]);
                acc[rr][3] = fmaf(s, w.w, acc[rr][3]);
            }
        }
#pragma unroll
        for (int rr = 0; rr < RPT; rr++) {
            int row = tile + grp * RPT + rr;
            if (row < NN) {
                *reinterpret_cast<float4*>(&t[(size_t)row * DOUT + colq * 4]) =
                    make_float4(acc[rr][0], acc[rr][1], acc[rr][2], acc[rr][3]);
            }
        }
        __syncthreads();
    }
}

// ---------------- CSR gather: agg[n] = sum_in h[src]*norm + h[n]*dinv2 -------
template <int DOUT>
__global__ void __launch_bounds__(256)
k_gather(const int* __restrict__ rowPtr, const int* __restrict__ eSrc,
         const float* __restrict__ eNorm, const float* __restrict__ h,
         const float* __restrict__ dinv2, float* __restrict__ agg) {
    constexpr int VPL = DOUT / 32;   // floats per lane (4 or 2)
    const int lane = threadIdx.x & 31;
    const int warpId = (blockIdx.x * blockDim.x + threadIdx.x) >> 5;
    const int nWarps = (gridDim.x * blockDim.x) >> 5;

    for (int node = warpId; node < NN; node += nWarps) {
        const int beg = rowPtr[node];
        const int end = rowPtr[node + 1];

        float acc[VPL];
        {
            const float d2 = dinv2[node];
            if (VPL == 4) {
                float4 v = *reinterpret_cast<const float4*>(
                    h + (size_t)node * DOUT + lane * 4);
                acc[0] = v.x * d2; acc[1] = v.y * d2;
                acc[2] = v.z * d2; acc[3] = v.w * d2;
            } else {
                float2 v = *reinterpret_cast<const float2*>(
                    h + (size_t)node * DOUT + lane * 2);
                acc[0] = v.x * d2; acc[1] = v.y * d2;
            }
        }

        for (int base = beg; base < end; base += 32) {
            const int cnt = min(32, end - base);
            int s = 0; float nm = 0.0f;
            if (lane < cnt) {
                s  = eSrc[base + lane];
                nm = eNorm[base + lane];
            }
            for (int j = 0; j < cnt; j++) {
                const int ss   = __shfl_sync(0xffffffffu, s, j);
                const float nn = __shfl_sync(0xffffffffu, nm, j);
                if (VPL == 4) {
                    float4 v = *reinterpret_cast<const float4*>(
                        h + (size_t)ss * DOUT + lane * 4);
                    acc[0] = fmaf(v.x, nn, acc[0]);
                    acc[1] = fmaf(v.y, nn, acc[1]);
                    acc[2] = fmaf(v.z, nn, acc[2]);
                    acc[3] = fmaf(v.w, nn, acc[3]);
                } else {
                    float2 v = *reinterpret_cast<const float2*>(
                        h + (size_t)ss * DOUT + lane * 2);
                    acc[0] = fmaf(v.x, nn, acc[0]);
                    acc[1] = fmaf(v.y, nn, acc[1]);
                }
            }
        }

        if (VPL == 4) {
            *reinterpret_cast<float4*>(agg + (size_t)node * DOUT + lane * 4) =
                make_float4(acc[0], acc[1], acc[2], acc[3]);
        } else {
            *reinterpret_cast<float2*>(agg + (size_t)node * DOUT + lane * 2) =
                make_float2(acc[0], acc[1]);
        }
    }
}

// ---------------- fused actor/critic heads + softmax -------------------------
constexpr int HO_Wa1 = 0;                       // 64*128
constexpr int HO_Wa2 = HO_Wa1 + 64 * 128;       // 128*64
constexpr int HO_Wa3 = HO_Wa2 + 128 * 64;       // 64*8
constexpr int HO_Wc1 = HO_Wa3 + 64 * 8;         // 64*128
constexpr int HO_Wc2 = HO_Wc1 + 64 * 128;       // 128*64
constexpr int HO_Wc3 = HO_Wc2 + 128 * 64;       // 64
constexpr int HO_ba1 = HO_Wc3 + 64;             // 128
constexpr int HO_ba2 = HO_ba1 + 128;            // 64
constexpr int HO_ba3 = HO_ba2 + 64;             // 8
constexpr int HO_bc1 = HO_ba3 + 8;              // 128
constexpr int HO_bc2 = HO_bc1 + 128;            // 64
constexpr int HO_bc3 = HO_bc2 + 64;             // 1
constexpr int HO_b3  = HO_bc3 + 1;              // 64
constexpr int HO_H   = HO_b3 + 64;              // 16*64
constexpr int HO_A1  = HO_H + 16 * 64;          // 16*128
constexpr int HO_C1  = HO_A1 + 16 * 128;        // 16*128
constexpr int HO_A2  = HO_C1 + 16 * 128;        // 16*64
constexpr int HO_C2  = HO_A2 + 16 * 64;         // 16*64
constexpr int HO_LOG = HO_C2 + 16 * 64;         // 16*8
constexpr int HO_VAL = HO_LOG + 16 * 8;         // 16
constexpr int HO_TOT = HO_VAL + 16;

__device__ __forceinline__ void coop_copy(float* d, const float* s, int n, int tid, int nt) {
    for (int i = tid; i < n; i += nt) d[i] = s[i];
}

__global__ void __launch_bounds__(256)
k_heads(const float* __restrict__ hagg, const float* __restrict__ b3,
        const float* __restrict__ Wa1, const float* __restrict__ ba1,
        const float* __restrict__ Wa2, const float* __restrict__ ba2,
        const float* __restrict__ Wa3, const float* __restrict__ ba3,
        const float* __restrict__ Wc1, const float* __restrict__ bc1,
        const float* __restrict__ Wc2, const float* __restrict__ bc2,
        const float* __restrict__ Wc3, const float* __restrict__ bc3,
        float* __restrict__ out) {
    extern __shared__ float sm[];
    const int t = threadIdx.x;
    coop_copy(sm + HO_Wa1, Wa1, 64 * 128, t, 256);
    coop_copy(sm + HO_Wa2, Wa2, 128 * 64, t, 256);
    coop_copy(sm + HO_Wa3, Wa3, 64 * 8, t, 256);
    coop_copy(sm + HO_Wc1, Wc1, 64 * 128, t, 256);
    coop_copy(sm + HO_Wc2, Wc2, 128 * 64, t, 256);
    coop_copy(sm + HO_Wc3, Wc3, 64, t, 256);
    coop_copy(sm + HO_ba1, ba1, 128, t, 256);
    coop_copy(sm + HO_ba2, ba2, 64, t, 256);
    coop_copy(sm + HO_ba3, ba3, 8, t, 256);
    coop_copy(sm + HO_bc1, bc1, 128, t, 256);
    coop_copy(sm + HO_bc2, bc2, 64, t, 256);
    coop_copy(sm + HO_bc3, bc3, 1, t, 256);
    coop_copy(sm + HO_b3,  b3,  64, t, 256);
    __syncthreads();

    for (int tile = blockIdx.x * 16; tile < NN; tile += gridDim.x * 16) {
        const int rows = min(16, NN - tile);
        for (int i = t; i < rows * 64; i += 256) {
            int r = i >> 6, k = i & 63;
            sm[HO_H + i] = hagg[(size_t)(tile + r) * 64 + k] + sm[HO_b3 + k];
        }
        __syncthreads();

        {
            const bool actor = t < 128;
            const int col = t & 127;
            const float* Wl = actor ? (sm + HO_Wa1) : (sm + HO_Wc1);
            const float bias = actor ? sm[HO_ba1 + col] : sm[HO_bc1 + col];
            float* dstS = actor ? (sm + HO_A1) : (sm + HO_C1);
            for (int r = 0; r < rows; r++) {
                float acc = bias;
#pragma unroll 8
                for (int k = 0; k < 64; k++)
                    acc = fmaf(sm[HO_H + r * 64 + k], Wl[k * 128 + col], acc);
                dstS[r * 128 + col] = fmaxf(acc, 0.0f);
            }
        }
        __syncthreads();

        if ((t & 127) < 64) {
            const bool actor = t < 128;
            const int col = t & 63;
            const float* Wl = actor ? (sm + HO_Wa2) : (sm + HO_Wc2);
            const float* inS = actor ? (sm + HO_A1) : (sm + HO_C1);
            const float bias = actor ? sm[HO_ba2 + col] : sm[HO_bc2 + col];
            float* dstS = actor ? (sm + HO_A2) : (sm + HO_C2);
            for (int r = 0; r < rows; r++) {
                float acc = bias;
#pragma unroll 8
                for (int k = 0; k < 128; k++)
                    acc = fmaf(inS[r * 128 + k], Wl[k * 64 + col], acc);
                dstS[r * 64 + col] = fmaxf(acc, 0.0f);
            }
        }
        __syncthreads();

        if (t < 128) {
            int r = t >> 3, a = t & 7;
            if (r < rows) {
                float acc = sm[HO_ba3 + a];
#pragma unroll 8
                for (int k = 0; k < 64; k++)
                    acc = fmaf(sm[HO_A2 + r * 64 + k], sm[HO_Wa3 + k * 8 + a], acc);
                sm[HO_LOG + r * 8 + a] = acc;
            }
        } else if (t < 144) {
            int r = t - 128;
            if (r < rows) {
                float acc = sm[HO_bc3];
#pragma unroll 8
                for (int k = 0; k < 64; k++)
                    acc = fmaf(sm[HO_C2 + r * 64 + k], sm[HO_Wc3 + k], acc);
                sm[HO_VAL + r] = acc;
            }
        }
        __syncthreads();

        if (t < rows) {
            float mx = -1e30f;
#pragma unroll
            for (int a = 0; a < 8; a++) mx = fmaxf(mx, sm[HO_LOG + t * 8 + a]);
            float e[8], ssum = 0.0f;
#pragma unroll
            for (int a = 0; a < 8; a++) {
                e[a] = expf(sm[HO_LOG + t * 8 + a] - mx);
                ssum += e[a];
            }
            float inv = 1.0f / ssum;
            size_t o = (size_t)(tile + t) * 9;
#pragma unroll
            for (int a = 0; a < 8; a++) out[o + a] = e[a] * inv;
            out[o + 8] = sm[HO_VAL + t];
        }
        __syncthreads();
    }
}

// ---------------- launch -----------------------------------------------------
extern "C" void kernel_launch(void* const* d_in, const int* in_sizes, int n_in,
                              void* d_out, int out_size) {
    const float* x   = (const float*)d_in[0];
    const int*   eiw = (const int*)d_in[1];   // raw words; dtype resolved on-device
    const float* W1 = (const float*)d_in[2];  const float* b1 = (const float*)d_in[3];
    const float* W2 = (const float*)d_in[4];  const float* b2 = (const float*)d_in[5];
    const float* W3 = (const float*)d_in[6];  const float* b3 = (const float*)d_in[7];
    const float* Wa1 = (const float*)d_in[8];  const float* ba1 = (const float*)d_in[9];
    const float* Wa2 = (const float*)d_in[10]; const float* ba2 = (const float*)d_in[11];
    const float* Wa3 = (const float*)d_in[12]; const float* ba3 = (const float*)d_in[13];
    const float* Wc1 = (const float*)d_in[14]; const float* bc1 = (const float*)d_in[15];
    const float* Wc2 = (const float*)d_in[16]; const float* bc2 = (const float*)d_in[17];
    const float* Wc3 = (const float*)d_in[18]; const float* bc3 = (const float*)d_in[19];
    float* out = (float*)d_out;

    void *pA, *pB, *pdinv, *pdinv2, *psrc, *pdst, *pcnt, *prow, *pcur, *pes, *pen;
    cudaGetSymbolAddress(&pA, g_bufA);
    cudaGetSymbolAddress(&pB, g_bufB);
    cudaGetSymbolAddress(&pdinv, g_dinv);
    cudaGetSymbolAddress(&pdinv2, g_dinv2);
    cudaGetSymbolAddress(&psrc, g_srcI);
    cudaGetSymbolAddress(&pdst, g_dstI);
    cudaGetSymbolAddress(&pcnt, g_cnt);
    cudaGetSymbolAddress(&prow, g_rowPtr);
    cudaGetSymbolAddress(&pcur, g_cur);
    cudaGetSymbolAddress(&pes, g_eSrc);
    cudaGetSymbolAddress(&pen, g_eNorm);
    float* A = (float*)pA;  float* B = (float*)pB;
    float* dinv = (float*)pdinv;  float* dinv2 = (float*)pdinv2;
    int* src = (int*)psrc;  int* dst = (int*)pdst;
    int* cnt = (int*)pcnt;  int* rowPtr = (int*)prow;  int* cur = (int*)pcur;
    int* eSrc = (int*)pes;  float* eNorm = (float*)pen;

    const int SM_G1 = (128 * 128 + 16 * 128 + 128) * 4;  // 74240
    const int SM_G2 = (128 * 64 + 16 * 128 + 128) * 4;   // 41472
    const int SM_H  = HO_TOT * 4;                        // ~164 KB

    cudaFuncSetAttribute(k_gemm<128, 128, false>,
                         cudaFuncAttributeMaxDynamicSharedMemorySize, SM_G1);
    cudaFuncSetAttribute(k_gemm<128, 128, true>,
                         cudaFuncAttributeMaxDynamicSharedMemorySize, SM_G1);
    cudaFuncSetAttribute(k_gemm<128, 64, true>,
                         cudaFuncAttributeMaxDynamicSharedMemorySize, SM_G2);
    cudaFuncSetAttribute(k_heads,
                         cudaFuncAttributeMaxDynamicSharedMemorySize, SM_H);

    // ---- CSR build (once) ----
    k_detect<<<1, 32>>>(eiw);
    k_zero_cnt<<<(NN + 255) / 256, 256>>>(cnt);
    k_unpack_count<<<2048, 256>>>(eiw, src, dst, cnt);
    k_scan<<<1, 1024>>>(cnt, rowPtr, cur, dinv, dinv2);
    k_fill<<<2048, 256>>>(src, dst, dinv, cur, eSrc, eNorm);

    // ---- layer 1: h = x @ W1 -> A; agg -> B ----
    k_gemm<128, 128, false><<<456, 128, SM_G1>>>(x, W1, b1, A);
    k_gather<128><<<1568, 256>>>(rowPtr, eSrc, eNorm, A, dinv2, B);

    // ---- layer 2: h = relu(B + b1) @ W2 -> A; agg -> B ----
    k_gemm<128, 128, true><<<456, 128, SM_G1>>>(B, W2, b1, A);
    k_gather<128><<<1568, 256>>>(rowPtr, eSrc, eNorm, A, dinv2, B);

    // ---- layer 3: h = relu(B + b2) @ W3 -> A (64-dim); agg -> B ----
    k_gemm<128, 64, true><<<456, 128, SM_G2>>>(B, W3, b2, A);
    k_gather<64><<<1568, 256>>>(rowPtr, eSrc, eNorm, A, dinv2, B);

    // ---- heads ----
    k_heads<<<152, 256, SM_H>>>(B, b3,
                                Wa1, ba1, Wa2, ba2, Wa3, ba3,
                                Wc1, bc1, Wc2, bc2, Wc3, bc3, out);
}

// round 5
// speedup vs baseline: 2.0081x; 1.0849x over previous
#include <cuda_runtime.h>
#include <cstddef>
#include <cstdint>

#define NN 100000
#define NE 3200000
#define NCHUNK ((NN + 1023) / 1024)   // 98

// ---------------- scratch (module-load allocated, no runtime alloc) ----------
__device__ __align__(16) float g_bufA[(size_t)NN * 128];  // GEMM output h
__device__ __align__(16) float g_bufB[(size_t)NN * 128];  // aggregation out
__device__ float g_dinv[NN];
__device__ float g_dinv2[NN];
__device__ int g_srcI[NE];
__device__ int g_dstI[NE];
__device__ int g_cnt[NN];         // in-degree counts (excl self)
__device__ int g_rowPtr[NN + 1];
__device__ int g_cur[NN];         // fill cursors
__device__ int g_eSrc[NE];        // CSR-by-dst: src per slot
__device__ float g_eNorm[NE];     // CSR-by-dst: norm per slot
__device__ int g_chunkSum[NCHUNK];
__device__ int g_chunkOff[NCHUNK + 1];
__device__ int g_is64;

// ---------------- edge-index dtype probe ------------------------------------
__global__ void k_detect(const int* __restrict__ w) {
    if (blockIdx.x == 0 && threadIdx.x == 0) {
        int is64 = 1;
        for (int i = 0; i < 2048; i += 2) {
            if (w[i + 1] != 0) { is64 = 0; break; }
        }
        g_is64 = is64;
    }
}

__global__ void k_zero_cnt(int* __restrict__ cnt) {
    int i = blockIdx.x * blockDim.x + threadIdx.x;
    if (i < NN) cnt[i] = 0;
}

// unpack indices to int32 AND count in-degree (by dst) in one pass
__global__ void k_unpack_count(const int* __restrict__ w,
                               int* __restrict__ srcI, int* __restrict__ dstI,
                               int* __restrict__ cnt) {
    const int is64 = g_is64;
    long long i = (long long)blockIdx.x * blockDim.x + threadIdx.x;
    long long stride = (long long)gridDim.x * blockDim.x;
    if (is64) {
        for (; i < NE; i += stride) {
            int s = w[2 * i];
            int d = w[2 * (long long)NE + 2 * i];
            srcI[i] = s; dstI[i] = d;
            atomicAdd(&cnt[d], 1);
        }
    } else {
        const int2* w2s = reinterpret_cast<const int2*>(w);
        const int2* w2d = reinterpret_cast<const int2*>(w + NE);
        for (; i < NE / 2; i += stride) {
            int2 s2 = w2s[i];
            int2 d2 = w2d[i];
            srcI[2 * i] = s2.x;  srcI[2 * i + 1] = s2.y;
            dstI[2 * i] = d2.x;  dstI[2 * i + 1] = d2.y;
            atomicAdd(&cnt[d2.x], 1);
            atomicAdd(&cnt[d2.y], 1);
        }
    }
}

// ---------------- parallel 3-phase prefix scan -------------------------------
// phase 1: per-chunk (1024 counts) sum
__global__ void __launch_bounds__(1024)
k_chunk_sum(const int* __restrict__ cnt, int* __restrict__ chunkSum) {
    __shared__ int sred[32];
    const int tid = threadIdx.x;
    const int idx = blockIdx.x * 1024 + tid;
    int v = (idx < NN) ? cnt[idx] : 0;
    // warp reduce
    for (int o = 16; o > 0; o >>= 1) v += __shfl_down_sync(0xffffffffu, v, o);
    if ((tid & 31) == 0) sred[tid >> 5] = v;
    __syncthreads();
    if (tid < 32) {
        int x = sred[tid];
        for (int o = 16; o > 0; o >>= 1) x += __shfl_down_sync(0xffffffffu, x, o);
        if (tid == 0) chunkSum[blockIdx.x] = x;
    }
}

// phase 2: exclusive scan of NCHUNK partials (one small block)
__global__ void __launch_bounds__(128)
k_scan_part(const int* __restrict__ chunkSum, int* __restrict__ chunkOff) {
    __shared__ int s[NCHUNK];
    const int tid = threadIdx.x;
    for (int i = tid; i < NCHUNK; i += 128) s[i] = chunkSum[i];
    __syncthreads();
    if (tid == 0) {
        int acc = 0;
        for (int i = 0; i < NCHUNK; i++) { int v = s[i]; s[i] = acc; acc += v; }
        chunkOff[NCHUNK] = acc;
    }
    __syncthreads();
    for (int i = tid; i < NCHUNK; i += 128) chunkOff[i] = s[i];
}

// phase 3: local scan within each chunk + global offset; emit rowPtr/cur/dinv
__global__ void __launch_bounds__(1024)
k_scan_final(const int* __restrict__ cnt, const int* __restrict__ chunkOff,
             int* __restrict__ rowPtr, int* __restrict__ cur,
             float* __restrict__ dinv, float* __restrict__ dinv2) {
    __shared__ int sdata[1024];
    __shared__ int swarp[32];
    const int tid = threadIdx.x;
    const int idx = blockIdx.x * 1024 + tid;
    int v = (idx < NN) ? cnt[idx] : 0;

    // warp-level inclusive scan
    int incl = v;
    for (int o = 1; o < 32; o <<= 1) {
        int t = __shfl_up_sync(0xffffffffu, incl, o);
        if ((tid & 31) >= o) incl += t;
    }
    if ((tid & 31) == 31) swarp[tid >> 5] = incl;
    __syncthreads();
    if (tid < 32) {
        int x = swarp[tid];
        for (int o = 1; o < 32; o <<= 1) {
            int t = __shfl_up_sync(0xffffffffu, x, o);
            if (tid >= o) x += t;
        }
        swarp[tid] = x;
    }
    __syncthreads();
    int warpBase = (tid >= 32) ? swarp[(tid >> 5) - 1] : 0;
    int inclTotal = incl + warpBase;

    if (idx < NN) {
        int start = chunkOff[blockIdx.x] + inclTotal - v;
        rowPtr[idx] = start;
        cur[idx] = start;
        float dv = rsqrtf((float)(v + 1));   // +1 self loop
        dinv[idx] = dv;
        dinv2[idx] = dv * dv;
    }
    if (blockIdx.x == gridDim.x - 1 && tid == 0)
        rowPtr[NN] = chunkOff[NCHUNK];
    (void)sdata;
}

// fill CSR slots: eSrc, eNorm (norm = dinv[src]*dinv[dst] folded here)
__global__ void k_fill(const int* __restrict__ src, const int* __restrict__ dst,
                       const float* __restrict__ dinv,
                       int* __restrict__ cur,
                       int* __restrict__ eSrc, float* __restrict__ eNorm) {
    long long i = (long long)blockIdx.x * blockDim.x + threadIdx.x;
    long long stride = (long long)gridDim.x * blockDim.x;
    for (; i < NE; i += stride) {
        int s = src[i];
        int d = dst[i];
        int pos = atomicAdd(&cur[d], 1);
        eSrc[pos] = s;
        eNorm[pos] = dinv[s] * dinv[d];
    }
}

// ---------------- GEMM (+ fused prev bias/ReLU) ------------------------------
template <int DIN, int DOUT, bool PREACT>
__global__ void __launch_bounds__(128)
k_gemm(const float* __restrict__ in, const float* __restrict__ W,
       const float* __restrict__ pb, float* __restrict__ t) {
    extern __shared__ float sm[];
    float* sW  = sm;                     // DIN*DOUT
    float* sIn = sm + DIN * DOUT;        // 16*DIN
    float* sPb = sIn + 16 * DIN;         // DIN
    const int tid = threadIdx.x;

    for (int i = tid; i < DIN * DOUT; i += 128) sW[i] = W[i];
    if (PREACT)
        for (int i = tid; i < DIN; i += 128) sPb[i] = pb[i];
    __syncthreads();

    constexpr int CQ  = DOUT / 4;
    constexpr int G   = 128 / CQ;
    constexpr int RPT = 16 / G;
    const int colq = tid % CQ;
    const int grp  = tid / CQ;

    for (int tile = blockIdx.x * 16; tile < NN; tile += gridDim.x * 16) {
        for (int i = tid; i < 16 * DIN; i += 128) {
            int r = i / DIN, k = i - r * DIN;
            float v = 0.0f;
            if (tile + r < NN) {
                v = in[(size_t)(tile + r) * DIN + k];
                if (PREACT) v = fmaxf(v + sPb[k], 0.0f);
            }
            sIn[i] = v;
        }
        __syncthreads();

        float acc[RPT][4];
#pragma unroll
        for (int rr = 0; rr < RPT; rr++) {
            acc[rr][0] = 0.f; acc[rr][1] = 0.f; acc[rr][2] = 0.f; acc[rr][3] = 0.f;
        }
#pragma unroll 4
        for (int k = 0; k < DIN; k++) {
            float4 w = *reinterpret_cast<const float4*>(&sW[k * DOUT + colq * 4]);
#pragma unroll
            for (int rr = 0; rr < RPT; rr++) {
                float s = sIn[(grp * RPT + rr) * DIN + k];
                acc[rr][0] = fmaf(s, w.x, acc[rr][0]);
                acc[rr][1] = fmaf(s, w.y, acc[rr][1]);
                acc[rr][2] = fmaf(s, w.z, acc[rr][2]);
                acc[rr][3] = fmaf(s, w.w, acc[rr][3]);
            }
        }
#pragma unroll
        for (int rr = 0; rr < RPT; rr++) {
            int row = tile + grp * RPT + rr;
            if (row < NN) {
                *reinterpret_cast<float4*>(&t[(size_t)row * DOUT + colq * 4]) =
                    make_float4(acc[rr][0], acc[rr][1], acc[rr][2], acc[rr][3]);
            }
        }
        __syncthreads();
    }
}

// ---------------- CSR gather: agg[n] = sum_in h[src]*norm + h[n]*dinv2 -------
template <int DOUT>
__global__ void __launch_bounds__(256)
k_gather(const int* __restrict__ rowPtr, const int* __restrict__ eSrc,
         const float* __restrict__ eNorm, const float* __restrict__ h,
         const float* __restrict__ dinv2, float* __restrict__ agg) {
    constexpr int VPL = DOUT / 32;   // floats per lane (4 or 2)
    const int lane = threadIdx.x & 31;
    const int warpId = (blockIdx.x * blockDim.x + threadIdx.x) >> 5;
    const int nWarps = (gridDim.x * blockDim.x) >> 5;

    for (int node = warpId; node < NN; node += nWarps) {
        const int beg = rowPtr[node];
        const int end = rowPtr[node + 1];

        float acc[VPL];
        {
            const float d2 = dinv2[node];
            if (VPL == 4) {
                float4 v = *reinterpret_cast<const float4*>(
                    h + (size_t)node * DOUT + lane * 4);
                acc[0] = v.x * d2; acc[1] = v.y * d2;
                acc[2] = v.z * d2; acc[3] = v.w * d2;
            } else {
                float2 v = *reinterpret_cast<const float2*>(
                    h + (size_t)node * DOUT + lane * 2);
                acc[0] = v.x * d2; acc[1] = v.y * d2;
            }
        }

        for (int base = beg; base < end; base += 32) {
            const int cnt = min(32, end - base);
            int s = 0; float nm = 0.0f;
            if (lane < cnt) {
                s  = eSrc[base + lane];
                nm = eNorm[base + lane];
            }
            int j = 0;
            // 2-deep: two independent gathers in flight per iteration
            for (; j + 1 < cnt; j += 2) {
                const int ss0   = __shfl_sync(0xffffffffu, s,  j);
                const float nn0 = __shfl_sync(0xffffffffu, nm, j);
                const int ss1   = __shfl_sync(0xffffffffu, s,  j + 1);
                const float nn1 = __shfl_sync(0xffffffffu, nm, j + 1);
                if (VPL == 4) {
                    float4 v0 = *reinterpret_cast<const float4*>(
                        h + (size_t)ss0 * DOUT + lane * 4);
                    float4 v1 = *reinterpret_cast<const float4*>(
                        h + (size_t)ss1 * DOUT + lane * 4);
                    acc[0] = fmaf(v0.x, nn0, acc[0]);
                    acc[1] = fmaf(v0.y, nn0, acc[1]);
                    acc[2] = fmaf(v0.z, nn0, acc[2]);
                    acc[3] = fmaf(v0.w, nn0, acc[3]);
                    acc[0] = fmaf(v1.x, nn1, acc[0]);
                    acc[1] = fmaf(v1.y, nn1, acc[1]);
                    acc[2] = fmaf(v1.z, nn1, acc[2]);
                    acc[3] = fmaf(v1.w, nn1, acc[3]);
                } else {
                    float2 v0 = *reinterpret_cast<const float2*>(
                        h + (size_t)ss0 * DOUT + lane * 2);
                    float2 v1 = *reinterpret_cast<const float2*>(
                        h + (size_t)ss1 * DOUT + lane * 2);
                    acc[0] = fmaf(v0.x, nn0, acc[0]);
                    acc[1] = fmaf(v0.y, nn0, acc[1]);
                    acc[0] = fmaf(v1.x, nn1, acc[0]);
                    acc[1] = fmaf(v1.y, nn1, acc[1]);
                }
            }
            if (j < cnt) {
                const int ss   = __shfl_sync(0xffffffffu, s,  j);
                const float nn = __shfl_sync(0xffffffffu, nm, j);
                if (VPL == 4) {
                    float4 v = *reinterpret_cast<const float4*>(
                        h + (size_t)ss * DOUT + lane * 4);
                    acc[0] = fmaf(v.x, nn, acc[0]);
                    acc[1] = fmaf(v.y, nn, acc[1]);
                    acc[2] = fmaf(v.z, nn, acc[2]);
                    acc[3] = fmaf(v.w, nn, acc[3]);
                } else {
                    float2 v = *reinterpret_cast<const float2*>(
                        h + (size_t)ss * DOUT + lane * 2);
                    acc[0] = fmaf(v.x, nn, acc[0]);
                    acc[1] = fmaf(v.y, nn, acc[1]);
                }
            }
        }

        if (VPL == 4) {
            *reinterpret_cast<float4*>(agg + (size_t)node * DOUT + lane * 4) =
                make_float4(acc[0], acc[1], acc[2], acc[3]);
        } else {
            *reinterpret_cast<float2*>(agg + (size_t)node * DOUT + lane * 2) =
                make_float2(acc[0], acc[1]);
        }
    }
}

// ---------------- fused actor/critic heads + softmax -------------------------
constexpr int HO_Wa1 = 0;
constexpr int HO_Wa2 = HO_Wa1 + 64 * 128;
constexpr int HO_Wa3 = HO_Wa2 + 128 * 64;
constexpr int HO_Wc1 = HO_Wa3 + 64 * 8;
constexpr int HO_Wc2 = HO_Wc1 + 64 * 128;
constexpr int HO_Wc3 = HO_Wc2 + 128 * 64;
constexpr int HO_ba1 = HO_Wc3 + 64;
constexpr int HO_ba2 = HO_ba1 + 128;
constexpr int HO_ba3 = HO_ba2 + 64;
constexpr int HO_bc1 = HO_ba3 + 8;
constexpr int HO_bc2 = HO_bc1 + 128;
constexpr int HO_bc3 = HO_bc2 + 64;
constexpr int HO_b3  = HO_bc3 + 1;
constexpr int HO_H   = HO_b3 + 64;
constexpr int HO_A1  = HO_H + 16 * 64;
constexpr int HO_C1  = HO_A1 + 16 * 128;
constexpr int HO_A2  = HO_C1 + 16 * 128;
constexpr int HO_C2  = HO_A2 + 16 * 64;
constexpr int HO_LOG = HO_C2 + 16 * 64;
constexpr int HO_VAL = HO_LOG + 16 * 8;
constexpr int HO_TOT = HO_VAL + 16;

__device__ __forceinline__ void coop_copy(float* d, const float* s, int n, int tid, int nt) {
    for (int i = tid; i < n; i += nt) d[i] = s[i];
}

__global__ void __launch_bounds__(256)
k_heads(const float* __restrict__ hagg, const float* __restrict__ b3,
        const float* __restrict__ Wa1, const float* __restrict__ ba1,
        const float* __restrict__ Wa2, const float* __restrict__ ba2,
        const float* __restrict__ Wa3, const float* __restrict__ ba3,
        const float* __restrict__ Wc1, const float* __restrict__ bc1,
        const float* __restrict__ Wc2, const float* __restrict__ bc2,
        const float* __restrict__ Wc3, const float* __restrict__ bc3,
        float* __restrict__ out) {
    extern __shared__ float sm[];
    const int t = threadIdx.x;
    coop_copy(sm + HO_Wa1, Wa1, 64 * 128, t, 256);
    coop_copy(sm + HO_Wa2, Wa2, 128 * 64, t, 256);
    coop_copy(sm + HO_Wa3, Wa3, 64 * 8, t, 256);
    coop_copy(sm + HO_Wc1, Wc1, 64 * 128, t, 256);
    coop_copy(sm + HO_Wc2, Wc2, 128 * 64, t, 256);
    coop_copy(sm + HO_Wc3, Wc3, 64, t, 256);
    coop_copy(sm + HO_ba1, ba1, 128, t, 256);
    coop_copy(sm + HO_ba2, ba2, 64, t, 256);
    coop_copy(sm + HO_ba3, ba3, 8, t, 256);
    coop_copy(sm + HO_bc1, bc1, 128, t, 256);
    coop_copy(sm + HO_bc2, bc2, 64, t, 256);
    coop_copy(sm + HO_bc3, bc3, 1, t, 256);
    coop_copy(sm + HO_b3,  b3,  64, t, 256);
    __syncthreads();

    for (int tile = blockIdx.x * 16; tile < NN; tile += gridDim.x * 16) {
        const int rows = min(16, NN - tile);
        for (int i = t; i < rows * 64; i += 256) {
            int r = i >> 6, k = i & 63;
            sm[HO_H + i] = hagg[(size_t)(tile + r) * 64 + k] + sm[HO_b3 + k];
        }
        __syncthreads();

        {
            const bool actor = t < 128;
            const int col = t & 127;
            const float* Wl = actor ? (sm + HO_Wa1) : (sm + HO_Wc1);
            const float bias = actor ? sm[HO_ba1 + col] : sm[HO_bc1 + col];
            float* dstS = actor ? (sm + HO_A1) : (sm + HO_C1);
            for (int r = 0; r < rows; r++) {
                float acc = bias;
#pragma unroll 8
                for (int k = 0; k < 64; k++)
                    acc = fmaf(sm[HO_H + r * 64 + k], Wl[k * 128 + col], acc);
                dstS[r * 128 + col] = fmaxf(acc, 0.0f);
            }
        }
        __syncthreads();

        if ((t & 127) < 64) {
            const bool actor = t < 128;
            const int col = t & 63;
            const float* Wl = actor ? (sm + HO_Wa2) : (sm + HO_Wc2);
            const float* inS = actor ? (sm + HO_A1) : (sm + HO_C1);
            const float bias = actor ? sm[HO_ba2 + col] : sm[HO_bc2 + col];
            float* dstS = actor ? (sm + HO_A2) : (sm + HO_C2);
            for (int r = 0; r < rows; r++) {
                float acc = bias;
#pragma unroll 8
                for (int k = 0; k < 128; k++)
                    acc = fmaf(inS[r * 128 + k], Wl[k * 64 + col], acc);
                dstS[r * 64 + col] = fmaxf(acc, 0.0f);
            }
        }
        __syncthreads();

        if (t < 128) {
            int r = t >> 3, a = t & 7;
            if (r < rows) {
                float acc = sm[HO_ba3 + a];
#pragma unroll 8
                for (int k = 0; k < 64; k++)
                    acc = fmaf(sm[HO_A2 + r * 64 + k], sm[HO_Wa3 + k * 8 + a], acc);
                sm[HO_LOG + r * 8 + a] = acc;
            }
        } else if (t < 144) {
            int r = t - 128;
            if (r < rows) {
                float acc = sm[HO_bc3];
#pragma unroll 8
                for (int k = 0; k < 64; k++)
                    acc = fmaf(sm[HO_C2 + r * 64 + k], sm[HO_Wc3 + k], acc);
                sm[HO_VAL + r] = acc;
            }
        }
        __syncthreads();

        if (t < rows) {
            float mx = -1e30f;
#pragma unroll
            for (int a = 0; a < 8; a++) mx = fmaxf(mx, sm[HO_LOG + t * 8 + a]);
            float e[8], ssum = 0.0f;
#pragma unroll
            for (int a = 0; a < 8; a++) {
                e[a] = expf(sm[HO_LOG + t * 8 + a] - mx);
                ssum += e[a];
            }
            float inv = 1.0f / ssum;
            size_t o = (size_t)(tile + t) * 9;
#pragma unroll
            for (int a = 0; a < 8; a++) out[o + a] = e[a] * inv;
            out[o + 8] = sm[HO_VAL + t];
        }
        __syncthreads();
    }
}

// ---------------- launch -----------------------------------------------------
extern "C" void kernel_launch(void* const* d_in, const int* in_sizes, int n_in,
                              void* d_out, int out_size) {
    const float* x   = (const float*)d_in[0];
    const int*   eiw = (const int*)d_in[1];
    const float* W1 = (const float*)d_in[2];  const float* b1 = (const float*)d_in[3];
    const float* W2 = (const float*)d_in[4];  const float* b2 = (const float*)d_in[5];
    const float* W3 = (const float*)d_in[6];  const float* b3 = (const float*)d_in[7];
    const float* Wa1 = (const float*)d_in[8];  const float* ba1 = (const float*)d_in[9];
    const float* Wa2 = (const float*)d_in[10]; const float* ba2 = (const float*)d_in[11];
    const float* Wa3 = (const float*)d_in[12]; const float* ba3 = (const float*)d_in[13];
    const float* Wc1 = (const float*)d_in[14]; const float* bc1 = (const float*)d_in[15];
    const float* Wc2 = (const float*)d_in[16]; const float* bc2 = (const float*)d_in[17];
    const float* Wc3 = (const float*)d_in[18]; const float* bc3 = (const float*)d_in[19];
    float* out = (float*)d_out;

    void *pA, *pB, *pdinv, *pdinv2, *psrc, *pdst, *pcnt, *prow, *pcur, *pes, *pen;
    void *pcs, *pco;
    cudaGetSymbolAddress(&pA, g_bufA);
    cudaGetSymbolAddress(&pB, g_bufB);
    cudaGetSymbolAddress(&pdinv, g_dinv);
    cudaGetSymbolAddress(&pdinv2, g_dinv2);
    cudaGetSymbolAddress(&psrc, g_srcI);
    cudaGetSymbolAddress(&pdst, g_dstI);
    cudaGetSymbolAddress(&pcnt, g_cnt);
    cudaGetSymbolAddress(&prow, g_rowPtr);
    cudaGetSymbolAddress(&pcur, g_cur);
    cudaGetSymbolAddress(&pes, g_eSrc);
    cudaGetSymbolAddress(&pen, g_eNorm);
    cudaGetSymbolAddress(&pcs, g_chunkSum);
    cudaGetSymbolAddress(&pco, g_chunkOff);
    float* A = (float*)pA;  float* B = (float*)pB;
    float* dinv = (float*)pdinv;  float* dinv2 = (float*)pdinv2;
    int* src = (int*)psrc;  int* dst = (int*)pdst;
    int* cnt = (int*)pcnt;  int* rowPtr = (int*)prow;  int* cur = (int*)pcur;
    int* eSrc = (int*)pes;  float* eNorm = (float*)pen;
    int* chunkSum = (int*)pcs;  int* chunkOff = (int*)pco;

    const int SM_G1 = (128 * 128 + 16 * 128 + 128) * 4;  // 74240
    const int SM_G2 = (128 * 64 + 16 * 128 + 128) * 4;   // 41472
    const int SM_H  = HO_TOT * 4;                        // ~164 KB

    cudaFuncSetAttribute(k_gemm<128, 128, false>,
                         cudaFuncAttributeMaxDynamicSharedMemorySize, SM_G1);
    cudaFuncSetAttribute(k_gemm<128, 128, true>,
                         cudaFuncAttributeMaxDynamicSharedMemorySize, SM_G1);
    cudaFuncSetAttribute(k_gemm<128, 64, true>,
                         cudaFuncAttributeMaxDynamicSharedMemorySize, SM_G2);
    cudaFuncSetAttribute(k_heads,
                         cudaFuncAttributeMaxDynamicSharedMemorySize, SM_H);

    // ---- CSR build (once) ----
    k_detect<<<1, 32>>>(eiw);
    k_zero_cnt<<<(NN + 255) / 256, 256>>>(cnt);
    k_unpack_count<<<2048, 256>>>(eiw, src, dst, cnt);
    k_chunk_sum<<<NCHUNK, 1024>>>(cnt, chunkSum);
    k_scan_part<<<1, 128>>>(chunkSum, chunkOff);
    k_scan_final<<<NCHUNK, 1024>>>(cnt, chunkOff, rowPtr, cur, dinv, dinv2);
    k_fill<<<2048, 256>>>(src, dst, dinv, cur, eSrc, eNorm);

    // ---- layer 1: h = x @ W1 -> A; agg -> B ----
    k_gemm<128, 128, false><<<456, 128, SM_G1>>>(x, W1, b1, A);
    k_gather<128><<<1568, 256>>>(rowPtr, eSrc, eNorm, A, dinv2, B);

    // ---- layer 2: h = relu(B + b1) @ W2 -> A; agg -> B ----
    k_gemm<128, 128, true><<<456, 128, SM_G1>>>(B, W2, b1, A);
    k_gather<128><<<1568, 256>>>(rowPtr, eSrc, eNorm, A, dinv2, B);

    // ---- layer 3: h = relu(B + b2) @ W3 -> A (64-dim); agg -> B ----
    k_gemm<128, 64, true><<<456, 128, SM_G2>>>(B, W3, b2, A);
    k_gather<64><<<1568, 256>>>(rowPtr, eSrc, eNorm, A, dinv2, B);

    // ---- heads ----
    k_heads<<<152, 256, SM_H>>>(B, b3,
                                Wa1, ba1, Wa2, ba2, Wa3, ba3,
                                Wc1, bc1, Wc2, bc2, Wc3, bc3, out);
}

// round 6
// speedup vs baseline: 2.8670x; 1.4278x over previous
#include <cuda_runtime.h>
#include <cuda_fp16.h>
#include <cstddef>
#include <cstdint>

#define NN 100000
#define NE 3200000
#define NCHUNK ((NN + 1023) / 1024)   // 98

// ---------------- scratch (module-load allocated, no runtime alloc) ----------
__device__ __align__(16) __half g_h[(size_t)NN * 128];   // GEMM output (fp16)
__device__ __align__(16) float g_bufB[(size_t)NN * 128]; // aggregation out (fp32)
__device__ float g_dinv[NN];
__device__ float g_dinv2[NN];
__device__ int g_cnt[NN];
__device__ int g_rowPtr[NN + 1];
__device__ int g_cur[NN];
__device__ __align__(16) int2 g_ePack[NE];   // {src, norm-as-int} per CSR slot
__device__ int g_chunkSum[NCHUNK];
__device__ int g_chunkOff[NCHUNK + 1];
__device__ int g_is64;

// ---------------- edge-index dtype probe ------------------------------------
__global__ void k_detect(const int* __restrict__ w) {
    if (blockIdx.x == 0 && threadIdx.x == 0) {
        int is64 = 1;
        for (int i = 0; i < 2048; i += 2) {
            if (w[i + 1] != 0) { is64 = 0; break; }
        }
        g_is64 = is64;
    }
}

__global__ void k_zero_cnt(int* __restrict__ cnt) {
    int i = blockIdx.x * blockDim.x + threadIdx.x;
    if (i < NN) cnt[i] = 0;
}

// count in-degree by dst straight from raw words
__global__ void k_count(const int* __restrict__ w, int* __restrict__ cnt) {
    const int is64 = g_is64;
    long long i = (long long)blockIdx.x * blockDim.x + threadIdx.x;
    long long stride = (long long)gridDim.x * blockDim.x;
    if (is64) {
        for (; i < NE; i += stride)
            atomicAdd(&cnt[w[2 * (long long)NE + 2 * i]], 1);
    } else {
        for (; i < NE; i += stride)
            atomicAdd(&cnt[w[NE + i]], 1);
    }
}

// ---------------- parallel 3-phase prefix scan -------------------------------
__global__ void __launch_bounds__(1024)
k_chunk_sum(const int* __restrict__ cnt, int* __restrict__ chunkSum) {
    __shared__ int sred[32];
    const int tid = threadIdx.x;
    const int idx = blockIdx.x * 1024 + tid;
    int v = (idx < NN) ? cnt[idx] : 0;
    for (int o = 16; o > 0; o >>= 1) v += __shfl_down_sync(0xffffffffu, v, o);
    if ((tid & 31) == 0) sred[tid >> 5] = v;
    __syncthreads();
    if (tid < 32) {
        int x = sred[tid];
        for (int o = 16; o > 0; o >>= 1) x += __shfl_down_sync(0xffffffffu, x, o);
        if (tid == 0) chunkSum[blockIdx.x] = x;
    }
}

__global__ void __launch_bounds__(128)
k_scan_part(const int* __restrict__ chunkSum, int* __restrict__ chunkOff) {
    __shared__ int s[NCHUNK];
    const int tid = threadIdx.x;
    for (int i = tid; i < NCHUNK; i += 128) s[i] = chunkSum[i];
    __syncthreads();
    if (tid == 0) {
        int acc = 0;
        for (int i = 0; i < NCHUNK; i++) { int v = s[i]; s[i] = acc; acc += v; }
        chunkOff[NCHUNK] = acc;
    }
    __syncthreads();
    for (int i = tid; i < NCHUNK; i += 128) chunkOff[i] = s[i];
}

__global__ void __launch_bounds__(1024)
k_scan_final(const int* __restrict__ cnt, const int* __restrict__ chunkOff,
             int* __restrict__ rowPtr, int* __restrict__ cur,
             float* __restrict__ dinv, float* __restrict__ dinv2) {
    __shared__ int swarp[32];
    const int tid = threadIdx.x;
    const int idx = blockIdx.x * 1024 + tid;
    int v = (idx < NN) ? cnt[idx] : 0;

    int incl = v;
    for (int o = 1; o < 32; o <<= 1) {
        int t = __shfl_up_sync(0xffffffffu, incl, o);
        if ((tid & 31) >= o) incl += t;
    }
    if ((tid & 31) == 31) swarp[tid >> 5] = incl;
    __syncthreads();
    if (tid < 32) {
        int x = swarp[tid];
        for (int o = 1; o < 32; o <<= 1) {
            int t = __shfl_up_sync(0xffffffffu, x, o);
            if (tid >= o) x += t;
        }
        swarp[tid] = x;
    }
    __syncthreads();
    int warpBase = (tid >= 32) ? swarp[(tid >> 5) - 1] : 0;
    int inclTotal = incl + warpBase;

    if (idx < NN) {
        int start = chunkOff[blockIdx.x] + inclTotal - v;
        rowPtr[idx] = start;
        cur[idx] = start;
        float dv = rsqrtf((float)(v + 1));
        dinv[idx] = dv;
        dinv2[idx] = dv * dv;
    }
    if (blockIdx.x == gridDim.x - 1 && tid == 0)
        rowPtr[NN] = chunkOff[NCHUNK];
}

// fill CSR slots straight from raw words: ePack = {src, norm}
__global__ void k_fill(const int* __restrict__ w, const float* __restrict__ dinv,
                       int* __restrict__ cur, int2* __restrict__ ePack) {
    const int is64 = g_is64;
    long long i = (long long)blockIdx.x * blockDim.x + threadIdx.x;
    long long stride = (long long)gridDim.x * blockDim.x;
    for (; i < NE; i += stride) {
        int s, d;
        if (is64) { s = w[2 * i]; d = w[2 * (long long)NE + 2 * i]; }
        else      { s = w[i];     d = w[NE + i]; }
        int pos = atomicAdd(&cur[d], 1);
        ePack[pos] = make_int2(s, __float_as_int(dinv[s] * dinv[d]));
    }
}

// ---------------- GEMM (+ fused prev bias/ReLU), fp16 output -----------------
template <int DIN, int DOUT, bool PREACT>
__global__ void __launch_bounds__(128)
k_gemm(const float* __restrict__ in, const float* __restrict__ W,
       const float* __restrict__ pb, __half* __restrict__ t) {
    extern __shared__ float sm[];
    float* sW  = sm;                     // DIN*DOUT
    float* sIn = sm + DIN * DOUT;        // 16*DIN
    float* sPb = sIn + 16 * DIN;         // DIN
    const int tid = threadIdx.x;

    for (int i = tid; i < DIN * DOUT; i += 128) sW[i] = W[i];
    if (PREACT)
        for (int i = tid; i < DIN; i += 128) sPb[i] = pb[i];
    __syncthreads();

    constexpr int CQ  = DOUT / 4;
    constexpr int G   = 128 / CQ;
    constexpr int RPT = 16 / G;
    const int colq = tid % CQ;
    const int grp  = tid / CQ;

    for (int tile = blockIdx.x * 16; tile < NN; tile += gridDim.x * 16) {
        for (int i = tid; i < 16 * DIN; i += 128) {
            int r = i / DIN, k = i - r * DIN;
            float v = 0.0f;
            if (tile + r < NN) {
                v = in[(size_t)(tile + r) * DIN + k];
                if (PREACT) v = fmaxf(v + sPb[k], 0.0f);
            }
            sIn[i] = v;
        }
        __syncthreads();

        float acc[RPT][4];
#pragma unroll
        for (int rr = 0; rr < RPT; rr++) {
            acc[rr][0] = 0.f; acc[rr][1] = 0.f; acc[rr][2] = 0.f; acc[rr][3] = 0.f;
        }
#pragma unroll 4
        for (int k = 0; k < DIN; k++) {
            float4 w = *reinterpret_cast<const float4*>(&sW[k * DOUT + colq * 4]);
#pragma unroll
            for (int rr = 0; rr < RPT; rr++) {
                float s = sIn[(grp * RPT + rr) * DIN + k];
                acc[rr][0] = fmaf(s, w.x, acc[rr][0]);
                acc[rr][1] = fmaf(s, w.y, acc[rr][1]);
                acc[rr][2] = fmaf(s, w.z, acc[rr][2]);
                acc[rr][3] = fmaf(s, w.w, acc[rr][3]);
            }
        }
#pragma unroll
        for (int rr = 0; rr < RPT; rr++) {
            int row = tile + grp * RPT + rr;
            if (row < NN) {
                __half2 p0 = __floats2half2_rn(acc[rr][0], acc[rr][1]);
                __half2 p1 = __floats2half2_rn(acc[rr][2], acc[rr][3]);
                uint2 raw;
                raw.x = *reinterpret_cast<unsigned*>(&p0);
                raw.y = *reinterpret_cast<unsigned*>(&p1);
                *reinterpret_cast<uint2*>(t + (size_t)row * DOUT + colq * 4) = raw;
            }
        }
        __syncthreads();
    }
}

// ---------------- CSR gather (fp16 in, fp32 out) -----------------------------
template <int DOUT>
__global__ void __launch_bounds__(256)
k_gather(const int* __restrict__ rowPtr, const int2* __restrict__ ePack,
         const __half* __restrict__ h, const float* __restrict__ dinv2,
         float* __restrict__ agg) {
    constexpr int VPL = DOUT / 32;   // halves per lane (4 or 2)
    const int lane = threadIdx.x & 31;
    const int warpId = (blockIdx.x * blockDim.x + threadIdx.x) >> 5;
    const int nWarps = (gridDim.x * blockDim.x) >> 5;

    for (int node = warpId; node < NN; node += nWarps) {
        const int beg = rowPtr[node];
        const int end = rowPtr[node + 1];

        float acc[VPL];
        {
            const float d2 = dinv2[node];
            const __half* hp = h + (size_t)node * DOUT + lane * VPL;
            if (VPL == 4) {
                uint2 raw = *reinterpret_cast<const uint2*>(hp);
                __half2 a = *reinterpret_cast<__half2*>(&raw.x);
                __half2 b = *reinterpret_cast<__half2*>(&raw.y);
                acc[0] = __low2float(a) * d2;  acc[1] = __high2float(a) * d2;
                acc[2] = __low2float(b) * d2;  acc[3] = __high2float(b) * d2;
            } else {
                unsigned raw = *reinterpret_cast<const unsigned*>(hp);
                __half2 a = *reinterpret_cast<__half2*>(&raw);
                acc[0] = __low2float(a) * d2;  acc[1] = __high2float(a) * d2;
            }
        }

        for (int base = beg; base < end; base += 32) {
            const int cnt = min(32, end - base);
            int s = 0; float nm = 0.0f;
            if (lane < cnt) {
                int2 e = ePack[base + lane];
                s = e.x; nm = __int_as_float(e.y);
            }
            int j = 0;
            for (; j + 1 < cnt; j += 2) {
                const int ss0   = __shfl_sync(0xffffffffu, s,  j);
                const float nn0 = __shfl_sync(0xffffffffu, nm, j);
                const int ss1   = __shfl_sync(0xffffffffu, s,  j + 1);
                const float nn1 = __shfl_sync(0xffffffffu, nm, j + 1);
                const __half* p0 = h + (size_t)ss0 * DOUT + lane * VPL;
                const __half* p1 = h + (size_t)ss1 * DOUT + lane * VPL;
                if (VPL == 4) {
                    uint2 r0 = *reinterpret_cast<const uint2*>(p0);
                    uint2 r1 = *reinterpret_cast<const uint2*>(p1);
                    __half2 a0 = *reinterpret_cast<__half2*>(&r0.x);
                    __half2 b0 = *reinterpret_cast<__half2*>(&r0.y);
                    __half2 a1 = *reinterpret_cast<__half2*>(&r1.x);
                    __half2 b1 = *reinterpret_cast<__half2*>(&r1.y);
                    acc[0] = fmaf(__low2float(a0),  nn0, acc[0]);
                    acc[1] = fmaf(__high2float(a0), nn0, acc[1]);
                    acc[2] = fmaf(__low2float(b0),  nn0, acc[2]);
                    acc[3] = fmaf(__high2float(b0), nn0, acc[3]);
                    acc[0] = fmaf(__low2float(a1),  nn1, acc[0]);
                    acc[1] = fmaf(__high2float(a1), nn1, acc[1]);
                    acc[2] = fmaf(__low2float(b1),  nn1, acc[2]);
                    acc[3] = fmaf(__high2float(b1), nn1, acc[3]);
                } else {
                    unsigned r0 = *reinterpret_cast<const unsigned*>(p0);
                    unsigned r1 = *reinterpret_cast<const unsigned*>(p1);
                    __half2 a0 = *reinterpret_cast<__half2*>(&r0);
                    __half2 a1 = *reinterpret_cast<__half2*>(&r1);
                    acc[0] = fmaf(__low2float(a0),  nn0, acc[0]);
                    acc[1] = fmaf(__high2float(a0), nn0, acc[1]);
                    acc[0] = fmaf(__low2float(a1),  nn1, acc[0]);
                    acc[1] = fmaf(__high2float(a1), nn1, acc[1]);
                }
            }
            if (j < cnt) {
                const int ss   = __shfl_sync(0xffffffffu, s,  j);
                const float nn = __shfl_sync(0xffffffffu, nm, j);
                const __half* p0 = h + (size_t)ss * DOUT + lane * VPL;
                if (VPL == 4) {
                    uint2 r0 = *reinterpret_cast<const uint2*>(p0);
                    __half2 a0 = *reinterpret_cast<__half2*>(&r0.x);
                    __half2 b0 = *reinterpret_cast<__half2*>(&r0.y);
                    acc[0] = fmaf(__low2float(a0),  nn, acc[0]);
                    acc[1] = fmaf(__high2float(a0), nn, acc[1]);
                    acc[2] = fmaf(__low2float(b0),  nn, acc[2]);
                    acc[3] = fmaf(__high2float(b0), nn, acc[3]);
                } else {
                    unsigned r0 = *reinterpret_cast<const unsigned*>(p0);
                    __half2 a0 = *reinterpret_cast<__half2*>(&r0);
                    acc[0] = fmaf(__low2float(a0),  nn, acc[0]);
                    acc[1] = fmaf(__high2float(a0), nn, acc[1]);
                }
            }
        }

        if (VPL == 4) {
            *reinterpret_cast<float4*>(agg + (size_t)node * DOUT + lane * 4) =
                make_float4(acc[0], acc[1], acc[2], acc[3]);
        } else {
            *reinterpret_cast<float2*>(agg + (size_t)node * DOUT + lane * 2) =
                make_float2(acc[0], acc[1]);
        }
    }
}

// ---------------- heads: actor/critic split by block parity ------------------
// smem layout (floats), sized for the larger (actor) variant
constexpr int S_W1  = 0;               // 64*128
constexpr int S_W2  = S_W1 + 8192;     // 128*64
constexpr int S_W3  = S_W2 + 8192;     // 64*8 (critic uses 64)
constexpr int S_B1  = S_W3 + 512;      // 128
constexpr int S_B2  = S_B1 + 128;      // 64
constexpr int S_B3  = S_B2 + 64;       // 8 (critic 1)
constexpr int S_BIN = S_B3 + 8;        // 64  (GCN b3)
constexpr int S_H   = S_BIN + 64;      // 16*64
constexpr int S_T1  = S_H + 1024;      // 16*128
constexpr int S_T2  = S_T1 + 2048;     // 16*64
constexpr int S_LOG = S_T2 + 1024;     // 16*8
constexpr int S_TOT = S_LOG + 128;     // 21384 floats = 85536 B

__device__ __forceinline__ void coop_copy(float* d, const float* s, int n, int tid, int nt) {
    for (int i = tid; i < n; i += nt) d[i] = s[i];
}

__global__ void __launch_bounds__(256)
k_heads(const float* __restrict__ hagg, const float* __restrict__ b3gcn,
        const float* __restrict__ Wa1, const float* __restrict__ ba1,
        const float* __restrict__ Wa2, const float* __restrict__ ba2,
        const float* __restrict__ Wa3, const float* __restrict__ ba3,
        const float* __restrict__ Wc1, const float* __restrict__ bc1,
        const float* __restrict__ Wc2, const float* __restrict__ bc2,
        const float* __restrict__ Wc3, const float* __restrict__ bc3,
        float* __restrict__ out) {
    extern __shared__ float sm[];
    const int t = threadIdx.x;
    const bool actor = (blockIdx.x & 1) == 0;

    coop_copy(sm + S_W1, actor ? Wa1 : Wc1, 8192, t, 256);
    coop_copy(sm + S_W2, actor ? Wa2 : Wc2, 8192, t, 256);
    coop_copy(sm + S_W3, actor ? Wa3 : Wc3, actor ? 512 : 64, t, 256);
    coop_copy(sm + S_B1, actor ? ba1 : bc1, 128, t, 256);
    coop_copy(sm + S_B2, actor ? ba2 : bc2, 64, t, 256);
    coop_copy(sm + S_B3, actor ? ba3 : bc3, actor ? 8 : 1, t, 256);
    coop_copy(sm + S_BIN, b3gcn, 64, t, 256);
    __syncthreads();

    const int tileStride = (gridDim.x >> 1) * 16;
    for (int tile = (blockIdx.x >> 1) * 16; tile < NN; tile += tileStride) {
        const int rows = min(16, NN - tile);

        for (int i = t; i < rows * 64; i += 256) {
            int r = i >> 6, k = i & 63;
            sm[S_H + i] = hagg[(size_t)(tile + r) * 64 + k] + sm[S_BIN + k];
        }
        __syncthreads();

        // stage 1: 64 -> 128, 2 threads per column (8 rows each)
        {
            const int col = t & 127;
            const int r0 = (t >> 7) * 8;
            const float bias = sm[S_B1 + col];
            const int rEnd = min(r0 + 8, rows);
            for (int r = r0; r < rEnd; r++) {
                float acc = bias;
#pragma unroll 8
                for (int k = 0; k < 64; k++)
                    acc = fmaf(sm[S_H + r * 64 + k], sm[S_W1 + k * 128 + col], acc);
                sm[S_T1 + r * 128 + col] = fmaxf(acc, 0.0f);
            }
        }
        __syncthreads();

        // stage 2: 128 -> 64, 4 threads per column (4 rows each)
        {
            const int col = t & 63;
            const int r0 = (t >> 6) * 4;
            const float bias = sm[S_B2 + col];
            const int rEnd = min(r0 + 4, rows);
            for (int r = r0; r < rEnd; r++) {
                float acc = bias;
#pragma unroll 8
                for (int k = 0; k < 128; k++)
                    acc = fmaf(sm[S_T1 + r * 128 + k], sm[S_W2 + k * 64 + col], acc);
                sm[S_T2 + r * 64 + col] = fmaxf(acc, 0.0f);
            }
        }
        __syncthreads();

        // stage 3
        if (actor) {
            if (t < 128) {
                int r = t >> 3, a = t & 7;
                if (r < rows) {
                    float acc = sm[S_B3 + a];
#pragma unroll 8
                    for (int k = 0; k < 64; k++)
                        acc = fmaf(sm[S_T2 + r * 64 + k], sm[S_W3 + k * 8 + a], acc);
                    sm[S_LOG + r * 8 + a] = acc;
                }
            }
            __syncthreads();
            if (t < rows) {
                float mx = -1e30f;
#pragma unroll
                for (int a = 0; a < 8; a++) mx = fmaxf(mx, sm[S_LOG + t * 8 + a]);
                float e[8], ssum = 0.0f;
#pragma unroll
                for (int a = 0; a < 8; a++) {
                    e[a] = expf(sm[S_LOG + t * 8 + a] - mx);
                    ssum += e[a];
                }
                float inv = 1.0f / ssum;
                size_t o = (size_t)(tile + t) * 9;
#pragma unroll
                for (int a = 0; a < 8; a++) out[o + a] = e[a] * inv;
            }
        } else {
            if (t < 16 && t < rows) {
                float acc = sm[S_B3];
#pragma unroll 8
                for (int k = 0; k < 64; k++)
                    acc = fmaf(sm[S_T2 + t * 64 + k], sm[S_W3 + k], acc);
                out[(size_t)(tile + t) * 9 + 8] = acc;
            }
            __syncthreads();
        }
        __syncthreads();
    }
}

// ---------------- launch -----------------------------------------------------
extern "C" void kernel_launch(void* const* d_in, const int* in_sizes, int n_in,
                              void* d_out, int out_size) {
    const float* x   = (const float*)d_in[0];
    const int*   eiw = (const int*)d_in[1];
    const float* W1 = (const float*)d_in[2];  const float* b1 = (const float*)d_in[3];
    const float* W2 = (const float*)d_in[4];  const float* b2 = (const float*)d_in[5];
    const float* W3 = (const float*)d_in[6];  const float* b3 = (const float*)d_in[7];
    const float* Wa1 = (const float*)d_in[8];  const float* ba1 = (const float*)d_in[9];
    const float* Wa2 = (const float*)d_in[10]; const float* ba2 = (const float*)d_in[11];
    const float* Wa3 = (const float*)d_in[12]; const float* ba3 = (const float*)d_in[13];
    const float* Wc1 = (const float*)d_in[14]; const float* bc1 = (const float*)d_in[15];
    const float* Wc2 = (const float*)d_in[16]; const float* bc2 = (const float*)d_in[17];
    const float* Wc3 = (const float*)d_in[18]; const float* bc3 = (const float*)d_in[19];
    float* out = (float*)d_out;

    void *ph, *pB, *pdinv, *pdinv2, *pcnt, *prow, *pcur, *pep, *pcs, *pco;
    cudaGetSymbolAddress(&ph, g_h);
    cudaGetSymbolAddress(&pB, g_bufB);
    cudaGetSymbolAddress(&pdinv, g_dinv);
    cudaGetSymbolAddress(&pdinv2, g_dinv2);
    cudaGetSymbolAddress(&pcnt, g_cnt);
    cudaGetSymbolAddress(&prow, g_rowPtr);
    cudaGetSymbolAddress(&pcur, g_cur);
    cudaGetSymbolAddress(&pep, g_ePack);
    cudaGetSymbolAddress(&pcs, g_chunkSum);
    cudaGetSymbolAddress(&pco, g_chunkOff);
    __half* H = (__half*)ph;  float* B = (float*)pB;
    float* dinv = (float*)pdinv;  float* dinv2 = (float*)pdinv2;
    int* cnt = (int*)pcnt;  int* rowPtr = (int*)prow;  int* cur = (int*)pcur;
    int2* ePack = (int2*)pep;
    int* chunkSum = (int*)pcs;  int* chunkOff = (int*)pco;

    const int SM_G1 = (128 * 128 + 16 * 128 + 128) * 4;  // 74240
    const int SM_G2 = (128 * 64 + 16 * 128 + 128) * 4;   // 41472
    const int SM_H  = S_TOT * 4;                         // 85536

    cudaFuncSetAttribute(k_gemm<128, 128, false>,
                         cudaFuncAttributeMaxDynamicSharedMemorySize, SM_G1);
    cudaFuncSetAttribute(k_gemm<128, 128, true>,
                         cudaFuncAttributeMaxDynamicSharedMemorySize, SM_G1);
    cudaFuncSetAttribute(k_gemm<128, 64, true>,
                         cudaFuncAttributeMaxDynamicSharedMemorySize, SM_G2);
    cudaFuncSetAttribute(k_heads,
                         cudaFuncAttributeMaxDynamicSharedMemorySize, SM_H);

    // ---- CSR build (once) ----
    k_detect<<<1, 32>>>(eiw);
    k_zero_cnt<<<(NN + 255) / 256, 256>>>(cnt);
    k_count<<<2048, 256>>>(eiw, cnt);
    k_chunk_sum<<<NCHUNK, 1024>>>(cnt, chunkSum);
    k_scan_part<<<1, 128>>>(chunkSum, chunkOff);
    k_scan_final<<<NCHUNK, 1024>>>(cnt, chunkOff, rowPtr, cur, dinv, dinv2);
    k_fill<<<2048, 256>>>(eiw, dinv, cur, ePack);

    // ---- layer 1: h = x @ W1 -> H (fp16); agg -> B ----
    k_gemm<128, 128, false><<<456, 128, SM_G1>>>(x, W1, b1, H);
    k_gather<128><<<1568, 256>>>(rowPtr, ePack, H, dinv2, B);

    // ---- layer 2: h = relu(B + b1) @ W2 -> H; agg -> B ----
    k_gemm<128, 128, true><<<456, 128, SM_G1>>>(B, W2, b1, H);
    k_gather<128><<<1568, 256>>>(rowPtr, ePack, H, dinv2, B);

    // ---- layer 3: h = relu(B + b2) @ W3 -> H (64-dim); agg -> B ----
    k_gemm<128, 64, true><<<456, 128, SM_G2>>>(B, W3, b2, H);
    k_gather<64><<<1568, 256>>>(rowPtr, ePack, H, dinv2, B);

    // ---- heads (actor: even blocks, critic: odd blocks) ----
    k_heads<<<304, 256, SM_H>>>(B, b3,
                                Wa1, ba1, Wa2, ba2, Wa3, ba3,
                                Wc1, bc1, Wc2, bc2, Wc3, bc3, out);
}

// round 7
// speedup vs baseline: 2.9859x; 1.0415x over previous
#include <cuda_runtime.h>
#include <cuda_fp16.h>
#include <mma.h>
#include <cstddef>
#include <cstdint>

using namespace nvcuda;

#define NN 100000
#define NE 3200000
#define NCHUNK ((NN + 1023) / 1024)   // 98

// ---------------- scratch (module-load allocated, no runtime alloc) ----------
__device__ __align__(16) __half g_h[(size_t)NN * 128];    // GEMM output (fp16)
__device__ __align__(16) __half g_act[(size_t)NN * 128];  // GEMM input (fp16)
__device__ __align__(16) float g_bufB[(size_t)NN * 64];   // final agg (fp32)
__device__ float g_dinv[NN];
__device__ float g_dinv2[NN];
__device__ int g_cnt[NN];
__device__ int g_rowPtr[NN + 1];
__device__ int g_cur[NN];
__device__ __align__(16) int2 g_ePack[NE];   // {src, norm-as-int} per CSR slot
__device__ int g_chunkSum[NCHUNK];
__device__ int g_chunkOff[NCHUNK + 1];
__device__ int g_is64;

// ---------------- edge-index dtype probe ------------------------------------
__global__ void k_detect(const int* __restrict__ w) {
    if (blockIdx.x == 0 && threadIdx.x == 0) {
        int is64 = 1;
        for (int i = 0; i < 2048; i += 2) {
            if (w[i + 1] != 0) { is64 = 0; break; }
        }
        g_is64 = is64;
    }
}

__global__ void k_zero_cnt(int* __restrict__ cnt) {
    int i = blockIdx.x * blockDim.x + threadIdx.x;
    if (i < NN) cnt[i] = 0;
}

__global__ void k_count(const int* __restrict__ w, int* __restrict__ cnt) {
    const int is64 = g_is64;
    long long i = (long long)blockIdx.x * blockDim.x + threadIdx.x;
    long long stride = (long long)gridDim.x * blockDim.x;
    if (is64) {
        for (; i < NE; i += stride)
            atomicAdd(&cnt[w[2 * (long long)NE + 2 * i]], 1);
    } else {
        for (; i < NE; i += stride)
            atomicAdd(&cnt[w[NE + i]], 1);
    }
}

// ---------------- parallel 3-phase prefix scan -------------------------------
__global__ void __launch_bounds__(1024)
k_chunk_sum(const int* __restrict__ cnt, int* __restrict__ chunkSum) {
    __shared__ int sred[32];
    const int tid = threadIdx.x;
    const int idx = blockIdx.x * 1024 + tid;
    int v = (idx < NN) ? cnt[idx] : 0;
    for (int o = 16; o > 0; o >>= 1) v += __shfl_down_sync(0xffffffffu, v, o);
    if ((tid & 31) == 0) sred[tid >> 5] = v;
    __syncthreads();
    if (tid < 32) {
        int x = sred[tid];
        for (int o = 16; o > 0; o >>= 1) x += __shfl_down_sync(0xffffffffu, x, o);
        if (tid == 0) chunkSum[blockIdx.x] = x;
    }
}

__global__ void __launch_bounds__(128)
k_scan_part(const int* __restrict__ chunkSum, int* __restrict__ chunkOff) {
    __shared__ int s[NCHUNK];
    const int tid = threadIdx.x;
    for (int i = tid; i < NCHUNK; i += 128) s[i] = chunkSum[i];
    __syncthreads();
    if (tid == 0) {
        int acc = 0;
        for (int i = 0; i < NCHUNK; i++) { int v = s[i]; s[i] = acc; acc += v; }
        chunkOff[NCHUNK] = acc;
    }
    __syncthreads();
    for (int i = tid; i < NCHUNK; i += 128) chunkOff[i] = s[i];
}

__global__ void __launch_bounds__(1024)
k_scan_final(const int* __restrict__ cnt, const int* __restrict__ chunkOff,
             int* __restrict__ rowPtr, int* __restrict__ cur,
             float* __restrict__ dinv, float* __restrict__ dinv2) {
    __shared__ int swarp[32];
    const int tid = threadIdx.x;
    const int idx = blockIdx.x * 1024 + tid;
    int v = (idx < NN) ? cnt[idx] : 0;

    int incl = v;
    for (int o = 1; o < 32; o <<= 1) {
        int t = __shfl_up_sync(0xffffffffu, incl, o);
        if ((tid & 31) >= o) incl += t;
    }
    if ((tid & 31) == 31) swarp[tid >> 5] = incl;
    __syncthreads();
    if (tid < 32) {
        int x = swarp[tid];
        for (int o = 1; o < 32; o <<= 1) {
            int t = __shfl_up_sync(0xffffffffu, x, o);
            if (tid >= o) x += t;
        }
        swarp[tid] = x;
    }
    __syncthreads();
    int warpBase = (tid >= 32) ? swarp[(tid >> 5) - 1] : 0;
    int inclTotal = incl + warpBase;

    if (idx < NN) {
        int start = chunkOff[blockIdx.x] + inclTotal - v;
        rowPtr[idx] = start;
        cur[idx] = start;
        float dv = rsqrtf((float)(v + 1));
        dinv[idx] = dv;
        dinv2[idx] = dv * dv;
    }
    if (blockIdx.x == gridDim.x - 1 && tid == 0)
        rowPtr[NN] = chunkOff[NCHUNK];
}

__global__ void k_fill(const int* __restrict__ w, const float* __restrict__ dinv,
                       int* __restrict__ cur, int2* __restrict__ ePack) {
    const int is64 = g_is64;
    long long i = (long long)blockIdx.x * blockDim.x + threadIdx.x;
    long long stride = (long long)gridDim.x * blockDim.x;
    for (; i < NE; i += stride) {
        int s, d;
        if (is64) { s = w[2 * i]; d = w[2 * (long long)NE + 2 * i]; }
        else      { s = w[i];     d = w[NE + i]; }
        int pos = atomicAdd(&cur[d], 1);
        ePack[pos] = make_int2(s, __float_as_int(dinv[s] * dinv[d]));
    }
}

// ---------------- x -> fp16 convert ------------------------------------------
__global__ void k_cvt(const float* __restrict__ x, __half* __restrict__ o) {
    long long i = (long long)blockIdx.x * blockDim.x + threadIdx.x;
    long long stride = (long long)gridDim.x * blockDim.x;
    const long long n4 = (long long)NN * 128 / 4;
    const float4* x4 = reinterpret_cast<const float4*>(x);
    for (; i < n4; i += stride) {
        float4 v = x4[i];
        __half2 p0 = __floats2half2_rn(v.x, v.y);
        __half2 p1 = __floats2half2_rn(v.z, v.w);
        uint2 raw;
        raw.x = *reinterpret_cast<unsigned*>(&p0);
        raw.y = *reinterpret_cast<unsigned*>(&p1);
        *reinterpret_cast<uint2*>(o + 4 * i) = raw;
    }
}

// ---------------- WMMA GEMM: out = in @ W  (fp16 in/out, fp16 accum) ---------
template <int DIN, int DOUT>
__global__ void __launch_bounds__(256)
k_gemm_wmma(const __half* __restrict__ in, const float* __restrict__ W,
            __half* __restrict__ out) {
    extern __shared__ __half sW[];     // DIN*DOUT halves
    const int tid = threadIdx.x;
    for (int i = tid; i < DIN * DOUT; i += 256) sW[i] = __float2half(W[i]);
    __syncthreads();

    constexpr int TILES = NN / 16;     // 6250, exact
    const int warpId = tid >> 5;
    const int warpsTotal = (gridDim.x * 256) >> 5;

    for (int tile = blockIdx.x * 8 + warpId; tile < TILES; tile += warpsTotal) {
        const int row0 = tile * 16;
        wmma::fragment<wmma::accumulator, 16, 16, 16, __half> acc[DOUT / 16];
#pragma unroll
        for (int c = 0; c < DOUT / 16; c++)
            wmma::fill_fragment(acc[c], __float2half(0.0f));

#pragma unroll
        for (int k = 0; k < DIN / 16; k++) {
            wmma::fragment<wmma::matrix_a, 16, 16, 16, __half, wmma::row_major> a;
            wmma::load_matrix_sync(a, in + (size_t)row0 * DIN + k * 16, DIN);
#pragma unroll
            for (int c = 0; c < DOUT / 16; c++) {
                wmma::fragment<wmma::matrix_b, 16, 16, 16, __half, wmma::row_major> b;
                wmma::load_matrix_sync(b, sW + k * 16 * DOUT + c * 16, DOUT);
                wmma::mma_sync(acc[c], a, b, acc[c]);
            }
        }
#pragma unroll
        for (int c = 0; c < DOUT / 16; c++)
            wmma::store_matrix_sync(out + (size_t)row0 * DOUT + c * 16, acc[c],
                                    DOUT, wmma::mem_row_major);
    }
}

// ---------------- CSR gather (fp16 in; epilogue bias+relu fp16 OR raw fp32) --
template <int DOUT, bool F16OUT>
__global__ void __launch_bounds__(256)
k_gather(const int* __restrict__ rowPtr, const int2* __restrict__ ePack,
         const __half* __restrict__ h, const float* __restrict__ dinv2,
         const float* __restrict__ bias,
         __half* __restrict__ outH, float* __restrict__ outF) {
    constexpr int VPL = DOUT / 32;
    const int lane = threadIdx.x & 31;
    const int warpId = (blockIdx.x * blockDim.x + threadIdx.x) >> 5;
    const int nWarps = (gridDim.x * blockDim.x) >> 5;

    float bl[VPL];
    if (F16OUT) {
#pragma unroll
        for (int i = 0; i < VPL; i++) bl[i] = bias[lane * VPL + i];
    }

    for (int node = warpId; node < NN; node += nWarps) {
        const int beg = rowPtr[node];
        const int end = rowPtr[node + 1];

        float acc[VPL];
        {
            const float d2 = dinv2[node];
            const __half* hp = h + (size_t)node * DOUT + lane * VPL;
            if (VPL == 4) {
                uint2 raw = *reinterpret_cast<const uint2*>(hp);
                __half2 a = *reinterpret_cast<__half2*>(&raw.x);
                __half2 b = *reinterpret_cast<__half2*>(&raw.y);
                acc[0] = __low2float(a) * d2;  acc[1] = __high2float(a) * d2;
                acc[2] = __low2float(b) * d2;  acc[3] = __high2float(b) * d2;
            } else {
                unsigned raw = *reinterpret_cast<const unsigned*>(hp);
                __half2 a = *reinterpret_cast<__half2*>(&raw);
                acc[0] = __low2float(a) * d2;  acc[1] = __high2float(a) * d2;
            }
        }

        for (int base = beg; base < end; base += 32) {
            const int cnt = min(32, end - base);
            int s = 0; float nm = 0.0f;
            if (lane < cnt) {
                int2 e = ePack[base + lane];
                s = e.x; nm = __int_as_float(e.y);
            }
            int j = 0;
            for (; j + 1 < cnt; j += 2) {
                const int ss0   = __shfl_sync(0xffffffffu, s,  j);
                const float nn0 = __shfl_sync(0xffffffffu, nm, j);
                const int ss1   = __shfl_sync(0xffffffffu, s,  j + 1);
                const float nn1 = __shfl_sync(0xffffffffu, nm, j + 1);
                const __half* p0 = h + (size_t)ss0 * DOUT + lane * VPL;
                const __half* p1 = h + (size_t)ss1 * DOUT + lane * VPL;
                if (VPL == 4) {
                    uint2 r0 = *reinterpret_cast<const uint2*>(p0);
                    uint2 r1 = *reinterpret_cast<const uint2*>(p1);
                    __half2 a0 = *reinterpret_cast<__half2*>(&r0.x);
                    __half2 b0 = *reinterpret_cast<__half2*>(&r0.y);
                    __half2 a1 = *reinterpret_cast<__half2*>(&r1.x);
                    __half2 b1 = *reinterpret_cast<__half2*>(&r1.y);
                    acc[0] = fmaf(__low2float(a0),  nn0, acc[0]);
                    acc[1] = fmaf(__high2float(a0), nn0, acc[1]);
                    acc[2] = fmaf(__low2float(b0),  nn0, acc[2]);
                    acc[3] = fmaf(__high2float(b0), nn0, acc[3]);
                    acc[0] = fmaf(__low2float(a1),  nn1, acc[0]);
                    acc[1] = fmaf(__high2float(a1), nn1, acc[1]);
                    acc[2] = fmaf(__low2float(b1),  nn1, acc[2]);
                    acc[3] = fmaf(__high2float(b1), nn1, acc[3]);
                } else {
                    unsigned r0 = *reinterpret_cast<const unsigned*>(p0);
                    unsigned r1 = *reinterpret_cast<const unsigned*>(p1);
                    __half2 a0 = *reinterpret_cast<__half2*>(&r0);
                    __half2 a1 = *reinterpret_cast<__half2*>(&r1);
                    acc[0] = fmaf(__low2float(a0),  nn0, acc[0]);
                    acc[1] = fmaf(__high2float(a0), nn0, acc[1]);
                    acc[0] = fmaf(__low2float(a1),  nn1, acc[0]);
                    acc[1] = fmaf(__high2float(a1), nn1, acc[1]);
                }
            }
            if (j < cnt) {
                const int ss   = __shfl_sync(0xffffffffu, s,  j);
                const float nn = __shfl_sync(0xffffffffu, nm, j);
                const __half* p0 = h + (size_t)ss * DOUT + lane * VPL;
                if (VPL == 4) {
                    uint2 r0 = *reinterpret_cast<const uint2*>(p0);
                    __half2 a0 = *reinterpret_cast<__half2*>(&r0.x);
                    __half2 b0 = *reinterpret_cast<__half2*>(&r0.y);
                    acc[0] = fmaf(__low2float(a0),  nn, acc[0]);
                    acc[1] = fmaf(__high2float(a0), nn, acc[1]);
                    acc[2] = fmaf(__low2float(b0),  nn, acc[2]);
                    acc[3] = fmaf(__high2float(b0), nn, acc[3]);
                } else {
                    unsigned r0 = *reinterpret_cast<const unsigned*>(p0);
                    __half2 a0 = *reinterpret_cast<__half2*>(&r0);
                    acc[0] = fmaf(__low2float(a0),  nn, acc[0]);
                    acc[1] = fmaf(__high2float(a0), nn, acc[1]);
                }
            }
        }

        if (F16OUT) {
            // next-layer input: relu(agg + bias), fp16
#pragma unroll
            for (int i = 0; i < VPL; i++) acc[i] = fmaxf(acc[i] + bl[i], 0.0f);
            if (VPL == 4) {
                __half2 p0 = __floats2half2_rn(acc[0], acc[1]);
                __half2 p1 = __floats2half2_rn(acc[2], acc[3]);
                uint2 raw;
                raw.x = *reinterpret_cast<unsigned*>(&p0);
                raw.y = *reinterpret_cast<unsigned*>(&p1);
                *reinterpret_cast<uint2*>(outH + (size_t)node * DOUT + lane * 4) = raw;
            } else {
                __half2 p0 = __floats2half2_rn(acc[0], acc[1]);
                *reinterpret_cast<unsigned*>(outH + (size_t)node * DOUT + lane * 2) =
                    *reinterpret_cast<unsigned*>(&p0);
            }
        } else {
            if (VPL == 4) {
                *reinterpret_cast<float4*>(outF + (size_t)node * DOUT + lane * 4) =
                    make_float4(acc[0], acc[1], acc[2], acc[3]);
            } else {
                *reinterpret_cast<float2*>(outF + (size_t)node * DOUT + lane * 2) =
                    make_float2(acc[0], acc[1]);
            }
        }
    }
}

// ---------------- heads: actor/critic split by block parity ------------------
constexpr int S_W1  = 0;               // 64*128
constexpr int S_W2  = S_W1 + 8192;     // 128*64
constexpr int S_W3  = S_W2 + 8192;     // 64*8
constexpr int S_B1  = S_W3 + 512;
constexpr int S_B2  = S_B1 + 128;
constexpr int S_B3  = S_B2 + 64;
constexpr int S_BIN = S_B3 + 8;
constexpr int S_H   = S_BIN + 64;      // 16*64
constexpr int S_T1  = S_H + 1024;      // 16*128
constexpr int S_T2  = S_T1 + 2048;     // 16*64
constexpr int S_LOG = S_T2 + 1024;     // 16*8
constexpr int S_TOT = S_LOG + 128;

__device__ __forceinline__ void coop_copy(float* d, const float* s, int n, int tid, int nt) {
    for (int i = tid; i < n; i += nt) d[i] = s[i];
}

__global__ void __launch_bounds__(256)
k_heads(const float* __restrict__ hagg, const float* __restrict__ b3gcn,
        const float* __restrict__ Wa1, const float* __restrict__ ba1,
        const float* __restrict__ Wa2, const float* __restrict__ ba2,
        const float* __restrict__ Wa3, const float* __restrict__ ba3,
        const float* __restrict__ Wc1, const float* __restrict__ bc1,
        const float* __restrict__ Wc2, const float* __restrict__ bc2,
        const float* __restrict__ Wc3, const float* __restrict__ bc3,
        float* __restrict__ out) {
    extern __shared__ float sm[];
    const int t = threadIdx.x;
    const bool actor = (blockIdx.x & 1) == 0;

    coop_copy(sm + S_W1, actor ? Wa1 : Wc1, 8192, t, 256);
    coop_copy(sm + S_W2, actor ? Wa2 : Wc2, 8192, t, 256);
    coop_copy(sm + S_W3, actor ? Wa3 : Wc3, actor ? 512 : 64, t, 256);
    coop_copy(sm + S_B1, actor ? ba1 : bc1, 128, t, 256);
    coop_copy(sm + S_B2, actor ? ba2 : bc2, 64, t, 256);
    coop_copy(sm + S_B3, actor ? ba3 : bc3, actor ? 8 : 1, t, 256);
    coop_copy(sm + S_BIN, b3gcn, 64, t, 256);
    __syncthreads();

    const int tileStride = (gridDim.x >> 1) * 16;
    for (int tile = (blockIdx.x >> 1) * 16; tile < NN; tile += tileStride) {
        const int rows = min(16, NN - tile);

        for (int i = t; i < rows * 64; i += 256) {
            int r = i >> 6, k = i & 63;
            sm[S_H + i] = hagg[(size_t)(tile + r) * 64 + k] + sm[S_BIN + k];
        }
        __syncthreads();

        {
            const int col = t & 127;
            const int r0 = (t >> 7) * 8;
            const float bias = sm[S_B1 + col];
            const int rEnd = min(r0 + 8, rows);
            for (int r = r0; r < rEnd; r++) {
                float acc = bias;
#pragma unroll 8
                for (int k = 0; k < 64; k++)
                    acc = fmaf(sm[S_H + r * 64 + k], sm[S_W1 + k * 128 + col], acc);
                sm[S_T1 + r * 128 + col] = fmaxf(acc, 0.0f);
            }
        }
        __syncthreads();

        {
            const int col = t & 63;
            const int r0 = (t >> 6) * 4;
            const float bias = sm[S_B2 + col];
            const int rEnd = min(r0 + 4, rows);
            for (int r = r0; r < rEnd; r++) {
                float acc = bias;
#pragma unroll 8
                for (int k = 0; k < 128; k++)
                    acc = fmaf(sm[S_T1 + r * 128 + k], sm[S_W2 + k * 64 + col], acc);
                sm[S_T2 + r * 64 + col] = fmaxf(acc, 0.0f);
            }
        }
        __syncthreads();

        if (actor) {
            if (t < 128) {
                int r = t >> 3, a = t & 7;
                if (r < rows) {
                    float acc = sm[S_B3 + a];
#pragma unroll 8
                    for (int k = 0; k < 64; k++)
                        acc = fmaf(sm[S_T2 + r * 64 + k], sm[S_W3 + k * 8 + a], acc);
                    sm[S_LOG + r * 8 + a] = acc;
                }
            }
            __syncthreads();
            if (t < rows) {
                float mx = -1e30f;
#pragma unroll
                for (int a = 0; a < 8; a++) mx = fmaxf(mx, sm[S_LOG + t * 8 + a]);
                float e[8], ssum = 0.0f;
#pragma unroll
                for (int a = 0; a < 8; a++) {
                    e[a] = expf(sm[S_LOG + t * 8 + a] - mx);
                    ssum += e[a];
                }
                float inv = 1.0f / ssum;
                size_t o = (size_t)(tile + t) * 9;
#pragma unroll
                for (int a = 0; a < 8; a++) out[o + a] = e[a] * inv;
            }
        } else {
            if (t < 16 && t < rows) {
                float acc = sm[S_B3];
#pragma unroll 8
                for (int k = 0; k < 64; k++)
                    acc = fmaf(sm[S_T2 + t * 64 + k], sm[S_W3 + k], acc);
                out[(size_t)(tile + t) * 9 + 8] = acc;
            }
            __syncthreads();
        }
        __syncthreads();
    }
}

// ---------------- launch -----------------------------------------------------
extern "C" void kernel_launch(void* const* d_in, const int* in_sizes, int n_in,
                              void* d_out, int out_size) {
    const float* x   = (const float*)d_in[0];
    const int*   eiw = (const int*)d_in[1];
    const float* W1 = (const float*)d_in[2];  const float* b1 = (const float*)d_in[3];
    const float* W2 = (const float*)d_in[4];  const float* b2 = (const float*)d_in[5];
    const float* W3 = (const float*)d_in[6];  const float* b3 = (const float*)d_in[7];
    const float* Wa1 = (const float*)d_in[8];  const float* ba1 = (const float*)d_in[9];
    const float* Wa2 = (const float*)d_in[10]; const float* ba2 = (const float*)d_in[11];
    const float* Wa3 = (const float*)d_in[12]; const float* ba3 = (const float*)d_in[13];
    const float* Wc1 = (const float*)d_in[14]; const float* bc1 = (const float*)d_in[15];
    const float* Wc2 = (const float*)d_in[16]; const float* bc2 = (const float*)d_in[17];
    const float* Wc3 = (const float*)d_in[18]; const float* bc3 = (const float*)d_in[19];
    float* out = (float*)d_out;

    void *ph, *pact, *pB, *pdinv, *pdinv2, *pcnt, *prow, *pcur, *pep, *pcs, *pco;
    cudaGetSymbolAddress(&ph, g_h);
    cudaGetSymbolAddress(&pact, g_act);
    cudaGetSymbolAddress(&pB, g_bufB);
    cudaGetSymbolAddress(&pdinv, g_dinv);
    cudaGetSymbolAddress(&pdinv2, g_dinv2);
    cudaGetSymbolAddress(&pcnt, g_cnt);
    cudaGetSymbolAddress(&prow, g_rowPtr);
    cudaGetSymbolAddress(&pcur, g_cur);
    cudaGetSymbolAddress(&pep, g_ePack);
    cudaGetSymbolAddress(&pcs, g_chunkSum);
    cudaGetSymbolAddress(&pco, g_chunkOff);
    __half* H = (__half*)ph;  __half* ACT = (__half*)pact;  float* B = (float*)pB;
    float* dinv = (float*)pdinv;  float* dinv2 = (float*)pdinv2;
    int* cnt = (int*)pcnt;  int* rowPtr = (int*)prow;  int* cur = (int*)pcur;
    int2* ePack = (int2*)pep;
    int* chunkSum = (int*)pcs;  int* chunkOff = (int*)pco;

    const int SM_W1 = 128 * 128 * 2;   // 32768
    const int SM_W2 = 128 * 64 * 2;    // 16384
    const int SM_H  = S_TOT * 4;       // 85536

    cudaFuncSetAttribute(k_gemm_wmma<128, 128>,
                         cudaFuncAttributeMaxDynamicSharedMemorySize, SM_W1);
    cudaFuncSetAttribute(k_gemm_wmma<128, 64>,
                         cudaFuncAttributeMaxDynamicSharedMemorySize, SM_W2);
    cudaFuncSetAttribute(k_heads,
                         cudaFuncAttributeMaxDynamicSharedMemorySize, SM_H);

    // ---- CSR build (once) ----
    k_detect<<<1, 32>>>(eiw);
    k_zero_cnt<<<(NN + 255) / 256, 256>>>(cnt);
    k_count<<<2048, 256>>>(eiw, cnt);
    k_chunk_sum<<<NCHUNK, 1024>>>(cnt, chunkSum);
    k_scan_part<<<1, 128>>>(chunkSum, chunkOff);
    k_scan_final<<<NCHUNK, 1024>>>(cnt, chunkOff, rowPtr, cur, dinv, dinv2);
    k_fill<<<2048, 256>>>(eiw, dinv, cur, ePack);

    // ---- x -> fp16 ----
    k_cvt<<<1184, 256>>>(x, ACT);

    // ---- layer 1: H = ACT @ W1; gather -> ACT (relu(+b1), fp16) ----
    k_gemm_wmma<128, 128><<<391, 256, SM_W1>>>(ACT, W1, H);
    k_gather<128, true><<<1568, 256>>>(rowPtr, ePack, H, dinv2, b1, ACT, nullptr);

    // ---- layer 2: H = ACT @ W2; gather -> ACT (relu(+b2), fp16) ----
    k_gemm_wmma<128, 128><<<391, 256, SM_W1>>>(ACT, W2, H);
    k_gather<128, true><<<1568, 256>>>(rowPtr, ePack, H, dinv2, b2, ACT, nullptr);

    // ---- layer 3: H = ACT @ W3 (64-dim); gather -> B (raw fp32) ----
    k_gemm_wmma<128, 64><<<391, 256, SM_W2>>>(ACT, W3, H);
    k_gather<64, false><<<1568, 256>>>(rowPtr, ePack, H, dinv2, nullptr, nullptr, B);

    // ---- heads (actor: even blocks, critic: odd blocks) ----
    k_heads<<<304, 256, SM_H>>>(B, b3,
                                Wa1, ba1, Wa2, ba2, Wa3, ba3,
                                Wc1, bc1, Wc2, bc2, Wc3, bc3, out);
}

// round 8
// speedup vs baseline: 3.1592x; 1.0580x over previous
#include <cuda_runtime.h>
#include <cuda_fp16.h>
#include <cuda_fp8.h>
#include <mma.h>
#include <cstddef>
#include <cstdint>

using namespace nvcuda;

#define NN 100000
#define NE 3200000
#define NCHUNK ((NN + 1023) / 1024)   // 98

// ---------------- scratch (module-load allocated, no runtime alloc) ----------
__device__ __align__(16) __half g_h[(size_t)NN * 128];    // GEMM output (fp16)
__device__ __align__(16) uint8_t g_h8[(size_t)NN * 128];  // fp8 copy for gather
__device__ __align__(16) __half g_act[(size_t)NN * 128];  // GEMM input (fp16)
__device__ __align__(16) float g_bufB[(size_t)NN * 64];   // final agg (fp32)
__device__ float g_dinv[NN];
__device__ float g_dinv2[NN];
__device__ int g_cnt[NN];
__device__ int g_rowPtr[NN + 1];
__device__ int g_cur[NN];
__device__ __align__(16) int2 g_ePack[NE];   // {src, norm-as-int} per CSR slot
__device__ int g_chunkSum[NCHUNK];
__device__ int g_chunkOff[NCHUNK + 1];
__device__ int g_is64;

// ---------------- edge-index dtype probe ------------------------------------
__global__ void k_detect(const int* __restrict__ w) {
    if (blockIdx.x == 0 && threadIdx.x == 0) {
        int is64 = 1;
        for (int i = 0; i < 2048; i += 2) {
            if (w[i + 1] != 0) { is64 = 0; break; }
        }
        g_is64 = is64;
    }
}

__global__ void k_zero_cnt(int* __restrict__ cnt) {
    int i = blockIdx.x * blockDim.x + threadIdx.x;
    if (i < NN) cnt[i] = 0;
}

__global__ void k_count(const int* __restrict__ w, int* __restrict__ cnt) {
    const int is64 = g_is64;
    long long i = (long long)blockIdx.x * blockDim.x + threadIdx.x;
    long long stride = (long long)gridDim.x * blockDim.x;
    if (is64) {
        for (; i < NE; i += stride)
            atomicAdd(&cnt[w[2 * (long long)NE + 2 * i]], 1);
    } else {
        for (; i < NE; i += stride)
            atomicAdd(&cnt[w[NE + i]], 1);
    }
}

// ---------------- parallel 3-phase prefix scan -------------------------------
__global__ void __launch_bounds__(1024)
k_chunk_sum(const int* __restrict__ cnt, int* __restrict__ chunkSum) {
    __shared__ int sred[32];
    const int tid = threadIdx.x;
    const int idx = blockIdx.x * 1024 + tid;
    int v = (idx < NN) ? cnt[idx] : 0;
    for (int o = 16; o > 0; o >>= 1) v += __shfl_down_sync(0xffffffffu, v, o);
    if ((tid & 31) == 0) sred[tid >> 5] = v;
    __syncthreads();
    if (tid < 32) {
        int x = sred[tid];
        for (int o = 16; o > 0; o >>= 1) x += __shfl_down_sync(0xffffffffu, x, o);
        if (tid == 0) chunkSum[blockIdx.x] = x;
    }
}

__global__ void __launch_bounds__(128)
k_scan_part(const int* __restrict__ chunkSum, int* __restrict__ chunkOff) {
    __shared__ int s[NCHUNK];
    const int tid = threadIdx.x;
    for (int i = tid; i < NCHUNK; i += 128) s[i] = chunkSum[i];
    __syncthreads();
    if (tid == 0) {
        int acc = 0;
        for (int i = 0; i < NCHUNK; i++) { int v = s[i]; s[i] = acc; acc += v; }
        chunkOff[NCHUNK] = acc;
    }
    __syncthreads();
    for (int i = tid; i < NCHUNK; i += 128) chunkOff[i] = s[i];
}

__global__ void __launch_bounds__(1024)
k_scan_final(const int* __restrict__ cnt, const int* __restrict__ chunkOff,
             int* __restrict__ rowPtr, int* __restrict__ cur,
             float* __restrict__ dinv, float* __restrict__ dinv2) {
    __shared__ int swarp[32];
    const int tid = threadIdx.x;
    const int idx = blockIdx.x * 1024 + tid;
    int v = (idx < NN) ? cnt[idx] : 0;

    int incl = v;
    for (int o = 1; o < 32; o <<= 1) {
        int t = __shfl_up_sync(0xffffffffu, incl, o);
        if ((tid & 31) >= o) incl += t;
    }
    if ((tid & 31) == 31) swarp[tid >> 5] = incl;
    __syncthreads();
    if (tid < 32) {
        int x = swarp[tid];
        for (int o = 1; o < 32; o <<= 1) {
            int t = __shfl_up_sync(0xffffffffu, x, o);
            if (tid >= o) x += t;
        }
        swarp[tid] = x;
    }
    __syncthreads();
    int warpBase = (tid >= 32) ? swarp[(tid >> 5) - 1] : 0;
    int inclTotal = incl + warpBase;

    if (idx < NN) {
        int start = chunkOff[blockIdx.x] + inclTotal - v;
        rowPtr[idx] = start;
        cur[idx] = start;
        float dv = rsqrtf((float)(v + 1));
        dinv[idx] = dv;
        dinv2[idx] = dv * dv;
    }
    if (blockIdx.x == gridDim.x - 1 && tid == 0)
        rowPtr[NN] = chunkOff[NCHUNK];
}

__global__ void k_fill(const int* __restrict__ w, const float* __restrict__ dinv,
                       int* __restrict__ cur, int2* __restrict__ ePack) {
    const int is64 = g_is64;
    long long i = (long long)blockIdx.x * blockDim.x + threadIdx.x;
    long long stride = (long long)gridDim.x * blockDim.x;
    for (; i < NE; i += stride) {
        int s, d;
        if (is64) { s = w[2 * i]; d = w[2 * (long long)NE + 2 * i]; }
        else      { s = w[i];     d = w[NE + i]; }
        int pos = atomicAdd(&cur[d], 1);
        ePack[pos] = make_int2(s, __float_as_int(dinv[s] * dinv[d]));
    }
}

// ---------------- x -> fp16 convert ------------------------------------------
__global__ void k_cvt(const float* __restrict__ x, __half* __restrict__ o) {
    long long i = (long long)blockIdx.x * blockDim.x + threadIdx.x;
    long long stride = (long long)gridDim.x * blockDim.x;
    const long long n4 = (long long)NN * 128 / 4;
    const float4* x4 = reinterpret_cast<const float4*>(x);
    for (; i < n4; i += stride) {
        float4 v = x4[i];
        __half2 p0 = __floats2half2_rn(v.x, v.y);
        __half2 p1 = __floats2half2_rn(v.z, v.w);
        uint2 raw;
        raw.x = *reinterpret_cast<unsigned*>(&p0);
        raw.y = *reinterpret_cast<unsigned*>(&p1);
        *reinterpret_cast<uint2*>(o + 4 * i) = raw;
    }
}

// ---------------- fp16 -> fp8(e4m3) convert ----------------------------------
__global__ void k_cvt8(const __half* __restrict__ h, uint8_t* __restrict__ o) {
    long long i = (long long)blockIdx.x * blockDim.x + threadIdx.x;
    long long stride = (long long)gridDim.x * blockDim.x;
    const long long n8 = (long long)NN * 128 / 8;
    const uint4* h8 = reinterpret_cast<const uint4*>(h);   // 8 halves
    for (; i < n8; i += stride) {
        uint4 v = h8[i];
        __half2_raw a0 = *reinterpret_cast<__half2_raw*>(&v.x);
        __half2_raw a1 = *reinterpret_cast<__half2_raw*>(&v.y);
        __half2_raw a2 = *reinterpret_cast<__half2_raw*>(&v.z);
        __half2_raw a3 = *reinterpret_cast<__half2_raw*>(&v.w);
        unsigned short f0 = __nv_cvt_halfraw2_to_fp8x2(a0, __NV_SATFINITE, __NV_E4M3);
        unsigned short f1 = __nv_cvt_halfraw2_to_fp8x2(a1, __NV_SATFINITE, __NV_E4M3);
        unsigned short f2 = __nv_cvt_halfraw2_to_fp8x2(a2, __NV_SATFINITE, __NV_E4M3);
        unsigned short f3 = __nv_cvt_halfraw2_to_fp8x2(a3, __NV_SATFINITE, __NV_E4M3);
        uint2 out;
        out.x = (unsigned)f0 | ((unsigned)f1 << 16);
        out.y = (unsigned)f2 | ((unsigned)f3 << 16);
        *reinterpret_cast<uint2*>(o + 8 * i) = out;
    }
}

// ---------------- WMMA GEMM: out = in @ W  (fp16 in/out, fp16 accum) ---------
template <int DIN, int DOUT>
__global__ void __launch_bounds__(256)
k_gemm_wmma(const __half* __restrict__ in, const float* __restrict__ W,
            __half* __restrict__ out) {
    extern __shared__ __half sW[];     // DIN*DOUT halves
    const int tid = threadIdx.x;
    for (int i = tid; i < DIN * DOUT; i += 256) sW[i] = __float2half(W[i]);
    __syncthreads();

    constexpr int TILES = NN / 16;     // 6250, exact
    const int warpId = tid >> 5;
    const int warpsTotal = (gridDim.x * 256) >> 5;

    for (int tile = blockIdx.x * 8 + warpId; tile < TILES; tile += warpsTotal) {
        const int row0 = tile * 16;
        wmma::fragment<wmma::accumulator, 16, 16, 16, __half> acc[DOUT / 16];
#pragma unroll
        for (int c = 0; c < DOUT / 16; c++)
            wmma::fill_fragment(acc[c], __float2half(0.0f));

#pragma unroll
        for (int k = 0; k < DIN / 16; k++) {
            wmma::fragment<wmma::matrix_a, 16, 16, 16, __half, wmma::row_major> a;
            wmma::load_matrix_sync(a, in + (size_t)row0 * DIN + k * 16, DIN);
#pragma unroll
            for (int c = 0; c < DOUT / 16; c++) {
                wmma::fragment<wmma::matrix_b, 16, 16, 16, __half, wmma::row_major> b;
                wmma::load_matrix_sync(b, sW + k * 16 * DOUT + c * 16, DOUT);
                wmma::mma_sync(acc[c], a, b, acc[c]);
            }
        }
#pragma unroll
        for (int c = 0; c < DOUT / 16; c++)
            wmma::store_matrix_sync(out + (size_t)row0 * DOUT + c * 16, acc[c],
                                    DOUT, wmma::mem_row_major);
    }
}

// ---------------- fp8 helpers ------------------------------------------------
__device__ __forceinline__ void fp8x4_to_f32x4(unsigned r, float* f) {
    unsigned short lo = (unsigned short)(r & 0xffff);
    unsigned short hi = (unsigned short)(r >> 16);
    __half2_raw h0 = __nv_cvt_fp8x2_to_halfraw2(lo, __NV_E4M3);
    __half2_raw h1 = __nv_cvt_fp8x2_to_halfraw2(hi, __NV_E4M3);
    __half2 a = *reinterpret_cast<__half2*>(&h0);
    __half2 b = *reinterpret_cast<__half2*>(&h1);
    f[0] = __low2float(a);  f[1] = __high2float(a);
    f[2] = __low2float(b);  f[3] = __high2float(b);
}

// ---------------- CSR gather, fp8 source (DOUT=128), fp16 out w/ bias+relu ---
__global__ void __launch_bounds__(256)
k_gather8(const int* __restrict__ rowPtr, const int2* __restrict__ ePack,
          const uint8_t* __restrict__ h8, const float* __restrict__ dinv2,
          const float* __restrict__ bias, __half* __restrict__ outH) {
    const int lane = threadIdx.x & 31;
    const int warpId = (blockIdx.x * blockDim.x + threadIdx.x) >> 5;
    const int nWarps = (gridDim.x * blockDim.x) >> 5;

    float bl[4];
#pragma unroll
    for (int i = 0; i < 4; i++) bl[i] = bias[lane * 4 + i];

    for (int node = warpId; node < NN; node += nWarps) {
        const int beg = rowPtr[node];
        const int end = rowPtr[node + 1];

        float acc[4];
        {
            const float d2 = dinv2[node];
            unsigned raw = *reinterpret_cast<const unsigned*>(
                h8 + (size_t)node * 128 + lane * 4);
            float f[4];
            fp8x4_to_f32x4(raw, f);
            acc[0] = f[0] * d2;  acc[1] = f[1] * d2;
            acc[2] = f[2] * d2;  acc[3] = f[3] * d2;
        }

        for (int base = beg; base < end; base += 32) {
            const int cnt = min(32, end - base);
            int s = 0; float nm = 0.0f;
            if (lane < cnt) {
                int2 e = ePack[base + lane];
                s = e.x; nm = __int_as_float(e.y);
            }
            int j = 0;
            for (; j + 3 < cnt; j += 4) {
                int ss[4]; float nn[4]; unsigned raw[4];
#pragma unroll
                for (int q = 0; q < 4; q++) {
                    ss[q] = __shfl_sync(0xffffffffu, s,  j + q);
                    nn[q] = __shfl_sync(0xffffffffu, nm, j + q);
                }
#pragma unroll
                for (int q = 0; q < 4; q++)
                    raw[q] = *reinterpret_cast<const unsigned*>(
                        h8 + (size_t)ss[q] * 128 + lane * 4);
#pragma unroll
                for (int q = 0; q < 4; q++) {
                    float f[4];
                    fp8x4_to_f32x4(raw[q], f);
                    acc[0] = fmaf(f[0], nn[q], acc[0]);
                    acc[1] = fmaf(f[1], nn[q], acc[1]);
                    acc[2] = fmaf(f[2], nn[q], acc[2]);
                    acc[3] = fmaf(f[3], nn[q], acc[3]);
                }
            }
            for (; j < cnt; j++) {
                const int ssq   = __shfl_sync(0xffffffffu, s,  j);
                const float nnq = __shfl_sync(0xffffffffu, nm, j);
                unsigned raw = *reinterpret_cast<const unsigned*>(
                    h8 + (size_t)ssq * 128 + lane * 4);
                float f[4];
                fp8x4_to_f32x4(raw, f);
                acc[0] = fmaf(f[0], nnq, acc[0]);
                acc[1] = fmaf(f[1], nnq, acc[1]);
                acc[2] = fmaf(f[2], nnq, acc[2]);
                acc[3] = fmaf(f[3], nnq, acc[3]);
            }
        }

        // relu(agg + bias) -> fp16 (next GEMM input)
#pragma unroll
        for (int i = 0; i < 4; i++) acc[i] = fmaxf(acc[i] + bl[i], 0.0f);
        __half2 p0 = __floats2half2_rn(acc[0], acc[1]);
        __half2 p1 = __floats2half2_rn(acc[2], acc[3]);
        uint2 raw;
        raw.x = *reinterpret_cast<unsigned*>(&p0);
        raw.y = *reinterpret_cast<unsigned*>(&p1);
        *reinterpret_cast<uint2*>(outH + (size_t)node * 128 + lane * 4) = raw;
    }
}

// ---------------- CSR gather, fp16 source (DOUT=64) -> fp32 ------------------
__global__ void __launch_bounds__(256)
k_gather64(const int* __restrict__ rowPtr, const int2* __restrict__ ePack,
           const __half* __restrict__ h, const float* __restrict__ dinv2,
           float* __restrict__ outF) {
    const int lane = threadIdx.x & 31;
    const int warpId = (blockIdx.x * blockDim.x + threadIdx.x) >> 5;
    const int nWarps = (gridDim.x * blockDim.x) >> 5;

    for (int node = warpId; node < NN; node += nWarps) {
        const int beg = rowPtr[node];
        const int end = rowPtr[node + 1];

        float acc[2];
        {
            const float d2 = dinv2[node];
            unsigned raw = *reinterpret_cast<const unsigned*>(
                h + (size_t)node * 64 + lane * 2);
            __half2 a = *reinterpret_cast<__half2*>(&raw);
            acc[0] = __low2float(a) * d2;  acc[1] = __high2float(a) * d2;
        }

        for (int base = beg; base < end; base += 32) {
            const int cnt = min(32, end - base);
            int s = 0; float nm = 0.0f;
            if (lane < cnt) {
                int2 e = ePack[base + lane];
                s = e.x; nm = __int_as_float(e.y);
            }
            int j = 0;
            for (; j + 3 < cnt; j += 4) {
                int ss[4]; float nn[4]; unsigned raw[4];
#pragma unroll
                for (int q = 0; q < 4; q++) {
                    ss[q] = __shfl_sync(0xffffffffu, s,  j + q);
                    nn[q] = __shfl_sync(0xffffffffu, nm, j + q);
                }
#pragma unroll
                for (int q = 0; q < 4; q++)
                    raw[q] = *reinterpret_cast<const unsigned*>(
                        h + (size_t)ss[q] * 64 + lane * 2);
#pragma unroll
                for (int q = 0; q < 4; q++) {
                    __half2 a = *reinterpret_cast<__half2*>(&raw[q]);
                    acc[0] = fmaf(__low2float(a),  nn[q], acc[0]);
                    acc[1] = fmaf(__high2float(a), nn[q], acc[1]);
                }
            }
            for (; j < cnt; j++) {
                const int ssq   = __shfl_sync(0xffffffffu, s,  j);
                const float nnq = __shfl_sync(0xffffffffu, nm, j);
                unsigned raw = *reinterpret_cast<const unsigned*>(
                    h + (size_t)ssq * 64 + lane * 2);
                __half2 a = *reinterpret_cast<__half2*>(&raw);
                acc[0] = fmaf(__low2float(a),  nnq, acc[0]);
                acc[1] = fmaf(__high2float(a), nnq, acc[1]);
            }
        }

        *reinterpret_cast<float2*>(outF + (size_t)node * 64 + lane * 2) =
            make_float2(acc[0], acc[1]);
    }
}

// ---------------- heads: actor/critic split by block parity ------------------
constexpr int S_W1  = 0;               // 64*128
constexpr int S_W2  = S_W1 + 8192;     // 128*64
constexpr int S_W3  = S_W2 + 8192;     // 64*8
constexpr int S_B1  = S_W3 + 512;
constexpr int S_B2  = S_B1 + 128;
constexpr int S_B3  = S_B2 + 64;
constexpr int S_BIN = S_B3 + 8;
constexpr int S_H   = S_BIN + 64;      // 16*64
constexpr int S_T1  = S_H + 1024;      // 16*128
constexpr int S_T2  = S_T1 + 2048;     // 16*64
constexpr int S_LOG = S_T2 + 1024;     // 16*8
constexpr int S_TOT = S_LOG + 128;

__device__ __forceinline__ void coop_copy(float* d, const float* s, int n, int tid, int nt) {
    for (int i = tid; i < n; i += nt) d[i] = s[i];
}

__global__ void __launch_bounds__(256)
k_heads(const float* __restrict__ hagg, const float* __restrict__ b3gcn,
        const float* __restrict__ Wa1, const float* __restrict__ ba1,
        const float* __restrict__ Wa2, const float* __restrict__ ba2,
        const float* __restrict__ Wa3, const float* __restrict__ ba3,
        const float* __restrict__ Wc1, const float* __restrict__ bc1,
        const float* __restrict__ Wc2, const float* __restrict__ bc2,
        const float* __restrict__ Wc3, const float* __restrict__ bc3,
        float* __restrict__ out) {
    extern __shared__ float sm[];
    const int t = threadIdx.x;
    const bool actor = (blockIdx.x & 1) == 0;

    coop_copy(sm + S_W1, actor ? Wa1 : Wc1, 8192, t, 256);
    coop_copy(sm + S_W2, actor ? Wa2 : Wc2, 8192, t, 256);
    coop_copy(sm + S_W3, actor ? Wa3 : Wc3, actor ? 512 : 64, t, 256);
    coop_copy(sm + S_B1, actor ? ba1 : bc1, 128, t, 256);
    coop_copy(sm + S_B2, actor ? ba2 : bc2, 64, t, 256);
    coop_copy(sm + S_B3, actor ? ba3 : bc3, actor ? 8 : 1, t, 256);
    coop_copy(sm + S_BIN, b3gcn, 64, t, 256);
    __syncthreads();

    const int tileStride = (gridDim.x >> 1) * 16;
    for (int tile = (blockIdx.x >> 1) * 16; tile < NN; tile += tileStride) {
        const int rows = min(16, NN - tile);

        for (int i = t; i < rows * 64; i += 256) {
            int r = i >> 6, k = i & 63;
            sm[S_H + i] = hagg[(size_t)(tile + r) * 64 + k] + sm[S_BIN + k];
        }
        __syncthreads();

        {
            const int col = t & 127;
            const int r0 = (t >> 7) * 8;
            const float bias = sm[S_B1 + col];
            const int rEnd = min(r0 + 8, rows);
            for (int r = r0; r < rEnd; r++) {
                float acc = bias;
#pragma unroll 8
                for (int k = 0; k < 64; k++)
                    acc = fmaf(sm[S_H + r * 64 + k], sm[S_W1 + k * 128 + col], acc);
                sm[S_T1 + r * 128 + col] = fmaxf(acc, 0.0f);
            }
        }
        __syncthreads();

        {
            const int col = t & 63;
            const int r0 = (t >> 6) * 4;
            const float bias = sm[S_B2 + col];
            const int rEnd = min(r0 + 4, rows);
            for (int r = r0; r < rEnd; r++) {
                float acc = bias;
#pragma unroll 8
                for (int k = 0; k < 128; k++)
                    acc = fmaf(sm[S_T1 + r * 128 + k], sm[S_W2 + k * 64 + col], acc);
                sm[S_T2 + r * 64 + col] = fmaxf(acc, 0.0f);
            }
        }
        __syncthreads();

        if (actor) {
            if (t < 128) {
                int r = t >> 3, a = t & 7;
                if (r < rows) {
                    float acc = sm[S_B3 + a];
#pragma unroll 8
                    for (int k = 0; k < 64; k++)
                        acc = fmaf(sm[S_T2 + r * 64 + k], sm[S_W3 + k * 8 + a], acc);
                    sm[S_LOG + r * 8 + a] = acc;
                }
            }
            __syncthreads();
            if (t < rows) {
                float mx = -1e30f;
#pragma unroll
                for (int a = 0; a < 8; a++) mx = fmaxf(mx, sm[S_LOG + t * 8 + a]);
                float e[8], ssum = 0.0f;
#pragma unroll
                for (int a = 0; a < 8; a++) {
                    e[a] = expf(sm[S_LOG + t * 8 + a] - mx);
                    ssum += e[a];
                }
                float inv = 1.0f / ssum;
                size_t o = (size_t)(tile + t) * 9;
#pragma unroll
                for (int a = 0; a < 8; a++) out[o + a] = e[a] * inv;
            }
        } else {
            if (t < 16 && t < rows) {
                float acc = sm[S_B3];
#pragma unroll 8
                for (int k = 0; k < 64; k++)
                    acc = fmaf(sm[S_T2 + t * 64 + k], sm[S_W3 + k], acc);
                out[(size_t)(tile + t) * 9 + 8] = acc;
            }
            __syncthreads();
        }
        __syncthreads();
    }
}

// ---------------- launch -----------------------------------------------------
extern "C" void kernel_launch(void* const* d_in, const int* in_sizes, int n_in,
                              void* d_out, int out_size) {
    const float* x   = (const float*)d_in[0];
    const int*   eiw = (const int*)d_in[1];
    const float* W1 = (const float*)d_in[2];  const float* b1 = (const float*)d_in[3];
    const float* W2 = (const float*)d_in[4];  const float* b2 = (const float*)d_in[5];
    const float* W3 = (const float*)d_in[6];  const float* b3 = (const float*)d_in[7];
    const float* Wa1 = (const float*)d_in[8];  const float* ba1 = (const float*)d_in[9];
    const float* Wa2 = (const float*)d_in[10]; const float* ba2 = (const float*)d_in[11];
    const float* Wa3 = (const float*)d_in[12]; const float* ba3 = (const float*)d_in[13];
    const float* Wc1 = (const float*)d_in[14]; const float* bc1 = (const float*)d_in[15];
    const float* Wc2 = (const float*)d_in[16]; const float* bc2 = (const float*)d_in[17];
    const float* Wc3 = (const float*)d_in[18]; const float* bc3 = (const float*)d_in[19];
    float* out = (float*)d_out;

    void *ph, *ph8, *pact, *pB, *pdinv, *pdinv2, *pcnt, *prow, *pcur, *pep, *pcs, *pco;
    cudaGetSymbolAddress(&ph, g_h);
    cudaGetSymbolAddress(&ph8, g_h8);
    cudaGetSymbolAddress(&pact, g_act);
    cudaGetSymbolAddress(&pB, g_bufB);
    cudaGetSymbolAddress(&pdinv, g_dinv);
    cudaGetSymbolAddress(&pdinv2, g_dinv2);
    cudaGetSymbolAddress(&pcnt, g_cnt);
    cudaGetSymbolAddress(&prow, g_rowPtr);
    cudaGetSymbolAddress(&pcur, g_cur);
    cudaGetSymbolAddress(&pep, g_ePack);
    cudaGetSymbolAddress(&pcs, g_chunkSum);
    cudaGetSymbolAddress(&pco, g_chunkOff);
    __half* H = (__half*)ph;  uint8_t* H8 = (uint8_t*)ph8;
    __half* ACT = (__half*)pact;  float* B = (float*)pB;
    float* dinv = (float*)pdinv;  float* dinv2 = (float*)pdinv2;
    int* cnt = (int*)pcnt;  int* rowPtr = (int*)prow;  int* cur = (int*)pcur;
    int2* ePack = (int2*)pep;
    int* chunkSum = (int*)pcs;  int* chunkOff = (int*)pco;

    const int SM_W1 = 128 * 128 * 2;   // 32768
    const int SM_W2 = 128 * 64 * 2;    // 16384
    const int SM_H  = S_TOT * 4;       // 85536

    cudaFuncSetAttribute(k_gemm_wmma<128, 128>,
                         cudaFuncAttributeMaxDynamicSharedMemorySize, SM_W1);
    cudaFuncSetAttribute(k_gemm_wmma<128, 64>,
                         cudaFuncAttributeMaxDynamicSharedMemorySize, SM_W2);
    cudaFuncSetAttribute(k_heads,
                         cudaFuncAttributeMaxDynamicSharedMemorySize, SM_H);

    // ---- CSR build (once) ----
    k_detect<<<1, 32>>>(eiw);
    k_zero_cnt<<<(NN + 255) / 256, 256>>>(cnt);
    k_count<<<2048, 256>>>(eiw, cnt);
    k_chunk_sum<<<NCHUNK, 1024>>>(cnt, chunkSum);
    k_scan_part<<<1, 128>>>(chunkSum, chunkOff);
    k_scan_final<<<NCHUNK, 1024>>>(cnt, chunkOff, rowPtr, cur, dinv, dinv2);
    k_fill<<<2048, 256>>>(eiw, dinv, cur, ePack);

    // ---- x -> fp16 ----
    k_cvt<<<1184, 256>>>(x, ACT);

    // ---- layer 1: H = ACT @ W1; fp8-ify; gather8 -> ACT (relu(+b1), fp16) ----
    k_gemm_wmma<128, 128><<<391, 256, SM_W1>>>(ACT, W1, H);
    k_cvt8<<<1184, 256>>>(H, H8);
    k_gather8<<<1568, 256>>>(rowPtr, ePack, H8, dinv2, b1, ACT);

    // ---- layer 2: H = ACT @ W2; fp8-ify; gather8 -> ACT (relu(+b2), fp16) ----
    k_gemm_wmma<128, 128><<<391, 256, SM_W1>>>(ACT, W2, H);
    k_cvt8<<<1184, 256>>>(H, H8);
    k_gather8<<<1568, 256>>>(rowPtr, ePack, H8, dinv2, b2, ACT);

    // ---- layer 3: H = ACT @ W3 (64-dim); gather64 -> B (fp32) ----
    k_gemm_wmma<128, 64><<<391, 256, SM_W2>>>(ACT, W3, H);
    k_gather64<<<1568, 256>>>(rowPtr, ePack, H, dinv2, B);

    // ---- heads (actor: even blocks, critic: odd blocks) ----
    k_heads<<<304, 256, SM_H>>>(B, b3,
                                Wa1, ba1, Wa2, ba2, Wa3, ba3,
                                Wc1, bc1, Wc2, bc2, Wc3, bc3, out);
}

// round 9
// speedup vs baseline: 4.0348x; 1.2771x over previous
#include <cuda_runtime.h>
#include <cuda_fp16.h>
#include <cuda_fp8.h>
#include <mma.h>
#include <cstddef>
#include <cstdint>

using namespace nvcuda;

#define NN 100000
#define NE 3200000
#define NCHUNK ((NN + 1023) / 1024)   // 98

// ---------------- scratch (module-load allocated, no runtime alloc) ----------
__device__ __align__(16) __half g_h[(size_t)NN * 128];    // GEMM out / C1
__device__ __align__(16) uint8_t g_h8[(size_t)NN * 128];  // fp8 copy / A2(half)
__device__ __align__(16) __half g_act[(size_t)NN * 128];  // GEMM in / A1
__device__ __align__(16) __half g_hd[(size_t)NN * 128];   // Hfinal (64) + C2 (64)
__device__ float g_dinv[NN];
__device__ float g_dinv2[NN];
__device__ int g_cnt[NN];
__device__ int g_rowPtr[NN + 1];
__device__ int g_cur[NN];
__device__ __align__(16) int2 g_ePack[NE];   // {src, norm-as-int} per CSR slot
__device__ int g_chunkSum[NCHUNK];
__device__ int g_chunkOff[NCHUNK + 1];
__device__ int g_is64;

// ---------------- edge-index dtype probe ------------------------------------
__global__ void k_detect(const int* __restrict__ w) {
    if (blockIdx.x == 0 && threadIdx.x == 0) {
        int is64 = 1;
        for (int i = 0; i < 2048; i += 2) {
            if (w[i + 1] != 0) { is64 = 0; break; }
        }
        g_is64 = is64;
    }
}

__global__ void k_zero_cnt(int* __restrict__ cnt) {
    int i = blockIdx.x * blockDim.x + threadIdx.x;
    if (i < NN) cnt[i] = 0;
}

__global__ void k_count(const int* __restrict__ w, int* __restrict__ cnt) {
    const int is64 = g_is64;
    long long i = (long long)blockIdx.x * blockDim.x + threadIdx.x;
    long long stride = (long long)gridDim.x * blockDim.x;
    if (is64) {
        for (; i < NE; i += stride)
            atomicAdd(&cnt[w[2 * (long long)NE + 2 * i]], 1);
    } else {
        for (; i < NE; i += stride)
            atomicAdd(&cnt[w[NE + i]], 1);
    }
}

// ---------------- parallel 3-phase prefix scan -------------------------------
__global__ void __launch_bounds__(1024)
k_chunk_sum(const int* __restrict__ cnt, int* __restrict__ chunkSum) {
    __shared__ int sred[32];
    const int tid = threadIdx.x;
    const int idx = blockIdx.x * 1024 + tid;
    int v = (idx < NN) ? cnt[idx] : 0;
    for (int o = 16; o > 0; o >>= 1) v += __shfl_down_sync(0xffffffffu, v, o);
    if ((tid & 31) == 0) sred[tid >> 5] = v;
    __syncthreads();
    if (tid < 32) {
        int x = sred[tid];
        for (int o = 16; o > 0; o >>= 1) x += __shfl_down_sync(0xffffffffu, x, o);
        if (tid == 0) chunkSum[blockIdx.x] = x;
    }
}

__global__ void __launch_bounds__(128)
k_scan_part(const int* __restrict__ chunkSum, int* __restrict__ chunkOff) {
    __shared__ int s[NCHUNK];
    const int tid = threadIdx.x;
    for (int i = tid; i < NCHUNK; i += 128) s[i] = chunkSum[i];
    __syncthreads();
    if (tid == 0) {
        int acc = 0;
        for (int i = 0; i < NCHUNK; i++) { int v = s[i]; s[i] = acc; acc += v; }
        chunkOff[NCHUNK] = acc;
    }
    __syncthreads();
    for (int i = tid; i < NCHUNK; i += 128) chunkOff[i] = s[i];
}

__global__ void __launch_bounds__(1024)
k_scan_final(const int* __restrict__ cnt, const int* __restrict__ chunkOff,
             int* __restrict__ rowPtr, int* __restrict__ cur,
             float* __restrict__ dinv, float* __restrict__ dinv2) {
    __shared__ int swarp[32];
    const int tid = threadIdx.x;
    const int idx = blockIdx.x * 1024 + tid;
    int v = (idx < NN) ? cnt[idx] : 0;

    int incl = v;
    for (int o = 1; o < 32; o <<= 1) {
        int t = __shfl_up_sync(0xffffffffu, incl, o);
        if ((tid & 31) >= o) incl += t;
    }
    if ((tid & 31) == 31) swarp[tid >> 5] = incl;
    __syncthreads();
    if (tid < 32) {
        int x = swarp[tid];
        for (int o = 1; o < 32; o <<= 1) {
            int t = __shfl_up_sync(0xffffffffu, x, o);
            if (tid >= o) x += t;
        }
        swarp[tid] = x;
    }
    __syncthreads();
    int warpBase = (tid >= 32) ? swarp[(tid >> 5) - 1] : 0;
    int inclTotal = incl + warpBase;

    if (idx < NN) {
        int start = chunkOff[blockIdx.x] + inclTotal - v;
        rowPtr[idx] = start;
        cur[idx] = start;
        float dv = rsqrtf((float)(v + 1));
        dinv[idx] = dv;
        dinv2[idx] = dv * dv;
    }
    if (blockIdx.x == gridDim.x - 1 && tid == 0)
        rowPtr[NN] = chunkOff[NCHUNK];
}

__global__ void k_fill(const int* __restrict__ w, const float* __restrict__ dinv,
                       int* __restrict__ cur, int2* __restrict__ ePack) {
    const int is64 = g_is64;
    long long i = (long long)blockIdx.x * blockDim.x + threadIdx.x;
    long long stride = (long long)gridDim.x * blockDim.x;
    for (; i < NE; i += stride) {
        int s, d;
        if (is64) { s = w[2 * i]; d = w[2 * (long long)NE + 2 * i]; }
        else      { s = w[i];     d = w[NE + i]; }
        int pos = atomicAdd(&cur[d], 1);
        ePack[pos] = make_int2(s, __float_as_int(dinv[s] * dinv[d]));
    }
}

// ---------------- x -> fp16 convert ------------------------------------------
__global__ void k_cvt(const float* __restrict__ x, __half* __restrict__ o) {
    long long i = (long long)blockIdx.x * blockDim.x + threadIdx.x;
    long long stride = (long long)gridDim.x * blockDim.x;
    const long long n4 = (long long)NN * 128 / 4;
    const float4* x4 = reinterpret_cast<const float4*>(x);
    for (; i < n4; i += stride) {
        float4 v = x4[i];
        __half2 p0 = __floats2half2_rn(v.x, v.y);
        __half2 p1 = __floats2half2_rn(v.z, v.w);
        uint2 raw;
        raw.x = *reinterpret_cast<unsigned*>(&p0);
        raw.y = *reinterpret_cast<unsigned*>(&p1);
        *reinterpret_cast<uint2*>(o + 4 * i) = raw;
    }
}

// ---------------- fp16 -> fp8(e4m3) convert ----------------------------------
__global__ void k_cvt8(const __half* __restrict__ h, uint8_t* __restrict__ o) {
    long long i = (long long)blockIdx.x * blockDim.x + threadIdx.x;
    long long stride = (long long)gridDim.x * blockDim.x;
    const long long n8 = (long long)NN * 128 / 8;
    const uint4* h8 = reinterpret_cast<const uint4*>(h);   // 8 halves
    for (; i < n8; i += stride) {
        uint4 v = h8[i];
        __half2_raw a0 = *reinterpret_cast<__half2_raw*>(&v.x);
        __half2_raw a1 = *reinterpret_cast<__half2_raw*>(&v.y);
        __half2_raw a2 = *reinterpret_cast<__half2_raw*>(&v.z);
        __half2_raw a3 = *reinterpret_cast<__half2_raw*>(&v.w);
        unsigned short f0 = __nv_cvt_halfraw2_to_fp8x2(a0, __NV_SATFINITE, __NV_E4M3);
        unsigned short f1 = __nv_cvt_halfraw2_to_fp8x2(a1, __NV_SATFINITE, __NV_E4M3);
        unsigned short f2 = __nv_cvt_halfraw2_to_fp8x2(a2, __NV_SATFINITE, __NV_E4M3);
        unsigned short f3 = __nv_cvt_halfraw2_to_fp8x2(a3, __NV_SATFINITE, __NV_E4M3);
        uint2 out;
        out.x = (unsigned)f0 | ((unsigned)f1 << 16);
        out.y = (unsigned)f2 | ((unsigned)f3 << 16);
        *reinterpret_cast<uint2*>(o + 8 * i) = out;
    }
}

// ---------------- WMMA GEMM: out = in @ W  (fp16 in/out, fp16 accum) ---------
template <int DIN, int DOUT>
__global__ void __launch_bounds__(256)
k_gemm_wmma(const __half* __restrict__ in, const float* __restrict__ W,
            __half* __restrict__ out) {
    extern __shared__ __half sW[];     // DIN*DOUT halves
    const int tid = threadIdx.x;
    for (int i = tid; i < DIN * DOUT; i += 256) sW[i] = __float2half(W[i]);
    __syncthreads();

    constexpr int TILES = NN / 16;     // 6250, exact
    const int warpId = tid >> 5;
    const int warpsTotal = (gridDim.x * 256) >> 5;

    for (int tile = blockIdx.x * 8 + warpId; tile < TILES; tile += warpsTotal) {
        const int row0 = tile * 16;
        wmma::fragment<wmma::accumulator, 16, 16, 16, __half> acc[DOUT / 16];
#pragma unroll
        for (int c = 0; c < DOUT / 16; c++)
            wmma::fill_fragment(acc[c], __float2half(0.0f));

#pragma unroll
        for (int k = 0; k < DIN / 16; k++) {
            wmma::fragment<wmma::matrix_a, 16, 16, 16, __half, wmma::row_major> a;
            wmma::load_matrix_sync(a, in + (size_t)row0 * DIN + k * 16, DIN);
#pragma unroll
            for (int c = 0; c < DOUT / 16; c++) {
                wmma::fragment<wmma::matrix_b, 16, 16, 16, __half, wmma::row_major> b;
                wmma::load_matrix_sync(b, sW + k * 16 * DOUT + c * 16, DOUT);
                wmma::mma_sync(acc[c], a, b, acc[c]);
            }
        }
#pragma unroll
        for (int c = 0; c < DOUT / 16; c++)
            wmma::store_matrix_sync(out + (size_t)row0 * DOUT + c * 16, acc[c],
                                    DOUT, wmma::mem_row_major);
    }
}

// ---------------- WMMA GEMM + bias + ReLU (heads) ----------------------------
template <int DIN, int DOUT>
__global__ void __launch_bounds__(256)
kh_gemm(const __half* __restrict__ in, const float* __restrict__ W,
        const float* __restrict__ bias, __half* __restrict__ out) {
    extern __shared__ __half smh[];
    __half* sW = smh;                                   // DIN*DOUT
    __half2* sB2 = (__half2*)(smh + DIN * DOUT);        // DOUT/2 half2
    __half* sStage = smh + DIN * DOUT + DOUT;           // 8 * 16 * DOUT
    const int tid = threadIdx.x;
    for (int i = tid; i < DIN * DOUT; i += 256) sW[i] = __float2half(W[i]);
    if (tid < DOUT / 2)
        sB2[tid] = __floats2half2_rn(bias[2 * tid], bias[2 * tid + 1]);
    __syncthreads();

    constexpr int TILES = NN / 16;
    const int warpId = tid >> 5;
    const int lane = tid & 31;
    __half* stage = sStage + warpId * 16 * DOUT;
    const int warpsTotal = (gridDim.x * 256) >> 5;
    const __half2 zero2 = __floats2half2_rn(0.0f, 0.0f);

    for (int tile = blockIdx.x * 8 + warpId; tile < TILES; tile += warpsTotal) {
        const int row0 = tile * 16;
        wmma::fragment<wmma::accumulator, 16, 16, 16, __half> acc[DOUT / 16];
#pragma unroll
        for (int c = 0; c < DOUT / 16; c++)
            wmma::fill_fragment(acc[c], __float2half(0.0f));

#pragma unroll
        for (int k = 0; k < DIN / 16; k++) {
            wmma::fragment<wmma::matrix_a, 16, 16, 16, __half, wmma::row_major> a;
            wmma::load_matrix_sync(a, in + (size_t)row0 * DIN + k * 16, DIN);
#pragma unroll
            for (int c = 0; c < DOUT / 16; c++) {
                wmma::fragment<wmma::matrix_b, 16, 16, 16, __half, wmma::row_major> b;
                wmma::load_matrix_sync(b, sW + k * 16 * DOUT + c * 16, DOUT);
                wmma::mma_sync(acc[c], a, b, acc[c]);
            }
        }
#pragma unroll
        for (int c = 0; c < DOUT / 16; c++)
            wmma::store_matrix_sync(stage + c * 16, acc[c], DOUT,
                                    wmma::mem_row_major);
        __syncwarp();

        // epilogue: each lane owns half a row (DOUT/2 halves, 16B aligned)
        {
            const int r = lane >> 1;
            const int hOff = (lane & 1) * (DOUT / 2);
            const __half2* src = (const __half2*)(stage + r * DOUT + hOff);
            __half2* dst = (__half2*)(out + (size_t)(row0 + r) * DOUT + hOff);
            const __half2* b2 = sB2 + hOff / 2;
#pragma unroll
            for (int i = 0; i < DOUT / 4; i++) {
                __half2 v = __hmax2(__hadd2(src[i], b2[i]), zero2);
                dst[i] = v;
            }
        }
        __syncwarp();
    }
}

// ---------------- fp8 helpers ------------------------------------------------
__device__ __forceinline__ void fp8x4_to_f32x4(unsigned r, float* f) {
    unsigned short lo = (unsigned short)(r & 0xffff);
    unsigned short hi = (unsigned short)(r >> 16);
    __half2_raw h0 = __nv_cvt_fp8x2_to_halfraw2(lo, __NV_E4M3);
    __half2_raw h1 = __nv_cvt_fp8x2_to_halfraw2(hi, __NV_E4M3);
    __half2 a = *reinterpret_cast<__half2*>(&h0);
    __half2 b = *reinterpret_cast<__half2*>(&h1);
    f[0] = __low2float(a);  f[1] = __high2float(a);
    f[2] = __low2float(b);  f[3] = __high2float(b);
}

// ---------------- CSR gather, fp8 source (DOUT=128), fp16 out w/ bias+relu ---
__global__ void __launch_bounds__(256)
k_gather8(const int* __restrict__ rowPtr, const int2* __restrict__ ePack,
          const uint8_t* __restrict__ h8, const float* __restrict__ dinv2,
          const float* __restrict__ bias, __half* __restrict__ outH) {
    const int lane = threadIdx.x & 31;
    const int warpId = (blockIdx.x * blockDim.x + threadIdx.x) >> 5;
    const int nWarps = (gridDim.x * blockDim.x) >> 5;

    float bl[4];
#pragma unroll
    for (int i = 0; i < 4; i++) bl[i] = bias[lane * 4 + i];

    for (int node = warpId; node < NN; node += nWarps) {
        const int beg = rowPtr[node];
        const int end = rowPtr[node + 1];

        float acc[4];
        {
            const float d2 = dinv2[node];
            unsigned raw = *reinterpret_cast<const unsigned*>(
                h8 + (size_t)node * 128 + lane * 4);
            float f[4];
            fp8x4_to_f32x4(raw, f);
            acc[0] = f[0] * d2;  acc[1] = f[1] * d2;
            acc[2] = f[2] * d2;  acc[3] = f[3] * d2;
        }

        for (int base = beg; base < end; base += 32) {
            const int cnt = min(32, end - base);
            int s = 0; float nm = 0.0f;
            if (lane < cnt) {
                int2 e = ePack[base + lane];
                s = e.x; nm = __int_as_float(e.y);
            }
            int j = 0;
            for (; j + 3 < cnt; j += 4) {
                int ss[4]; float nn[4]; unsigned raw[4];
#pragma unroll
                for (int q = 0; q < 4; q++) {
                    ss[q] = __shfl_sync(0xffffffffu, s,  j + q);
                    nn[q] = __shfl_sync(0xffffffffu, nm, j + q);
                }
#pragma unroll
                for (int q = 0; q < 4; q++)
                    raw[q] = *reinterpret_cast<const unsigned*>(
                        h8 + (size_t)ss[q] * 128 + lane * 4);
#pragma unroll
                for (int q = 0; q < 4; q++) {
                    float f[4];
                    fp8x4_to_f32x4(raw[q], f);
                    acc[0] = fmaf(f[0], nn[q], acc[0]);
                    acc[1] = fmaf(f[1], nn[q], acc[1]);
                    acc[2] = fmaf(f[2], nn[q], acc[2]);
                    acc[3] = fmaf(f[3], nn[q], acc[3]);
                }
            }
            for (; j < cnt; j++) {
                const int ssq   = __shfl_sync(0xffffffffu, s,  j);
                const float nnq = __shfl_sync(0xffffffffu, nm, j);
                unsigned raw = *reinterpret_cast<const unsigned*>(
                    h8 + (size_t)ssq * 128 + lane * 4);
                float f[4];
                fp8x4_to_f32x4(raw, f);
                acc[0] = fmaf(f[0], nnq, acc[0]);
                acc[1] = fmaf(f[1], nnq, acc[1]);
                acc[2] = fmaf(f[2], nnq, acc[2]);
                acc[3] = fmaf(f[3], nnq, acc[3]);
            }
        }

#pragma unroll
        for (int i = 0; i < 4; i++) acc[i] = fmaxf(acc[i] + bl[i], 0.0f);
        __half2 p0 = __floats2half2_rn(acc[0], acc[1]);
        __half2 p1 = __floats2half2_rn(acc[2], acc[3]);
        uint2 raw;
        raw.x = *reinterpret_cast<unsigned*>(&p0);
        raw.y = *reinterpret_cast<unsigned*>(&p1);
        *reinterpret_cast<uint2*>(outH + (size_t)node * 128 + lane * 4) = raw;
    }
}

// ---------------- CSR gather, fp16 src (DOUT=64) -> fp16 (+b3, NO relu) ------
__global__ void __launch_bounds__(256)
k_gather64h(const int* __restrict__ rowPtr, const int2* __restrict__ ePack,
            const __half* __restrict__ h, const float* __restrict__ dinv2,
            const float* __restrict__ b3, __half* __restrict__ outH) {
    const int lane = threadIdx.x & 31;
    const int warpId = (blockIdx.x * blockDim.x + threadIdx.x) >> 5;
    const int nWarps = (gridDim.x * blockDim.x) >> 5;

    const float b0 = b3[lane * 2];
    const float b1v = b3[lane * 2 + 1];

    for (int node = warpId; node < NN; node += nWarps) {
        const int beg = rowPtr[node];
        const int end = rowPtr[node + 1];

        float acc[2];
        {
            const float d2 = dinv2[node];
            unsigned raw = *reinterpret_cast<const unsigned*>(
                h + (size_t)node * 64 + lane * 2);
            __half2 a = *reinterpret_cast<__half2*>(&raw);
            acc[0] = __low2float(a) * d2;  acc[1] = __high2float(a) * d2;
        }

        for (int base = beg; base < end; base += 32) {
            const int cnt = min(32, end - base);
            int s = 0; float nm = 0.0f;
            if (lane < cnt) {
                int2 e = ePack[base + lane];
                s = e.x; nm = __int_as_float(e.y);
            }
            int j = 0;
            for (; j + 3 < cnt; j += 4) {
                int ss[4]; float nn[4]; unsigned raw[4];
#pragma unroll
                for (int q = 0; q < 4; q++) {
                    ss[q] = __shfl_sync(0xffffffffu, s,  j + q);
                    nn[q] = __shfl_sync(0xffffffffu, nm, j + q);
                }
#pragma unroll
                for (int q = 0; q < 4; q++)
                    raw[q] = *reinterpret_cast<const unsigned*>(
                        h + (size_t)ss[q] * 64 + lane * 2);
#pragma unroll
                for (int q = 0; q < 4; q++) {
                    __half2 a = *reinterpret_cast<__half2*>(&raw[q]);
                    acc[0] = fmaf(__low2float(a),  nn[q], acc[0]);
                    acc[1] = fmaf(__high2float(a), nn[q], acc[1]);
                }
            }
            for (; j < cnt; j++) {
                const int ssq   = __shfl_sync(0xffffffffu, s,  j);
                const float nnq = __shfl_sync(0xffffffffu, nm, j);
                unsigned raw = *reinterpret_cast<const unsigned*>(
                    h + (size_t)ssq * 64 + lane * 2);
                __half2 a = *reinterpret_cast<__half2*>(&raw);
                acc[0] = fmaf(__low2float(a),  nnq, acc[0]);
                acc[1] = fmaf(__high2float(a), nnq, acc[1]);
            }
        }

        __half2 p = __floats2half2_rn(acc[0] + b0, acc[1] + b1v);
        *reinterpret_cast<unsigned*>(outH + (size_t)node * 64 + lane * 2) =
            *reinterpret_cast<unsigned*>(&p);
    }
}

// ---------------- final: logits+softmax and value ----------------------------
__global__ void __launch_bounds__(256)
k_final(const __half* __restrict__ A2, const __half* __restrict__ C2,
        const float* __restrict__ Wa3, const float* __restrict__ ba3,
        const float* __restrict__ Wc3, const float* __restrict__ bc3,
        float* __restrict__ out) {
    __shared__ float sWa[64 * 8];
    __shared__ float sWc[64];
    __shared__ float sba[8];
    __shared__ float sbc;
    const int tid = threadIdx.x;
    for (int i = tid; i < 64 * 8; i += 256) sWa[i] = Wa3[i];
    if (tid < 64) sWc[tid] = Wc3[tid];
    if (tid < 8) sba[tid] = ba3[tid];
    if (tid == 0) sbc = bc3[0];
    __syncthreads();

    for (int node = blockIdx.x * 256 + tid; node < NN; node += gridDim.x * 256) {
        float lg[8];
#pragma unroll
        for (int a = 0; a < 8; a++) lg[a] = sba[a];
        const uint4* ap = reinterpret_cast<const uint4*>(A2 + (size_t)node * 64);
#pragma unroll
        for (int c = 0; c < 8; c++) {
            uint4 v = ap[c];
            const __half2* hp = reinterpret_cast<const __half2*>(&v);
#pragma unroll
            for (int p = 0; p < 4; p++) {
                float f0 = __low2float(hp[p]);
                float f1 = __high2float(hp[p]);
                int k0 = c * 8 + p * 2;
#pragma unroll
                for (int a = 0; a < 8; a++) {
                    lg[a] = fmaf(f0, sWa[k0 * 8 + a], lg[a]);
                    lg[a] = fmaf(f1, sWa[(k0 + 1) * 8 + a], lg[a]);
                }
            }
        }
        float mx = -1e30f;
#pragma unroll
        for (int a = 0; a < 8; a++) mx = fmaxf(mx, lg[a]);
        float e[8], ssum = 0.0f;
#pragma unroll
        for (int a = 0; a < 8; a++) { e[a] = expf(lg[a] - mx); ssum += e[a]; }
        float inv = 1.0f / ssum;

        float val = sbc;
        const uint4* cp = reinterpret_cast<const uint4*>(C2 + (size_t)node * 64);
#pragma unroll
        for (int c = 0; c < 8; c++) {
            uint4 v = cp[c];
            const __half2* hp = reinterpret_cast<const __half2*>(&v);
#pragma unroll
            for (int p = 0; p < 4; p++) {
                int k0 = c * 8 + p * 2;
                val = fmaf(__low2float(hp[p]),  sWc[k0], val);
                val = fmaf(__high2float(hp[p]), sWc[k0 + 1], val);
            }
        }

        size_t o = (size_t)node * 9;
#pragma unroll
        for (int a = 0; a < 8; a++) out[o + a] = e[a] * inv;
        out[o + 8] = val;
    }
}

// ---------------- launch -----------------------------------------------------
extern "C" void kernel_launch(void* const* d_in, const int* in_sizes, int n_in,
                              void* d_out, int out_size) {
    const float* x   = (const float*)d_in[0];
    const int*   eiw = (const int*)d_in[1];
    const float* W1 = (const float*)d_in[2];  const float* b1 = (const float*)d_in[3];
    const float* W2 = (const float*)d_in[4];  const float* b2 = (const float*)d_in[5];
    const float* W3 = (const float*)d_in[6];  const float* b3 = (const float*)d_in[7];
    const float* Wa1 = (const float*)d_in[8];  const float* ba1 = (const float*)d_in[9];
    const float* Wa2 = (const float*)d_in[10]; const float* ba2 = (const float*)d_in[11];
    const float* Wa3 = (const float*)d_in[12]; const float* ba3 = (const float*)d_in[13];
    const float* Wc1 = (const float*)d_in[14]; const float* bc1 = (const float*)d_in[15];
    const float* Wc2 = (const float*)d_in[16]; const float* bc2 = (const float*)d_in[17];
    const float* Wc3 = (const float*)d_in[18]; const float* bc3 = (const float*)d_in[19];
    float* out = (float*)d_out;

    void *ph, *ph8, *pact, *phd, *pdinv, *pdinv2, *pcnt, *prow, *pcur, *pep, *pcs, *pco;
    cudaGetSymbolAddress(&ph, g_h);
    cudaGetSymbolAddress(&ph8, g_h8);
    cudaGetSymbolAddress(&pact, g_act);
    cudaGetSymbolAddress(&phd, g_hd);
    cudaGetSymbolAddress(&pdinv, g_dinv);
    cudaGetSymbolAddress(&pdinv2, g_dinv2);
    cudaGetSymbolAddress(&pcnt, g_cnt);
    cudaGetSymbolAddress(&prow, g_rowPtr);
    cudaGetSymbolAddress(&pcur, g_cur);
    cudaGetSymbolAddress(&pep, g_ePack);
    cudaGetSymbolAddress(&pcs, g_chunkSum);
    cudaGetSymbolAddress(&pco, g_chunkOff);
    __half* H = (__half*)ph;  uint8_t* H8 = (uint8_t*)ph8;
    __half* ACT = (__half*)pact;
    __half* HF = (__half*)phd;                 // Hfinal [NN,64]
    __half* C2 = (__half*)phd + (size_t)NN * 64;
    __half* A1 = ACT;                          // reuse after layer-3 GEMM
    __half* C1 = H;                            // reuse after gather64h
    __half* A2 = (__half*)ph8;                 // reuse fp8 buffer as halves
    float* dinv = (float*)pdinv;  float* dinv2 = (float*)pdinv2;
    int* cnt = (int*)pcnt;  int* rowPtr = (int*)prow;  int* cur = (int*)pcur;
    int2* ePack = (int2*)pep;
    int* chunkSum = (int*)pcs;  int* chunkOff = (int*)pco;

    const int SM_W1 = 128 * 128 * 2;                            // 32768
    const int SM_W2 = 128 * 64 * 2;                             // 16384
    const int SM_HA = (64 * 128 + 128 + 8 * 16 * 128) * 2;      // 49408
    const int SM_HB = (128 * 64 + 64 + 8 * 16 * 64) * 2;        // 32896

    cudaFuncSetAttribute(k_gemm_wmma<128, 128>,
                         cudaFuncAttributeMaxDynamicSharedMemorySize, SM_W1);
    cudaFuncSetAttribute(k_gemm_wmma<128, 64>,
                         cudaFuncAttributeMaxDynamicSharedMemorySize, SM_W2);
    cudaFuncSetAttribute(kh_gemm<64, 128>,
                         cudaFuncAttributeMaxDynamicSharedMemorySize, SM_HA);
    cudaFuncSetAttribute(kh_gemm<128, 64>,
                         cudaFuncAttributeMaxDynamicSharedMemorySize, SM_HB);

    // ---- CSR build (once) ----
    k_detect<<<1, 32>>>(eiw);
    k_zero_cnt<<<(NN + 255) / 256, 256>>>(cnt);
    k_count<<<2048, 256>>>(eiw, cnt);
    k_chunk_sum<<<NCHUNK, 1024>>>(cnt, chunkSum);
    k_scan_part<<<1, 128>>>(chunkSum, chunkOff);
    k_scan_final<<<NCHUNK, 1024>>>(cnt, chunkOff, rowPtr, cur, dinv, dinv2);
    k_fill<<<2048, 256>>>(eiw, dinv, cur, ePack);

    // ---- x -> fp16 ----
    k_cvt<<<1184, 256>>>(x, ACT);

    // ---- layer 1 ----
    k_gemm_wmma<128, 128><<<391, 256, SM_W1>>>(ACT, W1, H);
    k_cvt8<<<1184, 256>>>(H, H8);
    k_gather8<<<1568, 256>>>(rowPtr, ePack, H8, dinv2, b1, ACT);

    // ---- layer 2 ----
    k_gemm_wmma<128, 128><<<391, 256, SM_W1>>>(ACT, W2, H);
    k_cvt8<<<1184, 256>>>(H, H8);
    k_gather8<<<1568, 256>>>(rowPtr, ePack, H8, dinv2, b2, ACT);

    // ---- layer 3: H = ACT @ W3 (64); gather -> HF = agg + b3 (fp16) ----
    k_gemm_wmma<128, 64><<<391, 256, SM_W2>>>(ACT, W3, H);
    k_gather64h<<<1568, 256>>>(rowPtr, ePack, H, dinv2, b3, HF);

    // ---- heads as WMMA GEMMs ----
    kh_gemm<64, 128><<<391, 256, SM_HA>>>(HF, Wa1, ba1, A1);
    kh_gemm<64, 128><<<391, 256, SM_HA>>>(HF, Wc1, bc1, C1);
    kh_gemm<128, 64><<<391, 256, SM_HB>>>(A1, Wa2, ba2, A2);
    kh_gemm<128, 64><<<391, 256, SM_HB>>>(C1, Wc2, bc2, C2);

    // ---- final: softmax + value -> out [NN, 9] ----
    k_final<<<391, 256>>>(A2, C2, Wa3, ba3, Wc3, bc3, out);
}

// round 10
// speedup vs baseline: 4.2987x; 1.0654x over previous
#include <cuda_runtime.h>
#include <cuda_fp16.h>
#include <cuda_fp8.h>
#include <mma.h>
#include <cstddef>
#include <cstdint>

using namespace nvcuda;

#define NN 100000
#define NE 3200000
#define NCHUNK ((NN + 1023) / 1024)   // 98

// ---------------- scratch (module-load allocated, no runtime alloc) ----------
__device__ __align__(16) __half g_h[(size_t)NN * 128];    // GEMM out L3 / C1
__device__ __align__(16) uint8_t g_h8[(size_t)NN * 128];  // fp8 GEMM out / A2
__device__ __align__(16) __half g_act[(size_t)NN * 128];  // GEMM in / A1
__device__ __align__(16) __half g_hd[(size_t)NN * 128];   // Hfinal (64) + C2 (64)
__device__ float g_dinv[NN];
__device__ float g_dinv2[NN];
__device__ int g_cnt[NN];
__device__ int g_rowPtr[NN + 1];
__device__ int g_cur[NN];
__device__ __align__(16) unsigned g_ePack[NE];  // (fp16 norm bits)<<17 | src
__device__ int g_chunkSum[NCHUNK];
__device__ int g_chunkOff[NCHUNK + 1];
__device__ int g_is64;

// ---------------- edge-index dtype probe ------------------------------------
__global__ void k_detect(const int* __restrict__ w) {
    if (blockIdx.x == 0 && threadIdx.x == 0) {
        int is64 = 1;
        for (int i = 0; i < 2048; i += 2) {
            if (w[i + 1] != 0) { is64 = 0; break; }
        }
        g_is64 = is64;
    }
}

__global__ void k_zero_cnt(int* __restrict__ cnt) {
    int i = blockIdx.x * blockDim.x + threadIdx.x;
    if (i < NN) cnt[i] = 0;
}

__global__ void k_count(const int* __restrict__ w, int* __restrict__ cnt) {
    const int is64 = g_is64;
    long long i = (long long)blockIdx.x * blockDim.x + threadIdx.x;
    long long stride = (long long)gridDim.x * blockDim.x;
    if (is64) {
        for (; i < NE; i += stride)
            atomicAdd(&cnt[w[2 * (long long)NE + 2 * i]], 1);
    } else {
        for (; i < NE; i += stride)
            atomicAdd(&cnt[w[NE + i]], 1);
    }
}

// ---------------- parallel 3-phase prefix scan -------------------------------
__global__ void __launch_bounds__(1024)
k_chunk_sum(const int* __restrict__ cnt, int* __restrict__ chunkSum) {
    __shared__ int sred[32];
    const int tid = threadIdx.x;
    const int idx = blockIdx.x * 1024 + tid;
    int v = (idx < NN) ? cnt[idx] : 0;
    for (int o = 16; o > 0; o >>= 1) v += __shfl_down_sync(0xffffffffu, v, o);
    if ((tid & 31) == 0) sred[tid >> 5] = v;
    __syncthreads();
    if (tid < 32) {
        int x = sred[tid];
        for (int o = 16; o > 0; o >>= 1) x += __shfl_down_sync(0xffffffffu, x, o);
        if (tid == 0) chunkSum[blockIdx.x] = x;
    }
}

__global__ void __launch_bounds__(128)
k_scan_part(const int* __restrict__ chunkSum, int* __restrict__ chunkOff) {
    __shared__ int s[NCHUNK];
    const int tid = threadIdx.x;
    for (int i = tid; i < NCHUNK; i += 128) s[i] = chunkSum[i];
    __syncthreads();
    if (tid == 0) {
        int acc = 0;
        for (int i = 0; i < NCHUNK; i++) { int v = s[i]; s[i] = acc; acc += v; }
        chunkOff[NCHUNK] = acc;
    }
    __syncthreads();
    for (int i = tid; i < NCHUNK; i += 128) chunkOff[i] = s[i];
}

__global__ void __launch_bounds__(1024)
k_scan_final(const int* __restrict__ cnt, const int* __restrict__ chunkOff,
             int* __restrict__ rowPtr, int* __restrict__ cur,
             float* __restrict__ dinv, float* __restrict__ dinv2) {
    __shared__ int swarp[32];
    const int tid = threadIdx.x;
    const int idx = blockIdx.x * 1024 + tid;
    int v = (idx < NN) ? cnt[idx] : 0;

    int incl = v;
    for (int o = 1; o < 32; o <<= 1) {
        int t = __shfl_up_sync(0xffffffffu, incl, o);
        if ((tid & 31) >= o) incl += t;
    }
    if ((tid & 31) == 31) swarp[tid >> 5] = incl;
    __syncthreads();
    if (tid < 32) {
        int x = swarp[tid];
        for (int o = 1; o < 32; o <<= 1) {
            int t = __shfl_up_sync(0xffffffffu, x, o);
            if (tid >= o) x += t;
        }
        swarp[tid] = x;
    }
    __syncthreads();
    int warpBase = (tid >= 32) ? swarp[(tid >> 5) - 1] : 0;
    int inclTotal = incl + warpBase;

    if (idx < NN) {
        int start = chunkOff[blockIdx.x] + inclTotal - v;
        rowPtr[idx] = start;
        cur[idx] = start;
        float dv = rsqrtf((float)(v + 1));
        dinv[idx] = dv;
        dinv2[idx] = dv * dv;
    }
    if (blockIdx.x == gridDim.x - 1 && tid == 0)
        rowPtr[NN] = chunkOff[NCHUNK];
}

// fill CSR slots: pack = (fp16(norm) bits)<<17 | src   (norm>0 -> sign bit 0)
__global__ void k_fill(const int* __restrict__ w, const float* __restrict__ dinv,
                       int* __restrict__ cur, unsigned* __restrict__ ePack) {
    const int is64 = g_is64;
    long long i = (long long)blockIdx.x * blockDim.x + threadIdx.x;
    long long stride = (long long)gridDim.x * blockDim.x;
    for (; i < NE; i += stride) {
        int s, d;
        if (is64) { s = w[2 * i]; d = w[2 * (long long)NE + 2 * i]; }
        else      { s = w[i];     d = w[NE + i]; }
        int pos = atomicAdd(&cur[d], 1);
        unsigned nb = __half_as_ushort(__float2half_rn(dinv[s] * dinv[d]));
        ePack[pos] = (nb << 17) | (unsigned)s;
    }
}

// ---------------- x -> fp16 convert ------------------------------------------
__global__ void k_cvt(const float* __restrict__ x, __half* __restrict__ o) {
    long long i = (long long)blockIdx.x * blockDim.x + threadIdx.x;
    long long stride = (long long)gridDim.x * blockDim.x;
    const long long n4 = (long long)NN * 128 / 4;
    const float4* x4 = reinterpret_cast<const float4*>(x);
    for (; i < n4; i += stride) {
        float4 v = x4[i];
        __half2 p0 = __floats2half2_rn(v.x, v.y);
        __half2 p1 = __floats2half2_rn(v.z, v.w);
        uint2 raw;
        raw.x = *reinterpret_cast<unsigned*>(&p0);
        raw.y = *reinterpret_cast<unsigned*>(&p1);
        *reinterpret_cast<uint2*>(o + 4 * i) = raw;
    }
}

// ---------------- WMMA GEMM: out = in @ W  (fp16), fp8 e4m3 output -----------
__global__ void __launch_bounds__(256)
k_gemm_wmma8(const __half* __restrict__ in, const float* __restrict__ W,
             uint8_t* __restrict__ out8) {
    extern __shared__ __half smg[];
    __half* sW = smg;                         // 128*128
    __half* sStage = smg + 128 * 128;         // 8 * 16 * 128
    const int tid = threadIdx.x;
    for (int i = tid; i < 128 * 128; i += 256) sW[i] = __float2half(W[i]);
    __syncthreads();

    constexpr int TILES = NN / 16;
    const int warpId = tid >> 5;
    const int lane = tid & 31;
    __half* stage = sStage + warpId * 16 * 128;
    const int warpsTotal = (gridDim.x * 256) >> 5;

    for (int tile = blockIdx.x * 8 + warpId; tile < TILES; tile += warpsTotal) {
        const int row0 = tile * 16;
        wmma::fragment<wmma::accumulator, 16, 16, 16, __half> acc[8];
#pragma unroll
        for (int c = 0; c < 8; c++)
            wmma::fill_fragment(acc[c], __float2half(0.0f));

#pragma unroll
        for (int k = 0; k < 8; k++) {
            wmma::fragment<wmma::matrix_a, 16, 16, 16, __half, wmma::row_major> a;
            wmma::load_matrix_sync(a, in + (size_t)row0 * 128 + k * 16, 128);
#pragma unroll
            for (int c = 0; c < 8; c++) {
                wmma::fragment<wmma::matrix_b, 16, 16, 16, __half, wmma::row_major> b;
                wmma::load_matrix_sync(b, sW + k * 16 * 128 + c * 16, 128);
                wmma::mma_sync(acc[c], a, b, acc[c]);
            }
        }
#pragma unroll
        for (int c = 0; c < 8; c++)
            wmma::store_matrix_sync(stage + c * 16, acc[c], 128,
                                    wmma::mem_row_major);
        __syncwarp();

        // epilogue: lane owns half a row (64 halves -> 64 fp8 bytes)
        {
            const int r = lane >> 1;
            const int hOff = (lane & 1) * 64;
            const __half2* src = (const __half2*)(stage + r * 128 + hOff);
            uint8_t* dst = out8 + (size_t)(row0 + r) * 128 + hOff;
#pragma unroll
            for (int g = 0; g < 4; g++) {
                unsigned short f[8];
#pragma unroll
                for (int p = 0; p < 8; p++) {
                    __half2 v = src[g * 8 + p];
                    __half2_raw vr = *reinterpret_cast<__half2_raw*>(&v);
                    f[p] = __nv_cvt_halfraw2_to_fp8x2(vr, __NV_SATFINITE, __NV_E4M3);
                }
                uint4 o;
                o.x = (unsigned)f[0] | ((unsigned)f[1] << 16);
                o.y = (unsigned)f[2] | ((unsigned)f[3] << 16);
                o.z = (unsigned)f[4] | ((unsigned)f[5] << 16);
                o.w = (unsigned)f[6] | ((unsigned)f[7] << 16);
                *reinterpret_cast<uint4*>(dst + g * 16) = o;
            }
        }
        __syncwarp();
    }
}

// ---------------- WMMA GEMM: fp16 out (layer 3) ------------------------------
template <int DIN, int DOUT>
__global__ void __launch_bounds__(256)
k_gemm_wmma(const __half* __restrict__ in, const float* __restrict__ W,
            __half* __restrict__ out) {
    extern __shared__ __half sW[];
    const int tid = threadIdx.x;
    for (int i = tid; i < DIN * DOUT; i += 256) sW[i] = __float2half(W[i]);
    __syncthreads();

    constexpr int TILES = NN / 16;
    const int warpId = tid >> 5;
    const int warpsTotal = (gridDim.x * 256) >> 5;

    for (int tile = blockIdx.x * 8 + warpId; tile < TILES; tile += warpsTotal) {
        const int row0 = tile * 16;
        wmma::fragment<wmma::accumulator, 16, 16, 16, __half> acc[DOUT / 16];
#pragma unroll
        for (int c = 0; c < DOUT / 16; c++)
            wmma::fill_fragment(acc[c], __float2half(0.0f));

#pragma unroll
        for (int k = 0; k < DIN / 16; k++) {
            wmma::fragment<wmma::matrix_a, 16, 16, 16, __half, wmma::row_major> a;
            wmma::load_matrix_sync(a, in + (size_t)row0 * DIN + k * 16, DIN);
#pragma unroll
            for (int c = 0; c < DOUT / 16; c++) {
                wmma::fragment<wmma::matrix_b, 16, 16, 16, __half, wmma::row_major> b;
                wmma::load_matrix_sync(b, sW + k * 16 * DOUT + c * 16, DOUT);
                wmma::mma_sync(acc[c], a, b, acc[c]);
            }
        }
#pragma unroll
        for (int c = 0; c < DOUT / 16; c++)
            wmma::store_matrix_sync(out + (size_t)row0 * DOUT + c * 16, acc[c],
                                    DOUT, wmma::mem_row_major);
    }
}

// ---------------- WMMA GEMM + bias + ReLU (heads) ----------------------------
template <int DIN, int DOUT>
__global__ void __launch_bounds__(256)
kh_gemm(const __half* __restrict__ in, const float* __restrict__ W,
        const float* __restrict__ bias, __half* __restrict__ out) {
    extern __shared__ __half smh[];
    __half* sW = smh;
    __half2* sB2 = (__half2*)(smh + DIN * DOUT);
    __half* sStage = smh + DIN * DOUT + DOUT;
    const int tid = threadIdx.x;
    for (int i = tid; i < DIN * DOUT; i += 256) sW[i] = __float2half(W[i]);
    if (tid < DOUT / 2)
        sB2[tid] = __floats2half2_rn(bias[2 * tid], bias[2 * tid + 1]);
    __syncthreads();

    constexpr int TILES = NN / 16;
    const int warpId = tid >> 5;
    const int lane = tid & 31;
    __half* stage = sStage + warpId * 16 * DOUT;
    const int warpsTotal = (gridDim.x * 256) >> 5;
    const __half2 zero2 = __floats2half2_rn(0.0f, 0.0f);

    for (int tile = blockIdx.x * 8 + warpId; tile < TILES; tile += warpsTotal) {
        const int row0 = tile * 16;
        wmma::fragment<wmma::accumulator, 16, 16, 16, __half> acc[DOUT / 16];
#pragma unroll
        for (int c = 0; c < DOUT / 16; c++)
            wmma::fill_fragment(acc[c], __float2half(0.0f));

#pragma unroll
        for (int k = 0; k < DIN / 16; k++) {
            wmma::fragment<wmma::matrix_a, 16, 16, 16, __half, wmma::row_major> a;
            wmma::load_matrix_sync(a, in + (size_t)row0 * DIN + k * 16, DIN);
#pragma unroll
            for (int c = 0; c < DOUT / 16; c++) {
                wmma::fragment<wmma::matrix_b, 16, 16, 16, __half, wmma::row_major> b;
                wmma::load_matrix_sync(b, sW + k * 16 * DOUT + c * 16, DOUT);
                wmma::mma_sync(acc[c], a, b, acc[c]);
            }
        }
#pragma unroll
        for (int c = 0; c < DOUT / 16; c++)
            wmma::store_matrix_sync(stage + c * 16, acc[c], DOUT,
                                    wmma::mem_row_major);
        __syncwarp();

        {
            const int r = lane >> 1;
            const int hOff = (lane & 1) * (DOUT / 2);
            const __half2* src = (const __half2*)(stage + r * DOUT + hOff);
            __half2* dst = (__half2*)(out + (size_t)(row0 + r) * DOUT + hOff);
            const __half2* b2 = sB2 + hOff / 2;
#pragma unroll
            for (int i = 0; i < DOUT / 4; i++) {
                __half2 v = __hmax2(__hadd2(src[i], b2[i]), zero2);
                dst[i] = v;
            }
        }
        __syncwarp();
    }
}

// ---------------- edge decode helpers ----------------------------------------
__device__ __forceinline__ int edge_src(unsigned v) { return (int)(v & 0x1FFFFu); }
__device__ __forceinline__ __half2 edge_norm_h2(unsigned v) {
    unsigned hb = v >> 17;                 // 15-bit fp16 (sign 0)
    unsigned pair = hb | (hb << 16);
    return *reinterpret_cast<__half2*>(&pair);
}
__device__ __forceinline__ float edge_norm_f(unsigned v) {
    unsigned short hb = (unsigned short)(v >> 17);
    return __half2float(__ushort_as_half(hb));
}

// ---------------- CSR gather, fp8 source (128), half2 accum ------------------
__global__ void __launch_bounds__(256)
k_gather8(const int* __restrict__ rowPtr, const unsigned* __restrict__ ePack,
          const uint8_t* __restrict__ h8, const float* __restrict__ dinv2,
          const float* __restrict__ bias, __half* __restrict__ outH) {
    const int lane = threadIdx.x & 31;
    const int warpId = (blockIdx.x * blockDim.x + threadIdx.x) >> 5;
    const int nWarps = (gridDim.x * blockDim.x) >> 5;

    float bl[4];
#pragma unroll
    for (int i = 0; i < 4; i++) bl[i] = bias[lane * 4 + i];

    for (int node = warpId; node < NN; node += nWarps) {
        const int beg = rowPtr[node];
        const int end = rowPtr[node + 1];

        __half2 acc0, acc1;
        {
            const float d2 = dinv2[node];
            const __half2 d2h = __float2half2_rn(d2);
            unsigned raw = *reinterpret_cast<const unsigned*>(
                h8 + (size_t)node * 128 + lane * 4);
            __half2_raw r0 = __nv_cvt_fp8x2_to_halfraw2(
                (unsigned short)(raw & 0xffff), __NV_E4M3);
            __half2_raw r1 = __nv_cvt_fp8x2_to_halfraw2(
                (unsigned short)(raw >> 16), __NV_E4M3);
            acc0 = __hmul2(*reinterpret_cast<__half2*>(&r0), d2h);
            acc1 = __hmul2(*reinterpret_cast<__half2*>(&r1), d2h);
        }

        for (int base = beg; base < end; base += 32) {
            const int cnt = min(32, end - base);
            unsigned e = (lane < cnt) ? ePack[base + lane] : 0u;
            int j = 0;
            for (; j + 3 < cnt; j += 4) {
                unsigned v[4]; unsigned raw[4];
#pragma unroll
                for (int q = 0; q < 4; q++)
                    v[q] = __shfl_sync(0xffffffffu, e, j + q);
#pragma unroll
                for (int q = 0; q < 4; q++)
                    raw[q] = *reinterpret_cast<const unsigned*>(
                        h8 + (size_t)edge_src(v[q]) * 128 + lane * 4);
#pragma unroll
                for (int q = 0; q < 4; q++) {
                    __half2 nm = edge_norm_h2(v[q]);
                    __half2_raw r0 = __nv_cvt_fp8x2_to_halfraw2(
                        (unsigned short)(raw[q] & 0xffff), __NV_E4M3);
                    __half2_raw r1 = __nv_cvt_fp8x2_to_halfraw2(
                        (unsigned short)(raw[q] >> 16), __NV_E4M3);
                    acc0 = __hfma2(*reinterpret_cast<__half2*>(&r0), nm, acc0);
                    acc1 = __hfma2(*reinterpret_cast<__half2*>(&r1), nm, acc1);
                }
            }
            for (; j < cnt; j++) {
                unsigned v = __shfl_sync(0xffffffffu, e, j);
                unsigned raw = *reinterpret_cast<const unsigned*>(
                    h8 + (size_t)edge_src(v) * 128 + lane * 4);
                __half2 nm = edge_norm_h2(v);
                __half2_raw r0 = __nv_cvt_fp8x2_to_halfraw2(
                    (unsigned short)(raw & 0xffff), __NV_E4M3);
                __half2_raw r1 = __nv_cvt_fp8x2_to_halfraw2(
                    (unsigned short)(raw >> 16), __NV_E4M3);
                acc0 = __hfma2(*reinterpret_cast<__half2*>(&r0), nm, acc0);
                acc1 = __hfma2(*reinterpret_cast<__half2*>(&r1), nm, acc1);
            }
        }

        // relu(agg + bias) in fp32 -> fp16
        float a0 = fmaxf(__low2float(acc0)  + bl[0], 0.0f);
        float a1 = fmaxf(__high2float(acc0) + bl[1], 0.0f);
        float a2 = fmaxf(__low2float(acc1)  + bl[2], 0.0f);
        float a3 = fmaxf(__high2float(acc1) + bl[3], 0.0f);
        __half2 p0 = __floats2half2_rn(a0, a1);
        __half2 p1 = __floats2half2_rn(a2, a3);
        uint2 raw;
        raw.x = *reinterpret_cast<unsigned*>(&p0);
        raw.y = *reinterpret_cast<unsigned*>(&p1);
        *reinterpret_cast<uint2*>(outH + (size_t)node * 128 + lane * 4) = raw;
    }
}

// ---------------- CSR gather, fp16 src (64) -> fp16 (+b3, NO relu) -----------
__global__ void __launch_bounds__(256)
k_gather64h(const int* __restrict__ rowPtr, const unsigned* __restrict__ ePack,
            const __half* __restrict__ h, const float* __restrict__ dinv2,
            const float* __restrict__ b3, __half* __restrict__ outH) {
    const int lane = threadIdx.x & 31;
    const int warpId = (blockIdx.x * blockDim.x + threadIdx.x) >> 5;
    const int nWarps = (gridDim.x * blockDim.x) >> 5;

    const float b0 = b3[lane * 2];
    const float b1v = b3[lane * 2 + 1];

    for (int node = warpId; node < NN; node += nWarps) {
        const int beg = rowPtr[node];
        const int end = rowPtr[node + 1];

        float acc0, acc1;
        {
            const float d2 = dinv2[node];
            unsigned raw = *reinterpret_cast<const unsigned*>(
                h + (size_t)node * 64 + lane * 2);
            __half2 a = *reinterpret_cast<__half2*>(&raw);
            acc0 = __low2float(a) * d2;  acc1 = __high2float(a) * d2;
        }

        for (int base = beg; base < end; base += 32) {
            const int cnt = min(32, end - base);
            unsigned e = (lane < cnt) ? ePack[base + lane] : 0u;
            int j = 0;
            for (; j + 3 < cnt; j += 4) {
                unsigned v[4]; unsigned raw[4];
#pragma unroll
                for (int q = 0; q < 4; q++)
                    v[q] = __shfl_sync(0xffffffffu, e, j + q);
#pragma unroll
                for (int q = 0; q < 4; q++)
                    raw[q] = *reinterpret_cast<const unsigned*>(
                        h + (size_t)edge_src(v[q]) * 64 + lane * 2);
#pragma unroll
                for (int q = 0; q < 4; q++) {
                    float nm = edge_norm_f(v[q]);
                    __half2 a = *reinterpret_cast<__half2*>(&raw[q]);
                    acc0 = fmaf(__low2float(a),  nm, acc0);
                    acc1 = fmaf(__high2float(a), nm, acc1);
                }
            }
            for (; j < cnt; j++) {
                unsigned v = __shfl_sync(0xffffffffu, e, j);
                unsigned raw = *reinterpret_cast<const unsigned*>(
                    h + (size_t)edge_src(v) * 64 + lane * 2);
                float nm = edge_norm_f(v);
                __half2 a = *reinterpret_cast<__half2*>(&raw);
                acc0 = fmaf(__low2float(a),  nm, acc0);
                acc1 = fmaf(__high2float(a), nm, acc1);
            }
        }

        __half2 p = __floats2half2_rn(acc0 + b0, acc1 + b1v);
        *reinterpret_cast<unsigned*>(outH + (size_t)node * 64 + lane * 2) =
            *reinterpret_cast<unsigned*>(&p);
    }
}

// ---------------- final: logits+softmax and value ----------------------------
__global__ void __launch_bounds__(256)
k_final(const __half* __restrict__ A2, const __half* __restrict__ C2,
        const float* __restrict__ Wa3, const float* __restrict__ ba3,
        const float* __restrict__ Wc3, const float* __restrict__ bc3,
        float* __restrict__ out) {
    __shared__ float sWa[64 * 8];
    __shared__ float sWc[64];
    __shared__ float sba[8];
    __shared__ float sbc;
    const int tid = threadIdx.x;
    for (int i = tid; i < 64 * 8; i += 256) sWa[i] = Wa3[i];
    if (tid < 64) sWc[tid] = Wc3[tid];
    if (tid < 8) sba[tid] = ba3[tid];
    if (tid == 0) sbc = bc3[0];
    __syncthreads();

    for (int node = blockIdx.x * 256 + tid; node < NN; node += gridDim.x * 256) {
        float lg[8];
#pragma unroll
        for (int a = 0; a < 8; a++) lg[a] = sba[a];
        const uint4* ap = reinterpret_cast<const uint4*>(A2 + (size_t)node * 64);
#pragma unroll
        for (int c = 0; c < 8; c++) {
            uint4 v = ap[c];
            const __half2* hp = reinterpret_cast<const __half2*>(&v);
#pragma unroll
            for (int p = 0; p < 4; p++) {
                float f0 = __low2float(hp[p]);
                float f1 = __high2float(hp[p]);
                int k0 = c * 8 + p * 2;
#pragma unroll
                for (int a = 0; a < 8; a++) {
                    lg[a] = fmaf(f0, sWa[k0 * 8 + a], lg[a]);
                    lg[a] = fmaf(f1, sWa[(k0 + 1) * 8 + a], lg[a]);
                }
            }
        }
        float mx = -1e30f;
#pragma unroll
        for (int a = 0; a < 8; a++) mx = fmaxf(mx, lg[a]);
        float e[8], ssum = 0.0f;
#pragma unroll
        for (int a = 0; a < 8; a++) { e[a] = expf(lg[a] - mx); ssum += e[a]; }
        float inv = 1.0f / ssum;

        float val = sbc;
        const uint4* cp = reinterpret_cast<const uint4*>(C2 + (size_t)node * 64);
#pragma unroll
        for (int c = 0; c < 8; c++) {
            uint4 v = cp[c];
            const __half2* hp = reinterpret_cast<const __half2*>(&v);
#pragma unroll
            for (int p = 0; p < 4; p++) {
                int k0 = c * 8 + p * 2;
                val = fmaf(__low2float(hp[p]),  sWc[k0], val);
                val = fmaf(__high2float(hp[p]), sWc[k0 + 1], val);
            }
        }

        size_t o = (size_t)node * 9;
#pragma unroll
        for (int a = 0; a < 8; a++) out[o + a] = e[a] * inv;
        out[o + 8] = val;
    }
}

// ---------------- launch -----------------------------------------------------
extern "C" void kernel_launch(void* const* d_in, const int* in_sizes, int n_in,
                              void* d_out, int out_size) {
    const float* x   = (const float*)d_in[0];
    const int*   eiw = (const int*)d_in[1];
    const float* W1 = (const float*)d_in[2];  const float* b1 = (const float*)d_in[3];
    const float* W2 = (const float*)d_in[4];  const float* b2 = (const float*)d_in[5];
    const float* W3 = (const float*)d_in[6];  const float* b3 = (const float*)d_in[7];
    const float* Wa1 = (const float*)d_in[8];  const float* ba1 = (const float*)d_in[9];
    const float* Wa2 = (const float*)d_in[10]; const float* ba2 = (const float*)d_in[11];
    const float* Wa3 = (const float*)d_in[12]; const float* ba3 = (const float*)d_in[13];
    const float* Wc1 = (const float*)d_in[14]; const float* bc1 = (const float*)d_in[15];
    const float* Wc2 = (const float*)d_in[16]; const float* bc2 = (const float*)d_in[17];
    const float* Wc3 = (const float*)d_in[18]; const float* bc3 = (const float*)d_in[19];
    float* out = (float*)d_out;

    void *ph, *ph8, *pact, *phd, *pdinv, *pdinv2, *pcnt, *prow, *pcur, *pep, *pcs, *pco;
    cudaGetSymbolAddress(&ph, g_h);
    cudaGetSymbolAddress(&ph8, g_h8);
    cudaGetSymbolAddress(&pact, g_act);
    cudaGetSymbolAddress(&phd, g_hd);
    cudaGetSymbolAddress(&pdinv, g_dinv);
    cudaGetSymbolAddress(&pdinv2, g_dinv2);
    cudaGetSymbolAddress(&pcnt, g_cnt);
    cudaGetSymbolAddress(&prow, g_rowPtr);
    cudaGetSymbolAddress(&pcur, g_cur);
    cudaGetSymbolAddress(&pep, g_ePack);
    cudaGetSymbolAddress(&pcs, g_chunkSum);
    cudaGetSymbolAddress(&pco, g_chunkOff);
    __half* H = (__half*)ph;  uint8_t* H8 = (uint8_t*)ph8;
    __half* ACT = (__half*)pact;
    __half* HF = (__half*)phd;                 // Hfinal [NN,64]
    __half* C2 = (__half*)phd + (size_t)NN * 64;
    __half* A1 = ACT;
    __half* C1 = H;
    __half* A2 = (__half*)ph8;
    float* dinv = (float*)pdinv;  float* dinv2 = (float*)pdinv2;
    int* cnt = (int*)pcnt;  int* rowPtr = (int*)prow;  int* cur = (int*)pcur;
    unsigned* ePack = (unsigned*)pep;
    int* chunkSum = (int*)pcs;  int* chunkOff = (int*)pco;

    const int SM_G8 = (128 * 128 + 8 * 16 * 128) * 2;           // 65536
    const int SM_W2 = 128 * 64 * 2;                             // 16384
    const int SM_HA = (64 * 128 + 128 + 8 * 16 * 128) * 2;      // 49408
    const int SM_HB = (128 * 64 + 64 + 8 * 16 * 64) * 2;        // 32896

    cudaFuncSetAttribute(k_gemm_wmma8,
                         cudaFuncAttributeMaxDynamicSharedMemorySize, SM_G8);
    cudaFuncSetAttribute(k_gemm_wmma<128, 64>,
                         cudaFuncAttributeMaxDynamicSharedMemorySize, SM_W2);
    cudaFuncSetAttribute(kh_gemm<64, 128>,
                         cudaFuncAttributeMaxDynamicSharedMemorySize, SM_HA);
    cudaFuncSetAttribute(kh_gemm<128, 64>,
                         cudaFuncAttributeMaxDynamicSharedMemorySize, SM_HB);

    // ---- CSR build (once) ----
    k_detect<<<1, 32>>>(eiw);
    k_zero_cnt<<<(NN + 255) / 256, 256>>>(cnt);
    k_count<<<2048, 256>>>(eiw, cnt);
    k_chunk_sum<<<NCHUNK, 1024>>>(cnt, chunkSum);
    k_scan_part<<<1, 128>>>(chunkSum, chunkOff);
    k_scan_final<<<NCHUNK, 1024>>>(cnt, chunkOff, rowPtr, cur, dinv, dinv2);
    k_fill<<<2048, 256>>>(eiw, dinv, cur, ePack);

    // ---- x -> fp16 ----
    k_cvt<<<1184, 256>>>(x, ACT);

    // ---- layer 1: H8 = fp8(ACT @ W1); gather8 -> ACT (relu(+b1), fp16) ----
    k_gemm_wmma8<<<391, 256, SM_G8>>>(ACT, W1, H8);
    k_gather8<<<1568, 256>>>(rowPtr, ePack, H8, dinv2, b1, ACT);

    // ---- layer 2 ----
    k_gemm_wmma8<<<391, 256, SM_G8>>>(ACT, W2, H8);
    k_gather8<<<1568, 256>>>(rowPtr, ePack, H8, dinv2, b2, ACT);

    // ---- layer 3: H = ACT @ W3 (64); gather -> HF = agg + b3 (fp16) ----
    k_gemm_wmma<128, 64><<<391, 256, SM_W2>>>(ACT, W3, H);
    k_gather64h<<<1568, 256>>>(rowPtr, ePack, H, dinv2, b3, HF);

    // ---- heads as WMMA GEMMs ----
    kh_gemm<64, 128><<<391, 256, SM_HA>>>(HF, Wa1, ba1, A1);
    kh_gemm<64, 128><<<391, 256, SM_HA>>>(HF, Wc1, bc1, C1);
    kh_gemm<128, 64><<<391, 256, SM_HB>>>(A1, Wa2, ba2, A2);
    kh_gemm<128, 64><<<391, 256, SM_HB>>>(C1, Wc2, bc2, C2);

    // ---- final: softmax + value -> out [NN, 9] ----
    k_final<<<391, 256>>>(A2, C2, Wa3, ba3, Wc3, bc3, out);
}

// round 11
// speedup vs baseline: 4.6582x; 1.0836x over previous
#include <cuda_runtime.h>
#include <cuda_fp16.h>
#include <cuda_fp8.h>
#include <mma.h>
#include <cstddef>
#include <cstdint>

using namespace nvcuda;

#define NN 100000
#define NE 3200000
#define NCHUNK ((NN + 1023) / 1024)   // 98

// ---------------- scratch (module-load allocated, no runtime alloc) ----------
__device__ __align__(16) __half g_h[(size_t)NN * 128];    // GEMM out L3
__device__ __align__(16) uint8_t g_h8[(size_t)NN * 128];  // fp8 GEMM out
__device__ __align__(16) __half g_act[(size_t)NN * 128];  // GEMM input
__device__ __align__(16) __half g_hd[(size_t)NN * 64];    // Hfinal
__device__ float g_dinv[NN];
__device__ float g_dinv2[NN];
__device__ int g_cnt[NN];
__device__ int g_rowPtr[NN + 1];
__device__ int g_cur[NN];
__device__ __align__(16) unsigned g_ePack[NE];  // (fp16 norm bits)<<17 | src
__device__ int g_chunkSum[NCHUNK];
__device__ int g_chunkOff[NCHUNK + 1];
__device__ int g_is64;

// ---------------- init: zero counts + edge dtype probe -----------------------
__global__ void k_init(const int* __restrict__ w, int* __restrict__ cnt) {
    int i = blockIdx.x * blockDim.x + threadIdx.x;
    if (i < NN) cnt[i] = 0;
    if (i == 0) {
        int is64 = 1;
        for (int k = 0; k < 2048; k += 2) {
            if (w[k + 1] != 0) { is64 = 0; break; }
        }
        g_is64 = is64;
    }
}

__global__ void k_count(const int* __restrict__ w, int* __restrict__ cnt) {
    const int is64 = g_is64;
    long long i = (long long)blockIdx.x * blockDim.x + threadIdx.x;
    long long stride = (long long)gridDim.x * blockDim.x;
    if (is64) {
        for (; i < NE; i += stride)
            atomicAdd(&cnt[w[2 * (long long)NE + 2 * i]], 1);
    } else {
        for (; i < NE; i += stride)
            atomicAdd(&cnt[w[NE + i]], 1);
    }
}

// ---------------- parallel 3-phase prefix scan -------------------------------
__global__ void __launch_bounds__(1024)
k_chunk_sum(const int* __restrict__ cnt, int* __restrict__ chunkSum) {
    __shared__ int sred[32];
    const int tid = threadIdx.x;
    const int idx = blockIdx.x * 1024 + tid;
    int v = (idx < NN) ? cnt[idx] : 0;
    for (int o = 16; o > 0; o >>= 1) v += __shfl_down_sync(0xffffffffu, v, o);
    if ((tid & 31) == 0) sred[tid >> 5] = v;
    __syncthreads();
    if (tid < 32) {
        int x = sred[tid];
        for (int o = 16; o > 0; o >>= 1) x += __shfl_down_sync(0xffffffffu, x, o);
        if (tid == 0) chunkSum[blockIdx.x] = x;
    }
}

__global__ void __launch_bounds__(128)
k_scan_part(const int* __restrict__ chunkSum, int* __restrict__ chunkOff) {
    __shared__ int s[NCHUNK];
    const int tid = threadIdx.x;
    for (int i = tid; i < NCHUNK; i += 128) s[i] = chunkSum[i];
    __syncthreads();
    if (tid == 0) {
        int acc = 0;
        for (int i = 0; i < NCHUNK; i++) { int v = s[i]; s[i] = acc; acc += v; }
        chunkOff[NCHUNK] = acc;
    }
    __syncthreads();
    for (int i = tid; i < NCHUNK; i += 128) chunkOff[i] = s[i];
}

__global__ void __launch_bounds__(1024)
k_scan_final(const int* __restrict__ cnt, const int* __restrict__ chunkOff,
             int* __restrict__ rowPtr, int* __restrict__ cur,
             float* __restrict__ dinv, float* __restrict__ dinv2) {
    __shared__ int swarp[32];
    const int tid = threadIdx.x;
    const int idx = blockIdx.x * 1024 + tid;
    int v = (idx < NN) ? cnt[idx] : 0;

    int incl = v;
    for (int o = 1; o < 32; o <<= 1) {
        int t = __shfl_up_sync(0xffffffffu, incl, o);
        if ((tid & 31) >= o) incl += t;
    }
    if ((tid & 31) == 31) swarp[tid >> 5] = incl;
    __syncthreads();
    if (tid < 32) {
        int x = swarp[tid];
        for (int o = 1; o < 32; o <<= 1) {
            int t = __shfl_up_sync(0xffffffffu, x, o);
            if (tid >= o) x += t;
        }
        swarp[tid] = x;
    }
    __syncthreads();
    int warpBase = (tid >= 32) ? swarp[(tid >> 5) - 1] : 0;
    int inclTotal = incl + warpBase;

    if (idx < NN) {
        int start = chunkOff[blockIdx.x] + inclTotal - v;
        rowPtr[idx] = start;
        cur[idx] = start;
        float dv = rsqrtf((float)(v + 1));
        dinv[idx] = dv;
        dinv2[idx] = dv * dv;
    }
    if (blockIdx.x == gridDim.x - 1 && tid == 0)
        rowPtr[NN] = chunkOff[NCHUNK];
}

// fill CSR slots: pack = (fp16(norm) bits)<<17 | src
__global__ void k_fill(const int* __restrict__ w, const float* __restrict__ dinv,
                       int* __restrict__ cur, unsigned* __restrict__ ePack) {
    const int is64 = g_is64;
    long long i = (long long)blockIdx.x * blockDim.x + threadIdx.x;
    long long stride = (long long)gridDim.x * blockDim.x;
    for (; i < NE; i += stride) {
        int s, d;
        if (is64) { s = w[2 * i]; d = w[2 * (long long)NE + 2 * i]; }
        else      { s = w[i];     d = w[NE + i]; }
        int pos = atomicAdd(&cur[d], 1);
        unsigned nb = __half_as_ushort(__float2half_rn(dinv[s] * dinv[d]));
        ePack[pos] = (nb << 17) | (unsigned)s;
    }
}

// ---------------- x -> fp16 convert ------------------------------------------
__global__ void k_cvt(const float* __restrict__ x, __half* __restrict__ o) {
    long long i = (long long)blockIdx.x * blockDim.x + threadIdx.x;
    long long stride = (long long)gridDim.x * blockDim.x;
    const long long n4 = (long long)NN * 128 / 4;
    const float4* x4 = reinterpret_cast<const float4*>(x);
    for (; i < n4; i += stride) {
        float4 v = x4[i];
        __half2 p0 = __floats2half2_rn(v.x, v.y);
        __half2 p1 = __floats2half2_rn(v.z, v.w);
        uint2 raw;
        raw.x = *reinterpret_cast<unsigned*>(&p0);
        raw.y = *reinterpret_cast<unsigned*>(&p1);
        *reinterpret_cast<uint2*>(o + 4 * i) = raw;
    }
}

// ---------------- WMMA GEMM: out = in @ W  (fp16), fp8 e4m3 output -----------
__global__ void __launch_bounds__(256)
k_gemm_wmma8(const __half* __restrict__ in, const float* __restrict__ W,
             uint8_t* __restrict__ out8) {
    extern __shared__ __half smg[];
    __half* sW = smg;                         // 128*128
    __half* sStage = smg + 128 * 128;         // 8 * 16 * 128
    const int tid = threadIdx.x;
    for (int i = tid; i < 128 * 128; i += 256) sW[i] = __float2half(W[i]);
    __syncthreads();

    constexpr int TILES = NN / 16;
    const int warpId = tid >> 5;
    const int lane = tid & 31;
    __half* stage = sStage + warpId * 16 * 128;
    const int warpsTotal = (gridDim.x * 256) >> 5;

    for (int tile = blockIdx.x * 8 + warpId; tile < TILES; tile += warpsTotal) {
        const int row0 = tile * 16;
        wmma::fragment<wmma::accumulator, 16, 16, 16, __half> acc[8];
#pragma unroll
        for (int c = 0; c < 8; c++)
            wmma::fill_fragment(acc[c], __float2half(0.0f));

#pragma unroll
        for (int k = 0; k < 8; k++) {
            wmma::fragment<wmma::matrix_a, 16, 16, 16, __half, wmma::row_major> a;
            wmma::load_matrix_sync(a, in + (size_t)row0 * 128 + k * 16, 128);
#pragma unroll
            for (int c = 0; c < 8; c++) {
                wmma::fragment<wmma::matrix_b, 16, 16, 16, __half, wmma::row_major> b;
                wmma::load_matrix_sync(b, sW + k * 16 * 128 + c * 16, 128);
                wmma::mma_sync(acc[c], a, b, acc[c]);
            }
        }
#pragma unroll
        for (int c = 0; c < 8; c++)
            wmma::store_matrix_sync(stage + c * 16, acc[c], 128,
                                    wmma::mem_row_major);
        __syncwarp();

        {
            const int r = lane >> 1;
            const int hOff = (lane & 1) * 64;
            const __half2* src = (const __half2*)(stage + r * 128 + hOff);
            uint8_t* dst = out8 + (size_t)(row0 + r) * 128 + hOff;
#pragma unroll
            for (int g = 0; g < 4; g++) {
                unsigned short f[8];
#pragma unroll
                for (int p = 0; p < 8; p++) {
                    __half2 v = src[g * 8 + p];
                    __half2_raw vr = *reinterpret_cast<__half2_raw*>(&v);
                    f[p] = __nv_cvt_halfraw2_to_fp8x2(vr, __NV_SATFINITE, __NV_E4M3);
                }
                uint4 o;
                o.x = (unsigned)f[0] | ((unsigned)f[1] << 16);
                o.y = (unsigned)f[2] | ((unsigned)f[3] << 16);
                o.z = (unsigned)f[4] | ((unsigned)f[5] << 16);
                o.w = (unsigned)f[6] | ((unsigned)f[7] << 16);
                *reinterpret_cast<uint4*>(dst + g * 16) = o;
            }
        }
        __syncwarp();
    }
}

// ---------------- WMMA GEMM: fp16 out (layer 3) ------------------------------
template <int DIN, int DOUT>
__global__ void __launch_bounds__(256)
k_gemm_wmma(const __half* __restrict__ in, const float* __restrict__ W,
            __half* __restrict__ out) {
    extern __shared__ __half sW[];
    const int tid = threadIdx.x;
    for (int i = tid; i < DIN * DOUT; i += 256) sW[i] = __float2half(W[i]);
    __syncthreads();

    constexpr int TILES = NN / 16;
    const int warpId = tid >> 5;
    const int warpsTotal = (gridDim.x * 256) >> 5;

    for (int tile = blockIdx.x * 8 + warpId; tile < TILES; tile += warpsTotal) {
        const int row0 = tile * 16;
        wmma::fragment<wmma::accumulator, 16, 16, 16, __half> acc[DOUT / 16];
#pragma unroll
        for (int c = 0; c < DOUT / 16; c++)
            wmma::fill_fragment(acc[c], __float2half(0.0f));

#pragma unroll
        for (int k = 0; k < DIN / 16; k++) {
            wmma::fragment<wmma::matrix_a, 16, 16, 16, __half, wmma::row_major> a;
            wmma::load_matrix_sync(a, in + (size_t)row0 * DIN + k * 16, DIN);
#pragma unroll
            for (int c = 0; c < DOUT / 16; c++) {
                wmma::fragment<wmma::matrix_b, 16, 16, 16, __half, wmma::row_major> b;
                wmma::load_matrix_sync(b, sW + k * 16 * DOUT + c * 16, DOUT);
                wmma::mma_sync(acc[c], a, b, acc[c]);
            }
        }
#pragma unroll
        for (int c = 0; c < DOUT / 16; c++)
            wmma::store_matrix_sync(out + (size_t)row0 * DOUT + c * 16, acc[c],
                                    DOUT, wmma::mem_row_major);
    }
}

// ---------------- edge decode helpers ----------------------------------------
__device__ __forceinline__ int edge_src(unsigned v) { return (int)(v & 0x1FFFFu); }
__device__ __forceinline__ __half2 edge_norm_h2(unsigned v) {
    unsigned hb = v >> 17;
    unsigned pair = hb | (hb << 16);
    return *reinterpret_cast<__half2*>(&pair);
}
__device__ __forceinline__ float edge_norm_f(unsigned v) {
    unsigned short hb = (unsigned short)(v >> 17);
    return __half2float(__ushort_as_half(hb));
}

// ---------------- CSR gather, fp8 source (128), half2 accum, 8-deep ----------
__global__ void __launch_bounds__(256)
k_gather8(const int* __restrict__ rowPtr, const unsigned* __restrict__ ePack,
          const uint8_t* __restrict__ h8, const float* __restrict__ dinv2,
          const float* __restrict__ bias, __half* __restrict__ outH) {
    const int lane = threadIdx.x & 31;
    const int warpId = (blockIdx.x * blockDim.x + threadIdx.x) >> 5;
    const int nWarps = (gridDim.x * blockDim.x) >> 5;

    float bl[4];
#pragma unroll
    for (int i = 0; i < 4; i++) bl[i] = bias[lane * 4 + i];

    for (int node = warpId; node < NN; node += nWarps) {
        const int beg = rowPtr[node];
        const int end = rowPtr[node + 1];

        __half2 acc0, acc1, acc2, acc3;
        {
            const float d2 = dinv2[node];
            const __half2 d2h = __float2half2_rn(d2);
            unsigned raw = *reinterpret_cast<const unsigned*>(
                h8 + (size_t)node * 128 + lane * 4);
            __half2_raw r0 = __nv_cvt_fp8x2_to_halfraw2(
                (unsigned short)(raw & 0xffff), __NV_E4M3);
            __half2_raw r1 = __nv_cvt_fp8x2_to_halfraw2(
                (unsigned short)(raw >> 16), __NV_E4M3);
            acc0 = __hmul2(*reinterpret_cast<__half2*>(&r0), d2h);
            acc1 = __hmul2(*reinterpret_cast<__half2*>(&r1), d2h);
            acc2 = __floats2half2_rn(0.0f, 0.0f);
            acc3 = acc2;
        }

        for (int base = beg; base < end; base += 32) {
            const int cnt = min(32, end - base);
            unsigned e = (lane < cnt) ? ePack[base + lane] : 0u;
            int j = 0;
            for (; j + 7 < cnt; j += 8) {
                unsigned v[8]; unsigned raw[8];
#pragma unroll
                for (int q = 0; q < 8; q++)
                    v[q] = __shfl_sync(0xffffffffu, e, j + q);
#pragma unroll
                for (int q = 0; q < 8; q++)
                    raw[q] = *reinterpret_cast<const unsigned*>(
                        h8 + (size_t)edge_src(v[q]) * 128 + lane * 4);
#pragma unroll
                for (int q = 0; q < 8; q++) {
                    __half2 nm = edge_norm_h2(v[q]);
                    __half2_raw r0 = __nv_cvt_fp8x2_to_halfraw2(
                        (unsigned short)(raw[q] & 0xffff), __NV_E4M3);
                    __half2_raw r1 = __nv_cvt_fp8x2_to_halfraw2(
                        (unsigned short)(raw[q] >> 16), __NV_E4M3);
                    if (q & 1) {
                        acc2 = __hfma2(*reinterpret_cast<__half2*>(&r0), nm, acc2);
                        acc3 = __hfma2(*reinterpret_cast<__half2*>(&r1), nm, acc3);
                    } else {
                        acc0 = __hfma2(*reinterpret_cast<__half2*>(&r0), nm, acc0);
                        acc1 = __hfma2(*reinterpret_cast<__half2*>(&r1), nm, acc1);
                    }
                }
            }
            for (; j < cnt; j++) {
                unsigned v = __shfl_sync(0xffffffffu, e, j);
                unsigned raw = *reinterpret_cast<const unsigned*>(
                    h8 + (size_t)edge_src(v) * 128 + lane * 4);
                __half2 nm = edge_norm_h2(v);
                __half2_raw r0 = __nv_cvt_fp8x2_to_halfraw2(
                    (unsigned short)(raw & 0xffff), __NV_E4M3);
                __half2_raw r1 = __nv_cvt_fp8x2_to_halfraw2(
                    (unsigned short)(raw >> 16), __NV_E4M3);
                acc0 = __hfma2(*reinterpret_cast<__half2*>(&r0), nm, acc0);
                acc1 = __hfma2(*reinterpret_cast<__half2*>(&r1), nm, acc1);
            }
        }
        acc0 = __hadd2(acc0, acc2);
        acc1 = __hadd2(acc1, acc3);

        float a0 = fmaxf(__low2float(acc0)  + bl[0], 0.0f);
        float a1 = fmaxf(__high2float(acc0) + bl[1], 0.0f);
        float a2 = fmaxf(__low2float(acc1)  + bl[2], 0.0f);
        float a3 = fmaxf(__high2float(acc1) + bl[3], 0.0f);
        __half2 p0 = __floats2half2_rn(a0, a1);
        __half2 p1 = __floats2half2_rn(a2, a3);
        uint2 raw;
        raw.x = *reinterpret_cast<unsigned*>(&p0);
        raw.y = *reinterpret_cast<unsigned*>(&p1);
        *reinterpret_cast<uint2*>(outH + (size_t)node * 128 + lane * 4) = raw;
    }
}

// ---------------- CSR gather, fp16 src (64) -> fp16 (+b3), 8-deep ------------
__global__ void __launch_bounds__(256)
k_gather64h(const int* __restrict__ rowPtr, const unsigned* __restrict__ ePack,
            const __half* __restrict__ h, const float* __restrict__ dinv2,
            const float* __restrict__ b3, __half* __restrict__ outH) {
    const int lane = threadIdx.x & 31;
    const int warpId = (blockIdx.x * blockDim.x + threadIdx.x) >> 5;
    const int nWarps = (gridDim.x * blockDim.x) >> 5;

    const float b0 = b3[lane * 2];
    const float b1v = b3[lane * 2 + 1];

    for (int node = warpId; node < NN; node += nWarps) {
        const int beg = rowPtr[node];
        const int end = rowPtr[node + 1];

        float acc0, acc1, acc2 = 0.0f, acc3 = 0.0f;
        {
            const float d2 = dinv2[node];
            unsigned raw = *reinterpret_cast<const unsigned*>(
                h + (size_t)node * 64 + lane * 2);
            __half2 a = *reinterpret_cast<__half2*>(&raw);
            acc0 = __low2float(a) * d2;  acc1 = __high2float(a) * d2;
        }

        for (int base = beg; base < end; base += 32) {
            const int cnt = min(32, end - base);
            unsigned e = (lane < cnt) ? ePack[base + lane] : 0u;
            int j = 0;
            for (; j + 7 < cnt; j += 8) {
                unsigned v[8]; unsigned raw[8];
#pragma unroll
                for (int q = 0; q < 8; q++)
                    v[q] = __shfl_sync(0xffffffffu, e, j + q);
#pragma unroll
                for (int q = 0; q < 8; q++)
                    raw[q] = *reinterpret_cast<const unsigned*>(
                        h + (size_t)edge_src(v[q]) * 64 + lane * 2);
#pragma unroll
                for (int q = 0; q < 8; q++) {
                    float nm = edge_norm_f(v[q]);
                    __half2 a = *reinterpret_cast<__half2*>(&raw[q]);
                    if (q & 1) {
                        acc2 = fmaf(__low2float(a),  nm, acc2);
                        acc3 = fmaf(__high2float(a), nm, acc3);
                    } else {
                        acc0 = fmaf(__low2float(a),  nm, acc0);
                        acc1 = fmaf(__high2float(a), nm, acc1);
                    }
                }
            }
            for (; j < cnt; j++) {
                unsigned v = __shfl_sync(0xffffffffu, e, j);
                unsigned raw = *reinterpret_cast<const unsigned*>(
                    h + (size_t)edge_src(v) * 64 + lane * 2);
                float nm = edge_norm_f(v);
                __half2 a = *reinterpret_cast<__half2*>(&raw);
                acc0 = fmaf(__low2float(a),  nm, acc0);
                acc1 = fmaf(__high2float(a), nm, acc1);
            }
        }
        acc0 += acc2;  acc1 += acc3;

        __half2 p = __floats2half2_rn(acc0 + b0, acc1 + b1v);
        *reinterpret_cast<unsigned*>(outH + (size_t)node * 64 + lane * 2) =
            *reinterpret_cast<unsigned*>(&p);
    }
}

// ---------------- fused heads: 6 GEMMs + softmax in one kernel ---------------
// smem half offsets
constexpr int H_WA1 = 0;               // 64*128
constexpr int H_WC1 = 8192;            // 64*128
constexpr int H_WA2 = 16384;           // 128*64
constexpr int H_WC2 = 24576;           // 128*64
constexpr int H_W3A = 32768;           // 64*16 (Wa3 zero-padded)
constexpr int H_W3C = 33792;           // 64*16 (Wc3 in col 0)
constexpr int H_BA1 = 34816;           // 128
constexpr int H_BC1 = 34944;           // 128
constexpr int H_BA2 = 35072;           // 64
constexpr int H_BC2 = 35136;           // 64
constexpr int H_F32 = 35200;           // 12 floats (ba3[8], bc3, pad) = 24 halves
constexpr int H_STG = 35264;           // per-warp stages: 8 * 3584
constexpr int HPW   = 3584;            // stageA 2048 + stageB 1024 + stageC 512(=256 f32)
constexpr int H_TOT = H_STG + 8 * HPW; // 63936 halves = 127872 B

__global__ void __launch_bounds__(256)
k_heads_fused(const __half* __restrict__ HF,
              const float* __restrict__ Wa1, const float* __restrict__ ba1,
              const float* __restrict__ Wa2, const float* __restrict__ ba2,
              const float* __restrict__ Wa3, const float* __restrict__ ba3,
              const float* __restrict__ Wc1, const float* __restrict__ bc1,
              const float* __restrict__ Wc2, const float* __restrict__ bc2,
              const float* __restrict__ Wc3, const float* __restrict__ bc3,
              float* __restrict__ out) {
    extern __shared__ __half sm[];
    const int tid = threadIdx.x;
    for (int i = tid; i < 8192; i += 256) {
        sm[H_WA1 + i] = __float2half(Wa1[i]);
        sm[H_WC1 + i] = __float2half(Wc1[i]);
        sm[H_WA2 + i] = __float2half(Wa2[i]);
        sm[H_WC2 + i] = __float2half(Wc2[i]);
    }
    for (int i = tid; i < 1024; i += 256) {
        int k = i >> 4, c = i & 15;
        sm[H_W3A + i] = (c < 8) ? __float2half(Wa3[k * 8 + c]) : __float2half(0.0f);
        sm[H_W3C + i] = (c == 0) ? __float2half(Wc3[k]) : __float2half(0.0f);
    }
    if (tid < 128) {
        sm[H_BA1 + tid] = __float2half(ba1[tid]);
        sm[H_BC1 + tid] = __float2half(bc1[tid]);
    }
    if (tid < 64) {
        sm[H_BA2 + tid] = __float2half(ba2[tid]);
        sm[H_BC2 + tid] = __float2half(bc2[tid]);
    }
    float* sF = (float*)(sm + H_F32);
    if (tid < 8) sF[tid] = ba3[tid];
    if (tid == 8) sF[8] = bc3[0];
    __syncthreads();

    constexpr int TILES = NN / 16;
    const int warpId = tid >> 5;
    const int lane = tid & 31;
    __half* stageA = sm + H_STG + warpId * HPW;          // 16x128
    __half* stageB = stageA + 2048;                      // 16x64
    float*  stageC = (float*)(stageB + 1024);            // 16x16 f32
    const int warpsTotal = (gridDim.x * 256) >> 5;
    const __half2 zero2 = __floats2half2_rn(0.0f, 0.0f);

    for (int tile = blockIdx.x * 8 + warpId; tile < TILES; tile += warpsTotal) {
        const int row0 = tile * 16;

        // load HF a-frags once, reused by actor and critic
        wmma::fragment<wmma::matrix_a, 16, 16, 16, __half, wmma::row_major> af[4];
#pragma unroll
        for (int k = 0; k < 4; k++)
            wmma::load_matrix_sync(af[k], HF + (size_t)row0 * 64 + k * 16, 64);

        float lg[8];
        float val = 0.0f;

#pragma unroll
        for (int path = 0; path < 2; path++) {
            const __half* W1p = sm + (path == 0 ? H_WA1 : H_WC1);
            const __half* W2p = sm + (path == 0 ? H_WA2 : H_WC2);
            const __half* W3p = sm + (path == 0 ? H_W3A : H_W3C);
            const __half* B1p = sm + (path == 0 ? H_BA1 : H_BC1);
            const __half* B2p = sm + (path == 0 ? H_BA2 : H_BC2);

            // stage1: 64 -> 128
            {
                wmma::fragment<wmma::accumulator, 16, 16, 16, __half> acc[8];
#pragma unroll
                for (int c = 0; c < 8; c++)
                    wmma::fill_fragment(acc[c], __float2half(0.0f));
#pragma unroll
                for (int k = 0; k < 4; k++) {
#pragma unroll
                    for (int c = 0; c < 8; c++) {
                        wmma::fragment<wmma::matrix_b, 16, 16, 16, __half,
                                       wmma::row_major> b;
                        wmma::load_matrix_sync(b, W1p + k * 16 * 128 + c * 16, 128);
                        wmma::mma_sync(acc[c], af[k], b, acc[c]);
                    }
                }
#pragma unroll
                for (int c = 0; c < 8; c++)
                    wmma::store_matrix_sync(stageA + c * 16, acc[c], 128,
                                            wmma::mem_row_major);
            }
            __syncwarp();
            // bias + relu stageA (lane: half a row = 64 halves)
            {
                const int r = lane >> 1;
                const int off = (lane & 1) * 64;
                __half2* p = (__half2*)(stageA + r * 128 + off);
                const __half2* b2 = (const __half2*)(B1p + off);
#pragma unroll
                for (int i = 0; i < 32; i++)
                    p[i] = __hmax2(__hadd2(p[i], b2[i]), zero2);
            }
            __syncwarp();

            // stage2: 128 -> 64
            {
                wmma::fragment<wmma::accumulator, 16, 16, 16, __half> acc[4];
#pragma unroll
                for (int c = 0; c < 4; c++)
                    wmma::fill_fragment(acc[c], __float2half(0.0f));
#pragma unroll
                for (int k = 0; k < 8; k++) {
                    wmma::fragment<wmma::matrix_a, 16, 16, 16, __half,
                                   wmma::row_major> a;
                    wmma::load_matrix_sync(a, stageA + k * 16, 128);
#pragma unroll
                    for (int c = 0; c < 4; c++) {
                        wmma::fragment<wmma::matrix_b, 16, 16, 16, __half,
                                       wmma::row_major> b;
                        wmma::load_matrix_sync(b, W2p + k * 16 * 64 + c * 16, 64);
                        wmma::mma_sync(acc[c], a, b, acc[c]);
                    }
                }
#pragma unroll
                for (int c = 0; c < 4; c++)
                    wmma::store_matrix_sync(stageB + c * 16, acc[c], 64,
                                            wmma::mem_row_major);
            }
            __syncwarp();
            // bias + relu stageB (lane: 32 halves)
            {
                const int r = lane >> 1;
                const int off = (lane & 1) * 32;
                __half2* p = (__half2*)(stageB + r * 64 + off);
                const __half2* b2 = (const __half2*)(B2p + off);
#pragma unroll
                for (int i = 0; i < 16; i++)
                    p[i] = __hmax2(__hadd2(p[i], b2[i]), zero2);
            }
            __syncwarp();

            // stage3: 64 -> 16 (fp32 accum)
            {
                wmma::fragment<wmma::accumulator, 16, 16, 16, float> accf;
                wmma::fill_fragment(accf, 0.0f);
#pragma unroll
                for (int k = 0; k < 4; k++) {
                    wmma::fragment<wmma::matrix_a, 16, 16, 16, __half,
                                   wmma::row_major> a;
                    wmma::load_matrix_sync(a, stageB + k * 16, 64);
                    wmma::fragment<wmma::matrix_b, 16, 16, 16, __half,
                                   wmma::row_major> b;
                    wmma::load_matrix_sync(b, W3p + k * 16 * 16, 16);
                    wmma::mma_sync(accf, a, b, accf);
                }
                wmma::store_matrix_sync(stageC, accf, 16, wmma::mem_row_major);
            }
            __syncwarp();

            if (path == 0) {
                if (lane < 16) {
#pragma unroll
                    for (int a = 0; a < 8; a++)
                        lg[a] = stageC[lane * 16 + a] + sF[a];
                }
            } else {
                if (lane < 16)
                    val = stageC[lane * 16] + sF[8];
            }
            __syncwarp();
        }

        // softmax + write
        if (lane < 16) {
            float mx = -1e30f;
#pragma unroll
            for (int a = 0; a < 8; a++) mx = fmaxf(mx, lg[a]);
            float e[8], ssum = 0.0f;
#pragma unroll
            for (int a = 0; a < 8; a++) { e[a] = expf(lg[a] - mx); ssum += e[a]; }
            float inv = 1.0f / ssum;
            size_t o = (size_t)(row0 + lane) * 9;
#pragma unroll
            for (int a = 0; a < 8; a++) out[o + a] = e[a] * inv;
            out[o + 8] = val;
        }
        __syncwarp();
    }
}

// ---------------- launch -----------------------------------------------------
extern "C" void kernel_launch(void* const* d_in, const int* in_sizes, int n_in,
                              void* d_out, int out_size) {
    const float* x   = (const float*)d_in[0];
    const int*   eiw = (const int*)d_in[1];
    const float* W1 = (const float*)d_in[2];  const float* b1 = (const float*)d_in[3];
    const float* W2 = (const float*)d_in[4];  const float* b2 = (const float*)d_in[5];
    const float* W3 = (const float*)d_in[6];  const float* b3 = (const float*)d_in[7];
    const float* Wa1 = (const float*)d_in[8];  const float* ba1 = (const float*)d_in[9];
    const float* Wa2 = (const float*)d_in[10]; const float* ba2 = (const float*)d_in[11];
    const float* Wa3 = (const float*)d_in[12]; const float* ba3 = (const float*)d_in[13];
    const float* Wc1 = (const float*)d_in[14]; const float* bc1 = (const float*)d_in[15];
    const float* Wc2 = (const float*)d_in[16]; const float* bc2 = (const float*)d_in[17];
    const float* Wc3 = (const float*)d_in[18]; const float* bc3 = (const float*)d_in[19];
    float* out = (float*)d_out;

    void *ph, *ph8, *pact, *phd, *pdinv, *pdinv2, *pcnt, *prow, *pcur, *pep, *pcs, *pco;
    cudaGetSymbolAddress(&ph, g_h);
    cudaGetSymbolAddress(&ph8, g_h8);
    cudaGetSymbolAddress(&pact, g_act);
    cudaGetSymbolAddress(&phd, g_hd);
    cudaGetSymbolAddress(&pdinv, g_dinv);
    cudaGetSymbolAddress(&pdinv2, g_dinv2);
    cudaGetSymbolAddress(&pcnt, g_cnt);
    cudaGetSymbolAddress(&prow, g_rowPtr);
    cudaGetSymbolAddress(&pcur, g_cur);
    cudaGetSymbolAddress(&pep, g_ePack);
    cudaGetSymbolAddress(&pcs, g_chunkSum);
    cudaGetSymbolAddress(&pco, g_chunkOff);
    __half* H = (__half*)ph;  uint8_t* H8 = (uint8_t*)ph8;
    __half* ACT = (__half*)pact;
    __half* HF = (__half*)phd;
    float* dinv = (float*)pdinv;  float* dinv2 = (float*)pdinv2;
    int* cnt = (int*)pcnt;  int* rowPtr = (int*)prow;  int* cur = (int*)pcur;
    unsigned* ePack = (unsigned*)pep;
    int* chunkSum = (int*)pcs;  int* chunkOff = (int*)pco;

    const int SM_G8 = (128 * 128 + 8 * 16 * 128) * 2;   // 65536
    const int SM_W2 = 128 * 64 * 2;                     // 16384
    const int SM_HF = H_TOT * 2;                        // 127872

    cudaFuncSetAttribute(k_gemm_wmma8,
                         cudaFuncAttributeMaxDynamicSharedMemorySize, SM_G8);
    cudaFuncSetAttribute(k_gemm_wmma<128, 64>,
                         cudaFuncAttributeMaxDynamicSharedMemorySize, SM_W2);
    cudaFuncSetAttribute(k_heads_fused,
                         cudaFuncAttributeMaxDynamicSharedMemorySize, SM_HF);

    // ---- CSR build (once) ----
    k_init<<<(NN + 255) / 256, 256>>>(eiw, cnt);
    k_count<<<2048, 256>>>(eiw, cnt);
    k_chunk_sum<<<NCHUNK, 1024>>>(cnt, chunkSum);
    k_scan_part<<<1, 128>>>(chunkSum, chunkOff);
    k_scan_final<<<NCHUNK, 1024>>>(cnt, chunkOff, rowPtr, cur, dinv, dinv2);
    k_fill<<<2048, 256>>>(eiw, dinv, cur, ePack);

    // ---- x -> fp16 ----
    k_cvt<<<1184, 256>>>(x, ACT);

    // ---- layer 1 ----
    k_gemm_wmma8<<<391, 256, SM_G8>>>(ACT, W1, H8);
    k_gather8<<<1568, 256>>>(rowPtr, ePack, H8, dinv2, b1, ACT);

    // ---- layer 2 ----
    k_gemm_wmma8<<<391, 256, SM_G8>>>(ACT, W2, H8);
    k_gather8<<<1568, 256>>>(rowPtr, ePack, H8, dinv2, b2, ACT);

    // ---- layer 3 ----
    k_gemm_wmma<128, 64><<<391, 256, SM_W2>>>(ACT, W3, H);
    k_gather64h<<<1568, 256>>>(rowPtr, ePack, H, dinv2, b3, HF);

    // ---- fused heads + softmax -> out ----
    k_heads_fused<<<296, 256, SM_HF>>>(HF,
                                       Wa1, ba1, Wa2, ba2, Wa3, ba3,
                                       Wc1, bc1, Wc2, bc2, Wc3, bc3, out);
}

// round 12
// speedup vs baseline: 4.8600x; 1.0433x over previous
#include <cuda_runtime.h>
#include <cuda_fp16.h>
#include <cuda_fp8.h>
#include <mma.h>
#include <cstddef>
#include <cstdint>

using namespace nvcuda;

#define NN 100000
#define NE 3200000
#define NCHUNK ((NN + 1023) / 1024)   // 98

// ---------------- scratch (module-load allocated, no runtime alloc) ----------
__device__ __align__(16) __half g_h[(size_t)NN * 128];    // GEMM out L3
__device__ __align__(16) uint8_t g_h8[(size_t)NN * 128];  // fp8 GEMM out
__device__ __align__(16) __half g_act[(size_t)NN * 128];  // GEMM input
__device__ __align__(16) __half g_hd[(size_t)NN * 64];    // Hfinal
__device__ float g_dinv[NN];
__device__ float g_dinv2[NN];
__device__ int g_cnt[NN];
__device__ int g_rowPtr[NN + 1];
__device__ int g_cur[NN];
__device__ __align__(16) unsigned g_ePack[NE];  // (fp16 norm bits)<<17 | src
__device__ int g_chunkSum[NCHUNK];
__device__ int g_chunkOff[NCHUNK + 1];
__device__ int g_is64;

// ---------------- fork/join stream (host-side, created at load time) ---------
struct ForkCtx {
    cudaStream_t s1;
    cudaEvent_t evFork, evJoin;
    ForkCtx() {
        cudaStreamCreateWithFlags(&s1, cudaStreamNonBlocking);
        cudaEventCreateWithFlags(&evFork, cudaEventDisableTiming);
        cudaEventCreateWithFlags(&evJoin, cudaEventDisableTiming);
    }
};
static ForkCtx g_fork;

// ---------------- init: zero counts + edge dtype probe -----------------------
__global__ void k_init(const int* __restrict__ w, int* __restrict__ cnt) {
    int i = blockIdx.x * blockDim.x + threadIdx.x;
    if (i < NN) cnt[i] = 0;
    if (i == 0) {
        int is64 = 1;
        for (int k = 0; k < 2048; k += 2) {
            if (w[k + 1] != 0) { is64 = 0; break; }
        }
        g_is64 = is64;
    }
}

__global__ void k_count(const int* __restrict__ w, int* __restrict__ cnt) {
    const int is64 = g_is64;
    long long i = (long long)blockIdx.x * blockDim.x + threadIdx.x;
    long long stride = (long long)gridDim.x * blockDim.x;
    if (is64) {
        for (; i < NE; i += stride)
            atomicAdd(&cnt[w[2 * (long long)NE + 2 * i]], 1);
    } else {
        for (; i < NE; i += stride)
            atomicAdd(&cnt[w[NE + i]], 1);
    }
}

// ---------------- parallel 3-phase prefix scan -------------------------------
__global__ void __launch_bounds__(1024)
k_chunk_sum(const int* __restrict__ cnt, int* __restrict__ chunkSum) {
    __shared__ int sred[32];
    const int tid = threadIdx.x;
    const int idx = blockIdx.x * 1024 + tid;
    int v = (idx < NN) ? cnt[idx] : 0;
    for (int o = 16; o > 0; o >>= 1) v += __shfl_down_sync(0xffffffffu, v, o);
    if ((tid & 31) == 0) sred[tid >> 5] = v;
    __syncthreads();
    if (tid < 32) {
        int x = sred[tid];
        for (int o = 16; o > 0; o >>= 1) x += __shfl_down_sync(0xffffffffu, x, o);
        if (tid == 0) chunkSum[blockIdx.x] = x;
    }
}

__global__ void __launch_bounds__(128)
k_scan_part(const int* __restrict__ chunkSum, int* __restrict__ chunkOff) {
    __shared__ int s[NCHUNK];
    const int tid = threadIdx.x;
    for (int i = tid; i < NCHUNK; i += 128) s[i] = chunkSum[i];
    __syncthreads();
    if (tid == 0) {
        int acc = 0;
        for (int i = 0; i < NCHUNK; i++) { int v = s[i]; s[i] = acc; acc += v; }
        chunkOff[NCHUNK] = acc;
    }
    __syncthreads();
    for (int i = tid; i < NCHUNK; i += 128) chunkOff[i] = s[i];
}

__global__ void __launch_bounds__(1024)
k_scan_final(const int* __restrict__ cnt, const int* __restrict__ chunkOff,
             int* __restrict__ rowPtr, int* __restrict__ cur,
             float* __restrict__ dinv, float* __restrict__ dinv2) {
    __shared__ int swarp[32];
    const int tid = threadIdx.x;
    const int idx = blockIdx.x * 1024 + tid;
    int v = (idx < NN) ? cnt[idx] : 0;

    int incl = v;
    for (int o = 1; o < 32; o <<= 1) {
        int t = __shfl_up_sync(0xffffffffu, incl, o);
        if ((tid & 31) >= o) incl += t;
    }
    if ((tid & 31) == 31) swarp[tid >> 5] = incl;
    __syncthreads();
    if (tid < 32) {
        int x = swarp[tid];
        for (int o = 1; o < 32; o <<= 1) {
            int t = __shfl_up_sync(0xffffffffu, x, o);
            if (tid >= o) x += t;
        }
        swarp[tid] = x;
    }
    __syncthreads();
    int warpBase = (tid >= 32) ? swarp[(tid >> 5) - 1] : 0;
    int inclTotal = incl + warpBase;

    if (idx < NN) {
        int start = chunkOff[blockIdx.x] + inclTotal - v;
        rowPtr[idx] = start;
        cur[idx] = start;
        float dv = rsqrtf((float)(v + 1));
        dinv[idx] = dv;
        dinv2[idx] = dv * dv;
    }
    if (blockIdx.x == gridDim.x - 1 && tid == 0)
        rowPtr[NN] = chunkOff[NCHUNK];
}

// fill CSR slots: pack = (fp16(norm) bits)<<17 | src
__global__ void k_fill(const int* __restrict__ w, const float* __restrict__ dinv,
                       int* __restrict__ cur, unsigned* __restrict__ ePack) {
    const int is64 = g_is64;
    long long i = (long long)blockIdx.x * blockDim.x + threadIdx.x;
    long long stride = (long long)gridDim.x * blockDim.x;
    for (; i < NE; i += stride) {
        int s, d;
        if (is64) { s = w[2 * i]; d = w[2 * (long long)NE + 2 * i]; }
        else      { s = w[i];     d = w[NE + i]; }
        int pos = atomicAdd(&cur[d], 1);
        unsigned nb = __half_as_ushort(__float2half_rn(dinv[s] * dinv[d]));
        ePack[pos] = (nb << 17) | (unsigned)s;
    }
}

// ---------------- x -> fp16 convert ------------------------------------------
__global__ void k_cvt(const float* __restrict__ x, __half* __restrict__ o) {
    long long i = (long long)blockIdx.x * blockDim.x + threadIdx.x;
    long long stride = (long long)gridDim.x * blockDim.x;
    const long long n4 = (long long)NN * 128 / 4;
    const float4* x4 = reinterpret_cast<const float4*>(x);
    for (; i < n4; i += stride) {
        float4 v = x4[i];
        __half2 p0 = __floats2half2_rn(v.x, v.y);
        __half2 p1 = __floats2half2_rn(v.z, v.w);
        uint2 raw;
        raw.x = *reinterpret_cast<unsigned*>(&p0);
        raw.y = *reinterpret_cast<unsigned*>(&p1);
        *reinterpret_cast<uint2*>(o + 4 * i) = raw;
    }
}

// ---------------- WMMA GEMM: out = in @ W  (fp16), fp8 e4m3 output -----------
__global__ void __launch_bounds__(256)
k_gemm_wmma8(const __half* __restrict__ in, const float* __restrict__ W,
             uint8_t* __restrict__ out8) {
    extern __shared__ __half smg[];
    __half* sW = smg;                         // 128*128
    __half* sStage = smg + 128 * 128;         // 8 * 16 * 128
    const int tid = threadIdx.x;
    for (int i = tid; i < 128 * 128; i += 256) sW[i] = __float2half(W[i]);
    __syncthreads();

    constexpr int TILES = NN / 16;
    const int warpId = tid >> 5;
    const int lane = tid & 31;
    __half* stage = sStage + warpId * 16 * 128;
    const int warpsTotal = (gridDim.x * 256) >> 5;

    for (int tile = blockIdx.x * 8 + warpId; tile < TILES; tile += warpsTotal) {
        const int row0 = tile * 16;
        wmma::fragment<wmma::accumulator, 16, 16, 16, __half> acc[8];
#pragma unroll
        for (int c = 0; c < 8; c++)
            wmma::fill_fragment(acc[c], __float2half(0.0f));

#pragma unroll
        for (int k = 0; k < 8; k++) {
            wmma::fragment<wmma::matrix_a, 16, 16, 16, __half, wmma::row_major> a;
            wmma::load_matrix_sync(a, in + (size_t)row0 * 128 + k * 16, 128);
#pragma unroll
            for (int c = 0; c < 8; c++) {
                wmma::fragment<wmma::matrix_b, 16, 16, 16, __half, wmma::row_major> b;
                wmma::load_matrix_sync(b, sW + k * 16 * 128 + c * 16, 128);
                wmma::mma_sync(acc[c], a, b, acc[c]);
            }
        }
#pragma unroll
        for (int c = 0; c < 8; c++)
            wmma::store_matrix_sync(stage + c * 16, acc[c], 128,
                                    wmma::mem_row_major);
        __syncwarp();

        {
            const int r = lane >> 1;
            const int hOff = (lane & 1) * 64;
            const __half2* src = (const __half2*)(stage + r * 128 + hOff);
            uint8_t* dst = out8 + (size_t)(row0 + r) * 128 + hOff;
#pragma unroll
            for (int g = 0; g < 4; g++) {
                unsigned short f[8];
#pragma unroll
                for (int p = 0; p < 8; p++) {
                    __half2 v = src[g * 8 + p];
                    __half2_raw vr = *reinterpret_cast<__half2_raw*>(&v);
                    f[p] = __nv_cvt_halfraw2_to_fp8x2(vr, __NV_SATFINITE, __NV_E4M3);
                }
                uint4 o;
                o.x = (unsigned)f[0] | ((unsigned)f[1] << 16);
                o.y = (unsigned)f[2] | ((unsigned)f[3] << 16);
                o.z = (unsigned)f[4] | ((unsigned)f[5] << 16);
                o.w = (unsigned)f[6] | ((unsigned)f[7] << 16);
                *reinterpret_cast<uint4*>(dst + g * 16) = o;
            }
        }
        __syncwarp();
    }
}

// ---------------- WMMA GEMM: fp16 out (layer 3) ------------------------------
template <int DIN, int DOUT>
__global__ void __launch_bounds__(256)
k_gemm_wmma(const __half* __restrict__ in, const float* __restrict__ W,
            __half* __restrict__ out) {
    extern __shared__ __half sW[];
    const int tid = threadIdx.x;
    for (int i = tid; i < DIN * DOUT; i += 256) sW[i] = __float2half(W[i]);
    __syncthreads();

    constexpr int TILES = NN / 16;
    const int warpId = tid >> 5;
    const int warpsTotal = (gridDim.x * 256) >> 5;

    for (int tile = blockIdx.x * 8 + warpId; tile < TILES; tile += warpsTotal) {
        const int row0 = tile * 16;
        wmma::fragment<wmma::accumulator, 16, 16, 16, __half> acc[DOUT / 16];
#pragma unroll
        for (int c = 0; c < DOUT / 16; c++)
            wmma::fill_fragment(acc[c], __float2half(0.0f));

#pragma unroll
        for (int k = 0; k < DIN / 16; k++) {
            wmma::fragment<wmma::matrix_a, 16, 16, 16, __half, wmma::row_major> a;
            wmma::load_matrix_sync(a, in + (size_t)row0 * DIN + k * 16, DIN);
#pragma unroll
            for (int c = 0; c < DOUT / 16; c++) {
                wmma::fragment<wmma::matrix_b, 16, 16, 16, __half, wmma::row_major> b;
                wmma::load_matrix_sync(b, sW + k * 16 * DOUT + c * 16, DOUT);
                wmma::mma_sync(acc[c], a, b, acc[c]);
            }
        }
#pragma unroll
        for (int c = 0; c < DOUT / 16; c++)
            wmma::store_matrix_sync(out + (size_t)row0 * DOUT + c * 16, acc[c],
                                    DOUT, wmma::mem_row_major);
    }
}

// ---------------- edge decode helpers ----------------------------------------
__device__ __forceinline__ int edge_src(unsigned v) { return (int)(v & 0x1FFFFu); }
__device__ __forceinline__ __half2 edge_norm_h2(unsigned v) {
    unsigned hb = v >> 17;
    unsigned pair = hb | (hb << 16);
    return *reinterpret_cast<__half2*>(&pair);
}
__device__ __forceinline__ float edge_norm_f(unsigned v) {
    unsigned short hb = (unsigned short)(v >> 17);
    return __half2float(__ushort_as_half(hb));
}

// ---------------- CSR gather, fp8 source (128), half2 accum, 8-deep ----------
__global__ void __launch_bounds__(256)
k_gather8(const int* __restrict__ rowPtr, const unsigned* __restrict__ ePack,
          const uint8_t* __restrict__ h8, const float* __restrict__ dinv2,
          const float* __restrict__ bias, __half* __restrict__ outH) {
    const int lane = threadIdx.x & 31;
    const int warpId = (blockIdx.x * blockDim.x + threadIdx.x) >> 5;
    const int nWarps = (gridDim.x * blockDim.x) >> 5;

    float bl[4];
#pragma unroll
    for (int i = 0; i < 4; i++) bl[i] = bias[lane * 4 + i];

    for (int node = warpId; node < NN; node += nWarps) {
        const int beg = rowPtr[node];
        const int end = rowPtr[node + 1];

        __half2 acc0, acc1, acc2, acc3;
        {
            const float d2 = dinv2[node];
            const __half2 d2h = __float2half2_rn(d2);
            unsigned raw = *reinterpret_cast<const unsigned*>(
                h8 + (size_t)node * 128 + lane * 4);
            __half2_raw r0 = __nv_cvt_fp8x2_to_halfraw2(
                (unsigned short)(raw & 0xffff), __NV_E4M3);
            __half2_raw r1 = __nv_cvt_fp8x2_to_halfraw2(
                (unsigned short)(raw >> 16), __NV_E4M3);
            acc0 = __hmul2(*reinterpret_cast<__half2*>(&r0), d2h);
            acc1 = __hmul2(*reinterpret_cast<__half2*>(&r1), d2h);
            acc2 = __floats2half2_rn(0.0f, 0.0f);
            acc3 = acc2;
        }

        for (int base = beg; base < end; base += 32) {
            const int cnt = min(32, end - base);
            unsigned e = (lane < cnt) ? ePack[base + lane] : 0u;
            int j = 0;
            for (; j + 7 < cnt; j += 8) {
                unsigned v[8]; unsigned raw[8];
#pragma unroll
                for (int q = 0; q < 8; q++)
                    v[q] = __shfl_sync(0xffffffffu, e, j + q);
#pragma unroll
                for (int q = 0; q < 8; q++)
                    raw[q] = *reinterpret_cast<const unsigned*>(
                        h8 + (size_t)edge_src(v[q]) * 128 + lane * 4);
#pragma unroll
                for (int q = 0; q < 8; q++) {
                    __half2 nm = edge_norm_h2(v[q]);
                    __half2_raw r0 = __nv_cvt_fp8x2_to_halfraw2(
                        (unsigned short)(raw[q] & 0xffff), __NV_E4M3);
                    __half2_raw r1 = __nv_cvt_fp8x2_to_halfraw2(
                        (unsigned short)(raw[q] >> 16), __NV_E4M3);
                    if (q & 1) {
                        acc2 = __hfma2(*reinterpret_cast<__half2*>(&r0), nm, acc2);
                        acc3 = __hfma2(*reinterpret_cast<__half2*>(&r1), nm, acc3);
                    } else {
                        acc0 = __hfma2(*reinterpret_cast<__half2*>(&r0), nm, acc0);
                        acc1 = __hfma2(*reinterpret_cast<__half2*>(&r1), nm, acc1);
                    }
                }
            }
            for (; j < cnt; j++) {
                unsigned v = __shfl_sync(0xffffffffu, e, j);
                unsigned raw = *reinterpret_cast<const unsigned*>(
                    h8 + (size_t)edge_src(v) * 128 + lane * 4);
                __half2 nm = edge_norm_h2(v);
                __half2_raw r0 = __nv_cvt_fp8x2_to_halfraw2(
                    (unsigned short)(raw & 0xffff), __NV_E4M3);
                __half2_raw r1 = __nv_cvt_fp8x2_to_halfraw2(
                    (unsigned short)(raw >> 16), __NV_E4M3);
                acc0 = __hfma2(*reinterpret_cast<__half2*>(&r0), nm, acc0);
                acc1 = __hfma2(*reinterpret_cast<__half2*>(&r1), nm, acc1);
            }
        }
        acc0 = __hadd2(acc0, acc2);
        acc1 = __hadd2(acc1, acc3);

        float a0 = fmaxf(__low2float(acc0)  + bl[0], 0.0f);
        float a1 = fmaxf(__high2float(acc0) + bl[1], 0.0f);
        float a2 = fmaxf(__low2float(acc1)  + bl[2], 0.0f);
        float a3 = fmaxf(__high2float(acc1) + bl[3], 0.0f);
        __half2 p0 = __floats2half2_rn(a0, a1);
        __half2 p1 = __floats2half2_rn(a2, a3);
        uint2 raw;
        raw.x = *reinterpret_cast<unsigned*>(&p0);
        raw.y = *reinterpret_cast<unsigned*>(&p1);
        *reinterpret_cast<uint2*>(outH + (size_t)node * 128 + lane * 4) = raw;
    }
}

// ---------------- CSR gather, fp16 src (64) -> fp16 (+b3), 8-deep ------------
__global__ void __launch_bounds__(256)
k_gather64h(const int* __restrict__ rowPtr, const unsigned* __restrict__ ePack,
            const __half* __restrict__ h, const float* __restrict__ dinv2,
            const float* __restrict__ b3, __half* __restrict__ outH) {
    const int lane = threadIdx.x & 31;
    const int warpId = (blockIdx.x * blockDim.x + threadIdx.x) >> 5;
    const int nWarps = (gridDim.x * blockDim.x) >> 5;

    const float b0 = b3[lane * 2];
    const float b1v = b3[lane * 2 + 1];

    for (int node = warpId; node < NN; node += nWarps) {
        const int beg = rowPtr[node];
        const int end = rowPtr[node + 1];

        float acc0, acc1, acc2 = 0.0f, acc3 = 0.0f;
        {
            const float d2 = dinv2[node];
            unsigned raw = *reinterpret_cast<const unsigned*>(
                h + (size_t)node * 64 + lane * 2);
            __half2 a = *reinterpret_cast<__half2*>(&raw);
            acc0 = __low2float(a) * d2;  acc1 = __high2float(a) * d2;
        }

        for (int base = beg; base < end; base += 32) {
            const int cnt = min(32, end - base);
            unsigned e = (lane < cnt) ? ePack[base + lane] : 0u;
            int j = 0;
            for (; j + 7 < cnt; j += 8) {
                unsigned v[8]; unsigned raw[8];
#pragma unroll
                for (int q = 0; q < 8; q++)
                    v[q] = __shfl_sync(0xffffffffu, e, j + q);
#pragma unroll
                for (int q = 0; q < 8; q++)
                    raw[q] = *reinterpret_cast<const unsigned*>(
                        h + (size_t)edge_src(v[q]) * 64 + lane * 2);
#pragma unroll
                for (int q = 0; q < 8; q++) {
                    float nm = edge_norm_f(v[q]);
                    __half2 a = *reinterpret_cast<__half2*>(&raw[q]);
                    if (q & 1) {
                        acc2 = fmaf(__low2float(a),  nm, acc2);
                        acc3 = fmaf(__high2float(a), nm, acc3);
                    } else {
                        acc0 = fmaf(__low2float(a),  nm, acc0);
                        acc1 = fmaf(__high2float(a), nm, acc1);
                    }
                }
            }
            for (; j < cnt; j++) {
                unsigned v = __shfl_sync(0xffffffffu, e, j);
                unsigned raw = *reinterpret_cast<const unsigned*>(
                    h + (size_t)edge_src(v) * 64 + lane * 2);
                float nm = edge_norm_f(v);
                __half2 a = *reinterpret_cast<__half2*>(&raw);
                acc0 = fmaf(__low2float(a),  nm, acc0);
                acc1 = fmaf(__high2float(a), nm, acc1);
            }
        }
        acc0 += acc2;  acc1 += acc3;

        __half2 p = __floats2half2_rn(acc0 + b0, acc1 + b1v);
        *reinterpret_cast<unsigned*>(outH + (size_t)node * 64 + lane * 2) =
            *reinterpret_cast<unsigned*>(&p);
    }
}

// ---------------- fused heads: 6 GEMMs + softmax in one kernel ---------------
constexpr int H_WA1 = 0;               // 64*128
constexpr int H_WC1 = 8192;            // 64*128
constexpr int H_WA2 = 16384;           // 128*64
constexpr int H_WC2 = 24576;           // 128*64
constexpr int H_W3A = 32768;           // 64*16 (Wa3 zero-padded)
constexpr int H_W3C = 33792;           // 64*16 (Wc3 in col 0)
constexpr int H_BA1 = 34816;           // 128
constexpr int H_BC1 = 34944;           // 128
constexpr int H_BA2 = 35072;           // 64
constexpr int H_BC2 = 35136;           // 64
constexpr int H_F32 = 35200;           // 12 floats = 24 halves
constexpr int H_STG = 35264;
constexpr int HPW   = 3584;
constexpr int H_TOT = H_STG + 8 * HPW; // 63936 halves = 127872 B

__global__ void __launch_bounds__(256)
k_heads_fused(const __half* __restrict__ HF,
              const float* __restrict__ Wa1, const float* __restrict__ ba1,
              const float* __restrict__ Wa2, const float* __restrict__ ba2,
              const float* __restrict__ Wa3, const float* __restrict__ ba3,
              const float* __restrict__ Wc1, const float* __restrict__ bc1,
              const float* __restrict__ Wc2, const float* __restrict__ bc2,
              const float* __restrict__ Wc3, const float* __restrict__ bc3,
              float* __restrict__ out) {
    extern __shared__ __half sm[];
    const int tid = threadIdx.x;
    for (int i = tid; i < 8192; i += 256) {
        sm[H_WA1 + i] = __float2half(Wa1[i]);
        sm[H_WC1 + i] = __float2half(Wc1[i]);
        sm[H_WA2 + i] = __float2half(Wa2[i]);
        sm[H_WC2 + i] = __float2half(Wc2[i]);
    }
    for (int i = tid; i < 1024; i += 256) {
        int k = i >> 4, c = i & 15;
        sm[H_W3A + i] = (c < 8) ? __float2half(Wa3[k * 8 + c]) : __float2half(0.0f);
        sm[H_W3C + i] = (c == 0) ? __float2half(Wc3[k]) : __float2half(0.0f);
    }
    if (tid < 128) {
        sm[H_BA1 + tid] = __float2half(ba1[tid]);
        sm[H_BC1 + tid] = __float2half(bc1[tid]);
    }
    if (tid < 64) {
        sm[H_BA2 + tid] = __float2half(ba2[tid]);
        sm[H_BC2 + tid] = __float2half(bc2[tid]);
    }
    float* sF = (float*)(sm + H_F32);
    if (tid < 8) sF[tid] = ba3[tid];
    if (tid == 8) sF[8] = bc3[0];
    __syncthreads();

    constexpr int TILES = NN / 16;
    const int warpId = tid >> 5;
    const int lane = tid & 31;
    __half* stageA = sm + H_STG + warpId * HPW;
    __half* stageB = stageA + 2048;
    float*  stageC = (float*)(stageB + 1024);
    const int warpsTotal = (gridDim.x * 256) >> 5;
    const __half2 zero2 = __floats2half2_rn(0.0f, 0.0f);

    for (int tile = blockIdx.x * 8 + warpId; tile < TILES; tile += warpsTotal) {
        const int row0 = tile * 16;

        wmma::fragment<wmma::matrix_a, 16, 16, 16, __half, wmma::row_major> af[4];
#pragma unroll
        for (int k = 0; k < 4; k++)
            wmma::load_matrix_sync(af[k], HF + (size_t)row0 * 64 + k * 16, 64);

        float lg[8];
        float val = 0.0f;

#pragma unroll
        for (int path = 0; path < 2; path++) {
            const __half* W1p = sm + (path == 0 ? H_WA1 : H_WC1);
            const __half* W2p = sm + (path == 0 ? H_WA2 : H_WC2);
            const __half* W3p = sm + (path == 0 ? H_W3A : H_W3C);
            const __half* B1p = sm + (path == 0 ? H_BA1 : H_BC1);
            const __half* B2p = sm + (path == 0 ? H_BA2 : H_BC2);

            {
                wmma::fragment<wmma::accumulator, 16, 16, 16, __half> acc[8];
#pragma unroll
                for (int c = 0; c < 8; c++)
                    wmma::fill_fragment(acc[c], __float2half(0.0f));
#pragma unroll
                for (int k = 0; k < 4; k++) {
#pragma unroll
                    for (int c = 0; c < 8; c++) {
                        wmma::fragment<wmma::matrix_b, 16, 16, 16, __half,
                                       wmma::row_major> b;
                        wmma::load_matrix_sync(b, W1p + k * 16 * 128 + c * 16, 128);
                        wmma::mma_sync(acc[c], af[k], b, acc[c]);
                    }
                }
#pragma unroll
                for (int c = 0; c < 8; c++)
                    wmma::store_matrix_sync(stageA + c * 16, acc[c], 128,
                                            wmma::mem_row_major);
            }
            __syncwarp();
            {
                const int r = lane >> 1;
                const int off = (lane & 1) * 64;
                __half2* p = (__half2*)(stageA + r * 128 + off);
                const __half2* b2 = (const __half2*)(B1p + off);
#pragma unroll
                for (int i = 0; i < 32; i++)
                    p[i] = __hmax2(__hadd2(p[i], b2[i]), zero2);
            }
            __syncwarp();

            {
                wmma::fragment<wmma::accumulator, 16, 16, 16, __half> acc[4];
#pragma unroll
                for (int c = 0; c < 4; c++)
                    wmma::fill_fragment(acc[c], __float2half(0.0f));
#pragma unroll
                for (int k = 0; k < 8; k++) {
                    wmma::fragment<wmma::matrix_a, 16, 16, 16, __half,
                                   wmma::row_major> a;
                    wmma::load_matrix_sync(a, stageA + k * 16, 128);
#pragma unroll
                    for (int c = 0; c < 4; c++) {
                        wmma::fragment<wmma::matrix_b, 16, 16, 16, __half,
                                       wmma::row_major> b;
                        wmma::load_matrix_sync(b, W2p + k * 16 * 64 + c * 16, 64);
                        wmma::mma_sync(acc[c], a, b, acc[c]);
                    }
                }
#pragma unroll
                for (int c = 0; c < 4; c++)
                    wmma::store_matrix_sync(stageB + c * 16, acc[c], 64,
                                            wmma::mem_row_major);
            }
            __syncwarp();
            {
                const int r = lane >> 1;
                const int off = (lane & 1) * 32;
                __half2* p = (__half2*)(stageB + r * 64 + off);
                const __half2* b2 = (const __half2*)(B2p + off);
#pragma unroll
                for (int i = 0; i < 16; i++)
                    p[i] = __hmax2(__hadd2(p[i], b2[i]), zero2);
            }
            __syncwarp();

            {
                wmma::fragment<wmma::accumulator, 16, 16, 16, float> accf;
                wmma::fill_fragment(accf, 0.0f);
#pragma unroll
                for (int k = 0; k < 4; k++) {
                    wmma::fragment<wmma::matrix_a, 16, 16, 16, __half,
                                   wmma::row_major> a;
                    wmma::load_matrix_sync(a, stageB + k * 16, 64);
                    wmma::fragment<wmma::matrix_b, 16, 16, 16, __half,
                                   wmma::row_major> b;
                    wmma::load_matrix_sync(b, W3p + k * 16 * 16, 16);
                    wmma::mma_sync(accf, a, b, accf);
                }
                wmma::store_matrix_sync(stageC, accf, 16, wmma::mem_row_major);
            }
            __syncwarp();

            if (path == 0) {
                if (lane < 16) {
#pragma unroll
                    for (int a = 0; a < 8; a++)
                        lg[a] = stageC[lane * 16 + a] + sF[a];
                }
            } else {
                if (lane < 16)
                    val = stageC[lane * 16] + sF[8];
            }
            __syncwarp();
        }

        if (lane < 16) {
            float mx = -1e30f;
#pragma unroll
            for (int a = 0; a < 8; a++) mx = fmaxf(mx, lg[a]);
            float e[8], ssum = 0.0f;
#pragma unroll
            for (int a = 0; a < 8; a++) { e[a] = expf(lg[a] - mx); ssum += e[a]; }
            float inv = 1.0f / ssum;
            size_t o = (size_t)(row0 + lane) * 9;
#pragma unroll
            for (int a = 0; a < 8; a++) out[o + a] = e[a] * inv;
            out[o + 8] = val;
        }
        __syncwarp();
    }
}

// ---------------- launch -----------------------------------------------------
extern "C" void kernel_launch(void* const* d_in, const int* in_sizes, int n_in,
                              void* d_out, int out_size) {
    const float* x   = (const float*)d_in[0];
    const int*   eiw = (const int*)d_in[1];
    const float* W1 = (const float*)d_in[2];  const float* b1 = (const float*)d_in[3];
    const float* W2 = (const float*)d_in[4];  const float* b2 = (const float*)d_in[5];
    const float* W3 = (const float*)d_in[6];  const float* b3 = (const float*)d_in[7];
    const float* Wa1 = (const float*)d_in[8];  const float* ba1 = (const float*)d_in[9];
    const float* Wa2 = (const float*)d_in[10]; const float* ba2 = (const float*)d_in[11];
    const float* Wa3 = (const float*)d_in[12]; const float* ba3 = (const float*)d_in[13];
    const float* Wc1 = (const float*)d_in[14]; const float* bc1 = (const float*)d_in[15];
    const float* Wc2 = (const float*)d_in[16]; const float* bc2 = (const float*)d_in[17];
    const float* Wc3 = (const float*)d_in[18]; const float* bc3 = (const float*)d_in[19];
    float* out = (float*)d_out;

    void *ph, *ph8, *pact, *phd, *pdinv, *pdinv2, *pcnt, *prow, *pcur, *pep, *pcs, *pco;
    cudaGetSymbolAddress(&ph, g_h);
    cudaGetSymbolAddress(&ph8, g_h8);
    cudaGetSymbolAddress(&pact, g_act);
    cudaGetSymbolAddress(&phd, g_hd);
    cudaGetSymbolAddress(&pdinv, g_dinv);
    cudaGetSymbolAddress(&pdinv2, g_dinv2);
    cudaGetSymbolAddress(&pcnt, g_cnt);
    cudaGetSymbolAddress(&prow, g_rowPtr);
    cudaGetSymbolAddress(&pcur, g_cur);
    cudaGetSymbolAddress(&pep, g_ePack);
    cudaGetSymbolAddress(&pcs, g_chunkSum);
    cudaGetSymbolAddress(&pco, g_chunkOff);
    __half* H = (__half*)ph;  uint8_t* H8 = (uint8_t*)ph8;
    __half* ACT = (__half*)pact;
    __half* HF = (__half*)phd;
    float* dinv = (float*)pdinv;  float* dinv2 = (float*)pdinv2;
    int* cnt = (int*)pcnt;  int* rowPtr = (int*)prow;  int* cur = (int*)pcur;
    unsigned* ePack = (unsigned*)pep;
    int* chunkSum = (int*)pcs;  int* chunkOff = (int*)pco;

    const int SM_G8 = (128 * 128 + 8 * 16 * 128) * 2;   // 65536
    const int SM_W2 = 128 * 64 * 2;                     // 16384
    const int SM_HF = H_TOT * 2;                        // 127872

    cudaFuncSetAttribute(k_gemm_wmma8,
                         cudaFuncAttributeMaxDynamicSharedMemorySize, SM_G8);
    cudaFuncSetAttribute(k_gemm_wmma<128, 64>,
                         cudaFuncAttributeMaxDynamicSharedMemorySize, SM_W2);
    cudaFuncSetAttribute(k_heads_fused,
                         cudaFuncAttributeMaxDynamicSharedMemorySize, SM_HF);

    cudaStream_t s1 = g_fork.s1;

    // ---- fork: stream s1 runs cvt + layer-1 GEMM concurrently with CSR build
    cudaEventRecord(g_fork.evFork, 0);
    cudaStreamWaitEvent(s1, g_fork.evFork, 0);

    // main stream: CSR build
    k_init<<<(NN + 255) / 256, 256>>>(eiw, cnt);
    k_count<<<1184, 256>>>(eiw, cnt);
    k_chunk_sum<<<NCHUNK, 1024>>>(cnt, chunkSum);
    k_scan_part<<<1, 128>>>(chunkSum, chunkOff);
    k_scan_final<<<NCHUNK, 1024>>>(cnt, chunkOff, rowPtr, cur, dinv, dinv2);
    k_fill<<<1184, 256>>>(eiw, dinv, cur, ePack);

    // forked stream: x -> fp16, layer-1 GEMM
    k_cvt<<<1184, 256, 0, s1>>>(x, ACT);
    k_gemm_wmma8<<<391, 256, SM_G8, s1>>>(ACT, W1, H8);

    // join
    cudaEventRecord(g_fork.evJoin, s1);
    cudaStreamWaitEvent(0, g_fork.evJoin, 0);

    // ---- layer 1 gather ----
    k_gather8<<<1184, 256>>>(rowPtr, ePack, H8, dinv2, b1, ACT);

    // ---- layer 2 ----
    k_gemm_wmma8<<<391, 256, SM_G8>>>(ACT, W2, H8);
    k_gather8<<<1184, 256>>>(rowPtr, ePack, H8, dinv2, b2, ACT);

    // ---- layer 3 ----
    k_gemm_wmma<128, 64><<<391, 256, SM_W2>>>(ACT, W3, H);
    k_gather64h<<<1184, 256>>>(rowPtr, ePack, H, dinv2, b3, HF);

    // ---- fused heads + softmax -> out ----
    k_heads_fused<<<296, 256, SM_HF>>>(HF,
                                       Wa1, ba1, Wa2, ba2, Wa3, ba3,
                                       Wc1, bc1, Wc2, bc2, Wc3, bc3, out);
}